// round 2
// baseline (speedup 1.0000x reference)
#include <cuda_runtime.h>
#include <cuda_bf16.h>
#include <math.h>

// ---------------------------------------------------------------------------
// Scratch (device globals — allocation-free per harness rules)
// ---------------------------------------------------------------------------
__device__ float g_x   [16384 * 256];
__device__ float g_y   [16384 * 256];
__device__ float g_q   [16384 * 256];
__device__ float g_k   [16384 * 256];
__device__ float g_v   [16384 * 256];
__device__ float g_o   [16384 * 256];
__device__ float g_h1  [16384 * 128];
__device__ float g_pre [16384 * 1024];
__device__ float g_WihEncT[256 * 1024];   // (wih[:,256:512]).T  -> [k][n]
__device__ float g_WmR [128 * 2048];      // (wih[:,:256]+whh).T rearranged per gate-block
__device__ float g_g0  [1024];            // dec_h0 @ whh.T
__device__ float g_biasTot[1024];         // bih + bhh
__device__ float g_hbuf[2 * 32 * 256];
__device__ float g_cbuf[32 * 256];

// ---------------------------------------------------------------------------
// SGEMM: C = [res +] A(MxK) @ B(KxN) + bias(N) [, relu]
// BM=BN=128, BK=8, 256 threads, 8x8 microtile. M%128==0, N%128==0, K%4==0.
// ---------------------------------------------------------------------------
__global__ __launch_bounds__(256) void sgemm_k(
    const float* __restrict__ A, const float* __restrict__ B,
    const float* __restrict__ bias, const float* __restrict__ res,
    float* __restrict__ C, int M, int N, int K, int relu)
{
    const int BM = 128, BN = 128, BK = 8;
    __shared__ float As[BK][BM];
    __shared__ float Bs[BK][BN];
    int tid = threadIdx.x;
    int bx = blockIdx.x, by = blockIdx.y;
    int tx = tid & 15, ty = tid >> 4;

    int a_r = tid >> 1, a_c = (tid & 1) << 2;   // A: 128 rows x 8 cols, float4
    int b_r = tid >> 5, b_c = (tid & 31) << 2;  // B: 8 rows x 128 cols, float4

    const float* Ablk = A + (size_t)(by * BM) * K;
    const float* Bblk = B + bx * BN;

    float acc[8][8];
#pragma unroll
    for (int i = 0; i < 8; i++)
#pragma unroll
        for (int j = 0; j < 8; j++) acc[i][j] = 0.f;

    for (int k0 = 0; k0 < K; k0 += BK) {
        float4 av = make_float4(0.f, 0.f, 0.f, 0.f);
        if (k0 + a_c < K) av = *(const float4*)(Ablk + (size_t)a_r * K + k0 + a_c);
        As[a_c + 0][a_r] = av.x;
        As[a_c + 1][a_r] = av.y;
        As[a_c + 2][a_r] = av.z;
        As[a_c + 3][a_r] = av.w;

        float4 bv = make_float4(0.f, 0.f, 0.f, 0.f);
        if (k0 + b_r < K) bv = *(const float4*)(Bblk + (size_t)(k0 + b_r) * N + b_c);
        *(float4*)(&Bs[b_r][b_c]) = bv;
        __syncthreads();

#pragma unroll
        for (int k = 0; k < BK; k++) {
            float ra[8], rb[8];
#pragma unroll
            for (int i = 0; i < 8; i++) ra[i] = As[k][ty * 8 + i];
#pragma unroll
            for (int j = 0; j < 8; j++) rb[j] = Bs[k][tx * 8 + j];
#pragma unroll
            for (int i = 0; i < 8; i++)
#pragma unroll
                for (int j = 0; j < 8; j++) acc[i][j] = fmaf(ra[i], rb[j], acc[i][j]);
        }
        __syncthreads();
    }

    int crow0 = by * BM + ty * 8, ccol0 = bx * BN + tx * 8;
#pragma unroll
    for (int i = 0; i < 8; i++) {
        size_t roff = (size_t)(crow0 + i) * N + ccol0;
#pragma unroll
        for (int j = 0; j < 8; j++) {
            float v = acc[i][j] + bias[ccol0 + j];
            if (res) v += res[roff + j];
            if (relu) v = fmaxf(v, 0.f);
            C[roff + j] = v;
        }
    }
}

// ---------------------------------------------------------------------------
// LayerNorm (reference semantics: var = sum((x-mean)^2)/(n-1); denom = sqrt(var)+eps)
// one block per row, 256 threads (E=256)
// ---------------------------------------------------------------------------
__global__ __launch_bounds__(256) void layernorm_k(
    const float* __restrict__ x, const float* __restrict__ g,
    const float* __restrict__ b, float* __restrict__ y)
{
    __shared__ float s1[8];
    int row = blockIdx.x, tid = threadIdx.x;
    float v = x[(size_t)row * 256 + tid];

    float sum = v;
#pragma unroll
    for (int o = 16; o > 0; o >>= 1) sum += __shfl_down_sync(0xffffffffu, sum, o);
    if ((tid & 31) == 0) s1[tid >> 5] = sum;
    __syncthreads();
    float tot = 0.f;
#pragma unroll
    for (int w = 0; w < 8; w++) tot += s1[w];
    float mean = tot * (1.f / 256.f);
    float d = v - mean;

    float sq = d * d;
#pragma unroll
    for (int o = 16; o > 0; o >>= 1) sq += __shfl_down_sync(0xffffffffu, sq, o);
    __syncthreads();
    if ((tid & 31) == 0) s1[tid >> 5] = sq;
    __syncthreads();
    float tot2 = 0.f;
#pragma unroll
    for (int w = 0; w < 8; w++) tot2 += s1[w];
    float var = tot2 * (1.f / 255.f);
    float r = 1.f / (sqrtf(var) + 1e-6f);
    y[(size_t)row * 256 + tid] = g[tid] * d * r + b[tid];
}

// ---------------------------------------------------------------------------
// Fused attention: one block per (b,h). K,V tiles (512x32 each) in smem.
// One q-row per thread (512 threads), online softmax, dk=32.
// Mask semantics match reference: mask broadcasts over KEY dim — a masked
// query row gets uniform attention.
// ---------------------------------------------------------------------------
__global__ __launch_bounds__(512) void attention_k(
    const float* __restrict__ Q, const float* __restrict__ K,
    const float* __restrict__ V, const float* __restrict__ mask,
    float* __restrict__ O)
{
    extern __shared__ float sm[];
    float* Ks = sm;
    float* Vs = sm + 512 * 32;

    int bh = blockIdx.x;
    int b = bh >> 3, h = bh & 7;
    int tid = threadIdx.x;

    const float* Kb = K + (size_t)(b * 512) * 256 + h * 32;
    const float* Vb = V + (size_t)(b * 512) * 256 + h * 32;
    for (int idx = tid; idx < 512 * 32; idx += 512) {
        int r = idx >> 5, d = idx & 31;
        Ks[idx] = Kb[(size_t)r * 256 + d];
        Vs[idx] = Vb[(size_t)r * 256 + d];
    }

    float q[32];
    const float* Qr = Q + (size_t)(b * 512 + tid) * 256 + h * 32;
#pragma unroll
    for (int d = 0; d < 32; d += 4) {
        float4 t4 = *(const float4*)(Qr + d);
        q[d] = t4.x; q[d + 1] = t4.y; q[d + 2] = t4.z; q[d + 3] = t4.w;
    }
    float mval = mask[b * 512 + tid];
    __syncthreads();

    const float scale = 0.17677669529663689f;  // 1/sqrt(32)
    float m = -1e30f, l = 0.f, acc[32];
#pragma unroll
    for (int d = 0; d < 32; d++) acc[d] = 0.f;

    for (int j = 0; j < 512; j++) {
        const float* kr = Ks + j * 32;
        float s = 0.f;
#pragma unroll
        for (int d = 0; d < 32; d++) s = fmaf(q[d], kr[d], s);
        s *= scale;
        if (mval == 0.f) s = -1e9f;
        float mn = fmaxf(m, s);
        float corr = __expf(m - mn);
        float p = __expf(s - mn);
        l = l * corr + p;
        const float* vr = Vs + j * 32;
#pragma unroll
        for (int d = 0; d < 32; d++) acc[d] = fmaf(acc[d], corr, p * vr[d]);
        m = mn;
    }
    float inv = 1.f / l;
    float* Or = O + (size_t)(b * 512 + tid) * 256 + h * 32;
#pragma unroll
    for (int d = 0; d < 32; d++) Or[d] = acc[d] * inv;
}

// ---------------------------------------------------------------------------
// LSTM prep: build transposed/merged weights, g0, biasTot
//   WihEncT[k][n] = wih[n][256+k]
//   WmR[blk][i]   = rearranged (wih[:, :256] + whh).T for gate block `blk`
//   g0[n]         = dec_h0 @ whh.T
// ---------------------------------------------------------------------------
__global__ __launch_bounds__(256) void lstm_prep_k(
    const float* __restrict__ wih, const float* __restrict__ whh,
    const float* __restrict__ bih, const float* __restrict__ bhh,
    const float* __restrict__ dec_h0,
    float* __restrict__ WihEncT, float* __restrict__ WmR,
    float* __restrict__ g0, float* __restrict__ biasTot)
{
    int idx = blockIdx.x * 256 + threadIdx.x;
    if (idx < 262144) {
        int k = idx >> 10, n = idx & 1023;
        WihEncT[idx] = wih[(size_t)n * 512 + 256 + k];

        // WmR layout: [blk (128)][k (256)][sub (8)],  sub = (el<<2)|g isn't used;
        // sub: g = sub&3, el = sub>>2; col n' = g*256 + blk*2 + el
        int blk = idx >> 11;
        int r = idx & 2047;
        int kk = r >> 3, sub = r & 7;
        int gg = sub & 3, ee = blk * 2 + (sub >> 2);
        int np = gg * 256 + ee;
        WmR[idx] = wih[(size_t)np * 512 + kk] + whh[(size_t)np * 256 + kk];
    }
    if (idx < 1024) {
        float a = 0.f;
        for (int k = 0; k < 256; k++) a = fmaf(dec_h0[k], whh[(size_t)idx * 256 + k], a);
        g0[idx] = a;
        biasTot[idx] = bih[idx] + bhh[idx];
    }
}

// ---------------------------------------------------------------------------
// LSTM step: blocks 0..127 = gates/cell-update (2 e-columns x 32 batches each),
// blocks 128..159 = lagged output MLP (computes p[t-1]).
// gates(t>=1) = h @ Wm + pre[:,t,:]   (o_prev == h for t>=1)
// gates(t==0) = pre[:,0,:] + g0       (o_prev == 0, h == dec_h0)
// Launched for t = 0..512 (t=512: MLP tail only).
// ---------------------------------------------------------------------------
__device__ __forceinline__ float sigf(float x) { return 1.f / (1.f + __expf(-x)); }

__global__ __launch_bounds__(256) void lstm_step_k(
    int t,
    const float* __restrict__ pre, const float* __restrict__ WmR,
    const float* __restrict__ g0, const float* __restrict__ dec_c0,
    const float* __restrict__ w1, const float* __restrict__ b1,
    const float* __restrict__ w2, const float* __restrict__ b2,
    const float* __restrict__ mask,
    float* __restrict__ hbuf, float* __restrict__ cbuf, float* __restrict__ out)
{
    int tid = threadIdx.x;
    if (blockIdx.x < 128) {
        if (t >= 512) return;
        __shared__ float hs[32 * 257];
        __shared__ float ws[2048];
        int b = tid >> 3;              // batch
        int sub = tid & 7;             // (el<<2)|g
        int g = tid & 3;               // gate index
        int e = blockIdx.x * 2 + ((tid >> 2) & 1);
        int col = g * 256 + e;

        float gate;
        if (t == 0) {
            gate = pre[(size_t)(b * 512) * 1024 + col] + g0[col];
        } else {
            for (int i = tid; i < 2048; i += 256)
                ws[i] = WmR[(size_t)blockIdx.x * 2048 + i];
            const float* hsrc = hbuf + (t & 1) * 8192;
            for (int i = tid; i < 8192; i += 256)
                hs[(i >> 8) * 257 + (i & 255)] = hsrc[i];
            __syncthreads();
            float acc = 0.f;
            const float* hr = hs + b * 257;
            const float* wc = ws + sub;
#pragma unroll 8
            for (int k = 0; k < 256; k++) acc = fmaf(hr[k], wc[k << 3], acc);
            gate = acc + pre[(size_t)(b * 512 + t) * 1024 + col];
        }

        unsigned base = (tid & 31) & ~3u;
        float gi = __shfl_sync(0xffffffffu, gate, base + 0);
        float gf = __shfl_sync(0xffffffffu, gate, base + 1);
        float gg = __shfl_sync(0xffffffffu, gate, base + 2);
        float go = __shfl_sync(0xffffffffu, gate, base + 3);
        if (g == 0) {
            float c = (t == 0) ? dec_c0[e] : cbuf[(b << 8) + e];
            float cn = sigf(gf) * c + sigf(gi) * tanhf(gg);
            float hn = sigf(go) * tanhf(cn);
            cbuf[(b << 8) + e] = cn;
            hbuf[((t + 1) & 1) * 8192 + (b << 8) + e] = hn;
        }
    } else {
        if (t == 0) return;            // lag: compute p[t-1]
        int tt = t - 1;
        int b = blockIdx.x - 128;
        __shared__ float hb[256];
        __shared__ float red[4];
        hb[tid] = hbuf[(t & 1) * 8192 + (b << 8) + tid];
        __syncthreads();
        float contrib = 0.f;
        if (tid < 128) {
            float a = b1[tid];
#pragma unroll 8
            for (int k = 0; k < 256; k++) a = fmaf(hb[k], w1[(k << 7) + tid], a);
            contrib = fmaxf(a, 0.f) * w2[tid];
        }
#pragma unroll
        for (int o = 16; o > 0; o >>= 1) contrib += __shfl_down_sync(0xffffffffu, contrib, o);
        if (tid < 128 && (tid & 31) == 0) red[tid >> 5] = contrib;
        __syncthreads();
        if (tid == 0) {
            float p = red[0] + red[1] + red[2] + red[3] + b2[0];
            out[(b << 9) + tt] = p * mask[(b << 9) + tt];
        }
    }
}

// ---------------------------------------------------------------------------
// Launcher
// ---------------------------------------------------------------------------
extern "C" void kernel_launch(void* const* d_in, const int* in_sizes, int n_in,
                              void* d_out, int out_size)
{
    const float* inputs   = (const float*)d_in[0];
    const float* mask     = (const float*)d_in[1];
    /* d_in[2] = lengths (unused) */
    const float* embed_w  = (const float*)d_in[3];
    const float* embed_b  = (const float*)d_in[4];
    const float* qkvo_w   = (const float*)d_in[5];
    const float* qkvo_b   = (const float*)d_in[6];
    const float* ln_g     = (const float*)d_in[7];
    const float* ln_b     = (const float*)d_in[8];
    const float* ff_w1    = (const float*)d_in[9];
    const float* ff_b1    = (const float*)d_in[10];
    const float* ff_w2    = (const float*)d_in[11];
    const float* ff_b2    = (const float*)d_in[12];
    const float* enc_ln_g = (const float*)d_in[13];
    const float* enc_ln_b = (const float*)d_in[14];
    const float* wih      = (const float*)d_in[15];
    const float* whh      = (const float*)d_in[16];
    const float* bih      = (const float*)d_in[17];
    const float* bhh      = (const float*)d_in[18];
    const float* dec_h0   = (const float*)d_in[19];
    const float* dec_c0   = (const float*)d_in[20];
    const float* out_w1   = (const float*)d_in[21];
    const float* out_b1   = (const float*)d_in[22];
    const float* out_w2   = (const float*)d_in[23];
    const float* out_b2   = (const float*)d_in[24];
    float* out = (float*)d_out;
    (void)in_sizes; (void)n_in; (void)out_size;

    float *px, *py, *pq, *pk, *pv, *po, *ph1, *ppre, *pWET, *pWmR, *pg0, *pbt, *phb, *pcb;
    cudaGetSymbolAddress((void**)&px,   g_x);
    cudaGetSymbolAddress((void**)&py,   g_y);
    cudaGetSymbolAddress((void**)&pq,   g_q);
    cudaGetSymbolAddress((void**)&pk,   g_k);
    cudaGetSymbolAddress((void**)&pv,   g_v);
    cudaGetSymbolAddress((void**)&po,   g_o);
    cudaGetSymbolAddress((void**)&ph1,  g_h1);
    cudaGetSymbolAddress((void**)&ppre, g_pre);
    cudaGetSymbolAddress((void**)&pWET, g_WihEncT);
    cudaGetSymbolAddress((void**)&pWmR, g_WmR);
    cudaGetSymbolAddress((void**)&pg0,  g_g0);
    cudaGetSymbolAddress((void**)&pbt,  g_biasTot);
    cudaGetSymbolAddress((void**)&phb,  g_hbuf);
    cudaGetSymbolAddress((void**)&pcb,  g_cbuf);

    cudaFuncSetAttribute(attention_k, cudaFuncAttributeMaxDynamicSharedMemorySize, 131072);

    const int M = 16384;
    dim3 g2(2, 128);   // N=256
    dim3 g1(1, 128);   // N=128
    dim3 g8(8, 128);   // N=1024

    // LSTM weight prep (cheap; runs every call for determinism)
    lstm_prep_k<<<1024, 256>>>(wih, whh, bih, bhh, dec_h0, pWET, pWmR, pg0, pbt);

    // Embed
    sgemm_k<<<g2, 256>>>(inputs, embed_w, embed_b, nullptr, px, M, 256, 300, 0);

    // Transformer layers
    for (int l = 0; l < 6; l++) {
        const float* Wq = qkvo_w + (size_t)(l * 4 + 0) * 65536;
        const float* Wk = qkvo_w + (size_t)(l * 4 + 1) * 65536;
        const float* Wv = qkvo_w + (size_t)(l * 4 + 2) * 65536;
        const float* Wo = qkvo_w + (size_t)(l * 4 + 3) * 65536;
        const float* bq = qkvo_b + (l * 4 + 0) * 256;
        const float* bk = qkvo_b + (l * 4 + 1) * 256;
        const float* bv = qkvo_b + (l * 4 + 2) * 256;
        const float* bo = qkvo_b + (l * 4 + 3) * 256;

        layernorm_k<<<16384, 256>>>(px, ln_g + l * 512, ln_b + l * 512, py);
        sgemm_k<<<g2, 256>>>(py, Wq, bq, nullptr, pq, M, 256, 256, 0);
        sgemm_k<<<g2, 256>>>(py, Wk, bk, nullptr, pk, M, 256, 256, 0);
        sgemm_k<<<g2, 256>>>(py, Wv, bv, nullptr, pv, M, 256, 256, 0);
        attention_k<<<256, 512, 131072>>>(pq, pk, pv, mask, po);
        sgemm_k<<<g2, 256>>>(po, Wo, bo, px, px, M, 256, 256, 0);

        layernorm_k<<<16384, 256>>>(px, ln_g + l * 512 + 256, ln_b + l * 512 + 256, py);
        sgemm_k<<<g1, 256>>>(py, ff_w1 + (size_t)l * 256 * 128, ff_b1 + l * 128,
                             nullptr, ph1, M, 128, 256, 1);
        sgemm_k<<<g2, 256>>>(ph1, ff_w2 + (size_t)l * 128 * 256, ff_b2 + l * 256,
                             px, px, M, 256, 128, 0);
    }

    // Encoder LN -> enc (in py)
    layernorm_k<<<16384, 256>>>(px, enc_ln_g, enc_ln_b, py);

    // pre = enc @ wih[:,256:].T + (bih+bhh)
    sgemm_k<<<g8, 256>>>(py, pWET, pbt, nullptr, ppre, M, 1024, 256, 0);

    // LSTM scan: 513 step launches (MLP lags one step; t=512 is MLP tail)
    for (int t = 0; t <= 512; t++) {
        lstm_step_k<<<160, 256>>>(t, ppre, pWmR, pg0, dec_c0,
                                  out_w1, out_b1, out_w2, out_b2,
                                  mask, phb, pcb, out);
    }
}

// round 3
// speedup vs baseline: 1.2600x; 1.2600x over previous
#include <cuda_runtime.h>
#include <cuda_bf16.h>
#include <math.h>

// ---------------------------------------------------------------------------
// Scratch (device globals — allocation-free per harness rules)
// ---------------------------------------------------------------------------
__device__ float g_x   [16384 * 256];
__device__ float g_y   [16384 * 256];
__device__ float g_q   [16384 * 256];
__device__ float g_k   [16384 * 256];
__device__ float g_v   [16384 * 256];
__device__ float g_o   [16384 * 256];
__device__ float g_h1  [16384 * 128];
__device__ float g_pre [16384 * 1024];
__device__ float g_WihEncT[256 * 1024];   // (wih[:,256:512]).T  -> [k][n]
__device__ float g_WmR [64 * 4096];       // merged (wih[:,:256]+whh).T per gate-block
__device__ float g_w1t [128 * 256];       // out_w1 transposed [h][k]
__device__ float g_g0  [1024];            // dec_h0 @ whh.T
__device__ float g_biasTot[1024];         // bih + bhh
__device__ float g_hbuf[2 * 32 * 256];
__device__ unsigned g_sync;               // grid barrier counter (zeroed in prep)

// ---------------------------------------------------------------------------
// SGEMM: C = [res +] A(MxK) @ B(KxN) + bias(N) [, relu]
// BM=BN=128, BK=8, 256 threads, 8x8 microtile, double-buffered smem.
// M%128==0, N%128==0, K%4==0.
// ---------------------------------------------------------------------------
__device__ __forceinline__ float4 ldA4(const float* Ablk, int r, int c, int K) {
    if (c < K) return *(const float4*)(Ablk + (size_t)r * K + c);
    return make_float4(0.f, 0.f, 0.f, 0.f);
}
__device__ __forceinline__ float4 ldB4(const float* Bblk, int r, int c, int N, int K) {
    if (r < K) return *(const float4*)(Bblk + (size_t)r * N + c);
    return make_float4(0.f, 0.f, 0.f, 0.f);
}

__global__ __launch_bounds__(256) void sgemm_k(
    const float* __restrict__ A, const float* __restrict__ B,
    const float* __restrict__ bias, const float* __restrict__ res,
    float* __restrict__ C, int M, int N, int K, int relu)
{
    const int BM = 128, BN = 128, BK = 8;
    __shared__ float As[2][BK][BM];
    __shared__ float Bs[2][BK][BN];
    int tid = threadIdx.x;
    int bx = blockIdx.x, by = blockIdx.y;
    int tx = tid & 15, ty = tid >> 4;

    int a_r = tid >> 1, a_c = (tid & 1) << 2;   // A: 128 rows x 8 cols, float4
    int b_r = tid >> 5, b_c = (tid & 31) << 2;  // B: 8 rows x 128 cols, float4

    const float* Ablk = A + (size_t)(by * BM) * K;
    const float* Bblk = B + bx * BN;

    float acc[8][8];
#pragma unroll
    for (int i = 0; i < 8; i++)
#pragma unroll
        for (int j = 0; j < 8; j++) acc[i][j] = 0.f;

    // prologue: tile 0
    {
        float4 av = ldA4(Ablk, a_r, a_c, K);
        float4 bv = ldB4(Bblk, b_r, b_c, N, K);
        As[0][a_c + 0][a_r] = av.x;
        As[0][a_c + 1][a_r] = av.y;
        As[0][a_c + 2][a_r] = av.z;
        As[0][a_c + 3][a_r] = av.w;
        *(float4*)(&Bs[0][b_r][b_c]) = bv;
    }
    __syncthreads();

    int cur = 0;
    for (int k0 = 0; k0 < K; k0 += BK) {
        bool haveNext = (k0 + BK < K);
        float4 av2, bv2;
        if (haveNext) {
            av2 = ldA4(Ablk, a_r, k0 + BK + a_c, K);
            bv2 = ldB4(Bblk, k0 + BK + b_r, b_c, N, K);
        }
#pragma unroll
        for (int k = 0; k < BK; k++) {
            float ra[8], rb[8];
#pragma unroll
            for (int i = 0; i < 8; i++) ra[i] = As[cur][k][ty * 8 + i];
#pragma unroll
            for (int j = 0; j < 8; j++) rb[j] = Bs[cur][k][tx * 8 + j];
#pragma unroll
            for (int i = 0; i < 8; i++)
#pragma unroll
                for (int j = 0; j < 8; j++) acc[i][j] = fmaf(ra[i], rb[j], acc[i][j]);
        }
        if (haveNext) {
            int nxt = cur ^ 1;
            As[nxt][a_c + 0][a_r] = av2.x;
            As[nxt][a_c + 1][a_r] = av2.y;
            As[nxt][a_c + 2][a_r] = av2.z;
            As[nxt][a_c + 3][a_r] = av2.w;
            *(float4*)(&Bs[nxt][b_r][b_c]) = bv2;
            __syncthreads();
            cur = nxt;
        }
    }

    int crow0 = by * BM + ty * 8, ccol0 = bx * BN + tx * 8;
#pragma unroll
    for (int i = 0; i < 8; i++) {
        size_t roff = (size_t)(crow0 + i) * N + ccol0;
#pragma unroll
        for (int j = 0; j < 8; j++) {
            float v = acc[i][j] + bias[ccol0 + j];
            if (res) v += res[roff + j];
            if (relu) v = fmaxf(v, 0.f);
            C[roff + j] = v;
        }
    }
}

// ---------------------------------------------------------------------------
// LayerNorm: warp per row (E=256), float4, 8 rows per 256-thread block.
// var = sum((x-mean)^2)/(n-1); denom = sqrt(var)+eps (reference semantics)
// ---------------------------------------------------------------------------
__global__ __launch_bounds__(256) void layernorm_k(
    const float* __restrict__ x, const float* __restrict__ g,
    const float* __restrict__ b, float* __restrict__ y)
{
    int tid = threadIdx.x;
    int lane = tid & 31;
    int row = blockIdx.x * 8 + (tid >> 5);

    const float4* xr = (const float4*)(x + (size_t)row * 256);
    float4 v0 = xr[lane], v1 = xr[lane + 32];

    float s = v0.x + v0.y + v0.z + v0.w + v1.x + v1.y + v1.z + v1.w;
#pragma unroll
    for (int o = 16; o > 0; o >>= 1) s += __shfl_xor_sync(0xffffffffu, s, o);
    float mean = s * (1.f / 256.f);

    float4 d0 = make_float4(v0.x - mean, v0.y - mean, v0.z - mean, v0.w - mean);
    float4 d1 = make_float4(v1.x - mean, v1.y - mean, v1.z - mean, v1.w - mean);
    float sq = d0.x * d0.x + d0.y * d0.y + d0.z * d0.z + d0.w * d0.w
             + d1.x * d1.x + d1.y * d1.y + d1.z * d1.z + d1.w * d1.w;
#pragma unroll
    for (int o = 16; o > 0; o >>= 1) sq += __shfl_xor_sync(0xffffffffu, sq, o);
    float var = sq * (1.f / 255.f);
    float r = 1.f / (sqrtf(var) + 1e-6f);

    const float4* g4 = (const float4*)g;
    const float4* b4 = (const float4*)b;
    float4 gg0 = g4[lane], gg1 = g4[lane + 32];
    float4 bb0 = b4[lane], bb1 = b4[lane + 32];

    float4 o0, o1;
    o0.x = gg0.x * d0.x * r + bb0.x; o0.y = gg0.y * d0.y * r + bb0.y;
    o0.z = gg0.z * d0.z * r + bb0.z; o0.w = gg0.w * d0.w * r + bb0.w;
    o1.x = gg1.x * d1.x * r + bb1.x; o1.y = gg1.y * d1.y * r + bb1.y;
    o1.z = gg1.z * d1.z * r + bb1.z; o1.w = gg1.w * d1.w * r + bb1.w;

    float4* yr = (float4*)(y + (size_t)row * 256);
    yr[lane] = o0;
    yr[lane + 32] = o1;
}

// ---------------------------------------------------------------------------
// Fused attention: one block per (b,h). K,V tiles (512x32) in smem, float4,
// chunk-of-8 online softmax. 512 threads, one q-row per thread, dk=32.
// ---------------------------------------------------------------------------
__global__ __launch_bounds__(512) void attention_k(
    const float* __restrict__ Q, const float* __restrict__ K,
    const float* __restrict__ V, const float* __restrict__ mask,
    float* __restrict__ O)
{
    extern __shared__ float sm[];
    float* Ks = sm;
    float* Vs = sm + 512 * 32;

    int bh = blockIdx.x;
    int b = bh >> 3, h = bh & 7;
    int tid = threadIdx.x;

    const float* Kb = K + (size_t)(b * 512) * 256 + h * 32;
    const float* Vb = V + (size_t)(b * 512) * 256 + h * 32;
    for (int idx = tid; idx < 512 * 8; idx += 512) {
        int r = idx >> 3, d4 = idx & 7;
        ((float4*)Ks)[idx] = ((const float4*)(Kb + (size_t)r * 256))[d4];
        ((float4*)Vs)[idx] = ((const float4*)(Vb + (size_t)r * 256))[d4];
    }

    float4 q4[8];
    const float* Qr = Q + (size_t)(b * 512 + tid) * 256 + h * 32;
#pragma unroll
    for (int d4 = 0; d4 < 8; d4++) q4[d4] = ((const float4*)Qr)[d4];
    bool mz = (mask[b * 512 + tid] == 0.f);
    __syncthreads();

    const float scale = 0.17677669529663689f;  // 1/sqrt(32)
    float m = -1e30f, l = 0.f, acc[32];
#pragma unroll
    for (int d = 0; d < 32; d++) acc[d] = 0.f;

    for (int j0 = 0; j0 < 512; j0 += 8) {
        float s[8];
#pragma unroll
        for (int jj = 0; jj < 8; jj++) {
            const float4* kr = (const float4*)(Ks + (j0 + jj) * 32);
            float a = 0.f;
#pragma unroll
            for (int d4 = 0; d4 < 8; d4++) {
                float4 kv = kr[d4];
                a = fmaf(q4[d4].x, kv.x, a);
                a = fmaf(q4[d4].y, kv.y, a);
                a = fmaf(q4[d4].z, kv.z, a);
                a = fmaf(q4[d4].w, kv.w, a);
            }
            s[jj] = a * scale;
        }
        if (mz) {
#pragma unroll
            for (int jj = 0; jj < 8; jj++) s[jj] = -1e9f;
        }
        float cm = s[0];
#pragma unroll
        for (int jj = 1; jj < 8; jj++) cm = fmaxf(cm, s[jj]);
        float mn = fmaxf(m, cm);
        float corr = __expf(m - mn);
        m = mn;
        l *= corr;
#pragma unroll
        for (int d = 0; d < 32; d++) acc[d] *= corr;
#pragma unroll
        for (int jj = 0; jj < 8; jj++) {
            float p = __expf(s[jj] - mn);
            l += p;
            const float4* vr = (const float4*)(Vs + (j0 + jj) * 32);
#pragma unroll
            for (int d4 = 0; d4 < 8; d4++) {
                float4 vv = vr[d4];
                acc[d4 * 4 + 0] = fmaf(p, vv.x, acc[d4 * 4 + 0]);
                acc[d4 * 4 + 1] = fmaf(p, vv.y, acc[d4 * 4 + 1]);
                acc[d4 * 4 + 2] = fmaf(p, vv.z, acc[d4 * 4 + 2]);
                acc[d4 * 4 + 3] = fmaf(p, vv.w, acc[d4 * 4 + 3]);
            }
        }
    }
    float inv = 1.f / l;
    float* Or = O + (size_t)(b * 512 + tid) * 256 + h * 32;
#pragma unroll
    for (int d = 0; d < 32; d++) Or[d] = acc[d] * inv;
}

// ---------------------------------------------------------------------------
// LSTM prep: build transposed/merged weights, g0, biasTot, w1t; zero barrier.
//   WihEncT[k][n] = wih[n][256+k]
//   WmR[gb][(g*4+el)*256+k] = wih[col][k] + whh[col][k], col = g*256+gb*4+el
//   w1t[h][k] = out_w1[k][h]
// ---------------------------------------------------------------------------
__global__ __launch_bounds__(256) void lstm_prep_k(
    const float* __restrict__ wih, const float* __restrict__ whh,
    const float* __restrict__ bih, const float* __restrict__ bhh,
    const float* __restrict__ dec_h0, const float* __restrict__ out_w1,
    float* __restrict__ WihEncT, float* __restrict__ WmR,
    float* __restrict__ w1t, float* __restrict__ g0,
    float* __restrict__ biasTot, unsigned* __restrict__ sync)
{
    int idx = blockIdx.x * 256 + threadIdx.x;
    if (idx == 0) *sync = 0u;
    if (idx < 262144) {
        int k = idx >> 10, n = idx & 1023;
        WihEncT[idx] = wih[(size_t)n * 512 + 256 + k];

        int gb = idx >> 12;
        int r = idx & 4095;
        int gi = r >> 10;
        int rem = r & 1023;
        int el = rem >> 8;
        int kk = rem & 255;
        int col = gi * 256 + gb * 4 + el;
        WmR[idx] = wih[(size_t)col * 512 + kk] + whh[(size_t)col * 256 + kk];
    }
    if (idx < 32768) {
        int h = idx >> 8, k = idx & 255;
        w1t[idx] = out_w1[(size_t)k * 128 + h];
    }
    if (idx < 1024) {
        float a = 0.f;
        for (int k = 0; k < 256; k++) a = fmaf(dec_h0[k], whh[(size_t)idx * 256 + k], a);
        g0[idx] = a;
        biasTot[idx] = bih[idx] + bhh[idx];
    }
}

// ---------------------------------------------------------------------------
// Persistent LSTM: 96 blocks (64 gate + 32 MLP), all co-resident (1/SM),
// custom grid barrier on g_sync. Gate block gb owns e in [gb*4, gb*4+4):
// weights cached in smem for the whole scan; c lives in registers.
// MLP block computes p(t-1) concurrently (h double-buffered, .cg coherence).
// ---------------------------------------------------------------------------
__device__ __forceinline__ float sigf(float x) { return 1.f / (1.f + __expf(-x)); }

__device__ __forceinline__ void grid_bar(unsigned* sync, unsigned target) {
    __threadfence();
    __syncthreads();
    if (threadIdx.x == 0) {
        atomicAdd(sync, 1u);
        while (*(volatile unsigned*)sync < target) { __nanosleep(20); }
        __threadfence();
    }
    __syncthreads();
}

__global__ __launch_bounds__(256, 1) void lstm_persist_k(
    const float* __restrict__ pre, const float* __restrict__ WmR,
    const float* __restrict__ w1t, const float* __restrict__ g0,
    const float* __restrict__ dec_c0,
    const float* __restrict__ b1, const float* __restrict__ w2,
    const float* __restrict__ b2, const float* __restrict__ mask,
    float* __restrict__ hbuf, unsigned* __restrict__ sync,
    float* __restrict__ out)
{
    extern __shared__ float sm[];
    const int tid = threadIdx.x;
    const unsigned NBLK = 96;

    if (blockIdx.x < 64) {
        // ---------------- gate block ----------------
        const int gb = blockIdx.x;
        const int half = tid & 1;
        const int p = tid >> 1;       // 0..127
        const int b = p & 31;
        const int el = p >> 5;        // 0..3
        const int e = gb * 4 + el;

        float4* ws4 = (float4*)sm;                 // 1024 float4 = 16KB
        float4* hs4 = (float4*)(sm + 4096);        // 32*66 = 2112 float4

        const float4* wsrc = (const float4*)(WmR + (size_t)gb * 4096);
        for (int i = tid; i < 1024; i += 256) ws4[i] = wsrc[i];

        float c = dec_c0[e];

        for (int t = 0; t < 512; ++t) {
            float gv0 = 0.f, gv1 = 0.f, gv2 = 0.f, gv3 = 0.f;
            if (t == 0) {
                if (half == 0) {
                    const float* pr = pre + (size_t)b * 512 * 1024;
                    gv0 = pr[e]       + g0[e];
                    gv1 = pr[256 + e] + g0[256 + e];
                    gv2 = pr[512 + e] + g0[512 + e];
                    gv3 = pr[768 + e] + g0[768 + e];
                }
            } else {
                // stage h_t into padded smem
                const float4* hsrc = (const float4*)(hbuf + (t & 1) * 8192);
                for (int j = tid; j < 2048; j += 256) {
                    float4 v = __ldcg(hsrc + j);
                    int bb = j >> 6, k4 = j & 63;
                    hs4[bb * 66 + (k4 >> 5) * 33 + (k4 & 31)] = v;
                }
                __syncthreads();

                float a0 = 0.f, a1 = 0.f, a2 = 0.f, a3 = 0.f;
                const float4* hp = hs4 + b * 66 + half * 33;
                const float4* wp = ws4 + el * 64 + half * 32;
#pragma unroll
                for (int kk = 0; kk < 32; kk++) {
                    float4 hv = hp[kk];
                    float4 w0 = wp[kk];
                    float4 w1v = wp[256 + kk];
                    float4 w2v = wp[512 + kk];
                    float4 w3v = wp[768 + kk];
                    a0 = fmaf(hv.x, w0.x, fmaf(hv.y, w0.y, fmaf(hv.z, w0.z, fmaf(hv.w, w0.w, a0))));
                    a1 = fmaf(hv.x, w1v.x, fmaf(hv.y, w1v.y, fmaf(hv.z, w1v.z, fmaf(hv.w, w1v.w, a1))));
                    a2 = fmaf(hv.x, w2v.x, fmaf(hv.y, w2v.y, fmaf(hv.z, w2v.z, fmaf(hv.w, w2v.w, a2))));
                    a3 = fmaf(hv.x, w3v.x, fmaf(hv.y, w3v.y, fmaf(hv.z, w3v.z, fmaf(hv.w, w3v.w, a3))));
                }
                a0 += __shfl_xor_sync(0xffffffffu, a0, 1);
                a1 += __shfl_xor_sync(0xffffffffu, a1, 1);
                a2 += __shfl_xor_sync(0xffffffffu, a2, 1);
                a3 += __shfl_xor_sync(0xffffffffu, a3, 1);
                if (half == 0) {
                    const float* pr = pre + ((size_t)b * 512 + t) * 1024;
                    gv0 = a0 + pr[e];
                    gv1 = a1 + pr[256 + e];
                    gv2 = a2 + pr[512 + e];
                    gv3 = a3 + pr[768 + e];
                }
            }
            if (half == 0) {
                float cn = sigf(gv1) * c + sigf(gv0) * tanhf(gv2);
                float hn = sigf(gv3) * tanhf(cn);
                c = cn;
                __stcg(hbuf + ((t + 1) & 1) * 8192 + b * 256 + e, hn);
            }
            grid_bar(sync, (unsigned)(t + 1) * NBLK);
        }
    } else {
        // ---------------- MLP block (lagged output head) ----------------
        const int b = blockIdx.x - 64;
        float* w1s  = sm;             // 128 rows, stride 260 floats (padded)
        float* hrow = sm + 33280;     // 256
        float* red  = sm + 33536;     // 8

        // cache w1t in smem (padded rows for conflict-free LDS.128)
        for (int i = tid; i < 8192; i += 256) {
            int h = i >> 6, k4 = i & 63;
            ((float4*)w1s)[h * 65 + k4] = ((const float4*)w1t)[i];
        }
        float w2v = (tid < 128) ? w2[tid] : 0.f;
        float b1v = (tid < 128) ? b1[tid] : 0.f;
        float b2v = b2[0];

        for (int t = 0; t <= 512; ++t) {
            if (t >= 1) {
                hrow[tid] = __ldcg(hbuf + (t & 1) * 8192 + b * 256 + tid);
                __syncthreads();
                float contrib = 0.f;
                if (tid < 128) {
                    float a = b1v;
                    const float4* h4 = (const float4*)hrow;
                    const float4* w4 = (const float4*)(w1s + tid * 260);
#pragma unroll 16
                    for (int kk = 0; kk < 64; kk++) {
                        float4 hv = h4[kk];
                        float4 wv = w4[kk];
                        a = fmaf(hv.x, wv.x, fmaf(hv.y, wv.y, fmaf(hv.z, wv.z, fmaf(hv.w, wv.w, a))));
                    }
                    contrib = fmaxf(a, 0.f) * w2v;
                }
#pragma unroll
                for (int o = 16; o > 0; o >>= 1)
                    contrib += __shfl_down_sync(0xffffffffu, contrib, o);
                if (tid < 128 && (tid & 31) == 0) red[tid >> 5] = contrib;
                __syncthreads();
                if (tid == 0) {
                    float pp = red[0] + red[1] + red[2] + red[3] + b2v;
                    out[b * 512 + (t - 1)] = pp * mask[b * 512 + (t - 1)];
                }
            }
            if (t < 512) grid_bar(sync, (unsigned)(t + 1) * NBLK);
        }
    }
}

// ---------------------------------------------------------------------------
// Launcher
// ---------------------------------------------------------------------------
extern "C" void kernel_launch(void* const* d_in, const int* in_sizes, int n_in,
                              void* d_out, int out_size)
{
    const float* inputs   = (const float*)d_in[0];
    const float* mask     = (const float*)d_in[1];
    /* d_in[2] = lengths (unused) */
    const float* embed_w  = (const float*)d_in[3];
    const float* embed_b  = (const float*)d_in[4];
    const float* qkvo_w   = (const float*)d_in[5];
    const float* qkvo_b   = (const float*)d_in[6];
    const float* ln_g     = (const float*)d_in[7];
    const float* ln_b     = (const float*)d_in[8];
    const float* ff_w1    = (const float*)d_in[9];
    const float* ff_b1    = (const float*)d_in[10];
    const float* ff_w2    = (const float*)d_in[11];
    const float* ff_b2    = (const float*)d_in[12];
    const float* enc_ln_g = (const float*)d_in[13];
    const float* enc_ln_b = (const float*)d_in[14];
    const float* wih      = (const float*)d_in[15];
    const float* whh      = (const float*)d_in[16];
    const float* bih      = (const float*)d_in[17];
    const float* bhh      = (const float*)d_in[18];
    const float* dec_h0   = (const float*)d_in[19];
    const float* dec_c0   = (const float*)d_in[20];
    const float* out_w1   = (const float*)d_in[21];
    const float* out_b1   = (const float*)d_in[22];
    const float* out_w2   = (const float*)d_in[23];
    const float* out_b2   = (const float*)d_in[24];
    float* out = (float*)d_out;
    (void)in_sizes; (void)n_in; (void)out_size;

    float *px, *py, *pq, *pk, *pv, *po, *ph1, *ppre, *pWET, *pWmR, *pw1t, *pg0, *pbt, *phb;
    unsigned* psync;
    cudaGetSymbolAddress((void**)&px,    g_x);
    cudaGetSymbolAddress((void**)&py,    g_y);
    cudaGetSymbolAddress((void**)&pq,    g_q);
    cudaGetSymbolAddress((void**)&pk,    g_k);
    cudaGetSymbolAddress((void**)&pv,    g_v);
    cudaGetSymbolAddress((void**)&po,    g_o);
    cudaGetSymbolAddress((void**)&ph1,   g_h1);
    cudaGetSymbolAddress((void**)&ppre,  g_pre);
    cudaGetSymbolAddress((void**)&pWET,  g_WihEncT);
    cudaGetSymbolAddress((void**)&pWmR,  g_WmR);
    cudaGetSymbolAddress((void**)&pw1t,  g_w1t);
    cudaGetSymbolAddress((void**)&pg0,   g_g0);
    cudaGetSymbolAddress((void**)&pbt,   g_biasTot);
    cudaGetSymbolAddress((void**)&phb,   g_hbuf);
    cudaGetSymbolAddress((void**)&psync, g_sync);

    cudaFuncSetAttribute(attention_k, cudaFuncAttributeMaxDynamicSharedMemorySize, 131072);
    cudaFuncSetAttribute(lstm_persist_k, cudaFuncAttributeMaxDynamicSharedMemorySize, 137216);

    const int M = 16384;
    dim3 g2(2, 128);   // N=256
    dim3 g1(1, 128);   // N=128
    dim3 g8(8, 128);   // N=1024

    // LSTM weight prep + barrier reset (runs every call for determinism)
    lstm_prep_k<<<1024, 256>>>(wih, whh, bih, bhh, dec_h0, out_w1,
                               pWET, pWmR, pw1t, pg0, pbt, psync);

    // Embed
    sgemm_k<<<g2, 256>>>(inputs, embed_w, embed_b, nullptr, px, M, 256, 300, 0);

    // Transformer layers
    for (int l = 0; l < 6; l++) {
        const float* Wq = qkvo_w + (size_t)(l * 4 + 0) * 65536;
        const float* Wk = qkvo_w + (size_t)(l * 4 + 1) * 65536;
        const float* Wv = qkvo_w + (size_t)(l * 4 + 2) * 65536;
        const float* Wo = qkvo_w + (size_t)(l * 4 + 3) * 65536;
        const float* bq = qkvo_b + (l * 4 + 0) * 256;
        const float* bk = qkvo_b + (l * 4 + 1) * 256;
        const float* bv = qkvo_b + (l * 4 + 2) * 256;
        const float* bo = qkvo_b + (l * 4 + 3) * 256;

        layernorm_k<<<2048, 256>>>(px, ln_g + l * 512, ln_b + l * 512, py);
        sgemm_k<<<g2, 256>>>(py, Wq, bq, nullptr, pq, M, 256, 256, 0);
        sgemm_k<<<g2, 256>>>(py, Wk, bk, nullptr, pk, M, 256, 256, 0);
        sgemm_k<<<g2, 256>>>(py, Wv, bv, nullptr, pv, M, 256, 256, 0);
        attention_k<<<256, 512, 131072>>>(pq, pk, pv, mask, po);
        sgemm_k<<<g2, 256>>>(po, Wo, bo, px, px, M, 256, 256, 0);

        layernorm_k<<<2048, 256>>>(px, ln_g + l * 512 + 256, ln_b + l * 512 + 256, py);
        sgemm_k<<<g1, 256>>>(py, ff_w1 + (size_t)l * 256 * 128, ff_b1 + l * 128,
                             nullptr, ph1, M, 128, 256, 1);
        sgemm_k<<<g2, 256>>>(ph1, ff_w2 + (size_t)l * 128 * 256, ff_b2 + l * 256,
                             px, px, M, 256, 128, 0);
    }

    // Encoder LN -> enc (in py)
    layernorm_k<<<2048, 256>>>(px, enc_ln_g, enc_ln_b, py);

    // pre = enc @ wih[:,256:].T + (bih+bhh)
    sgemm_k<<<g8, 256>>>(py, pWET, pbt, nullptr, ppre, M, 1024, 256, 0);

    // Persistent LSTM scan + output head (single launch, 96 blocks)
    lstm_persist_k<<<96, 256, 137216>>>(ppre, pWmR, pw1t, pg0, dec_c0,
                                        out_b1, out_w2, out_b2, mask,
                                        phb, psync, out);
}

// round 4
// speedup vs baseline: 1.6613x; 1.3184x over previous
#include <cuda_runtime.h>
#include <cuda_bf16.h>
#include <math.h>

// ---------------------------------------------------------------------------
// Scratch (device globals — allocation-free per harness rules)
// ---------------------------------------------------------------------------
__device__ float g_x   [16384 * 256];
__device__ float g_y   [16384 * 256];
__device__ float g_qkv [3 * 16384 * 256];
__device__ float g_o   [16384 * 256];
__device__ float g_h1  [16384 * 128];
__device__ float g_pre [16384 * 1024];
__device__ float g_WihEncT[256 * 1024];   // (wih[:,256:512]).T  -> [k][n]
__device__ float g_WmR [64 * 4096];       // merged (wih[:,:256]+whh).T per gate-block
__device__ float g_w1t [128 * 256];       // out_w1 transposed [h][k]
__device__ float g_g0  [1024];            // dec_h0 @ whh.T
__device__ float g_biasTot[1024];         // bih + bhh
__device__ float g_hbuf[2 * 32 * 256];
__device__ unsigned g_sync;               // grid barrier counter (zeroed in prep)

// ---------------------------------------------------------------------------
// tf32 helpers
// ---------------------------------------------------------------------------
__device__ __forceinline__ unsigned f2tf(float f) {
    unsigned u;
    asm("cvt.rna.tf32.f32 %0, %1;" : "=r"(u) : "f"(f));
    return u;
}

__device__ __forceinline__ void mma_tf32(float (&d)[4], const unsigned (&a)[4],
                                         const unsigned (&b)[2]) {
    asm volatile(
        "mma.sync.aligned.m16n8k8.row.col.f32.tf32.tf32.f32 "
        "{%0,%1,%2,%3}, {%4,%5,%6,%7}, {%8,%9}, {%0,%1,%2,%3};"
        : "+f"(d[0]), "+f"(d[1]), "+f"(d[2]), "+f"(d[3])
        : "r"(a[0]), "r"(a[1]), "r"(a[2]), "r"(a[3]), "r"(b[0]), "r"(b[1]));
}

__device__ __forceinline__ float4 ldA4g(const float* A, int r, int c, int K) {
    if (c + 3 < K) return *(const float4*)(A + (size_t)r * K + c);
    float4 v;
    v.x = (c     < K) ? A[(size_t)r * K + c]     : 0.f;
    v.y = (c + 1 < K) ? A[(size_t)r * K + c + 1] : 0.f;
    v.z = (c + 2 < K) ? A[(size_t)r * K + c + 2] : 0.f;
    v.w = (c + 3 < K) ? A[(size_t)r * K + c + 3] : 0.f;
    return v;
}

// ---------------------------------------------------------------------------
// tf32 tensor-core GEMM: C = [res +] A(MxK) @ B(KxN) + bias(N) [, relu]
// BM=BN=128, BK=16, 256 threads (8 warps, 2x4), warp tile 64x32 via m16n8k8.
// Multi-matrix support: bx -> (mat, col-block) with per-matrix B/C/bias strides.
// M%128==0, N%128==0.
// ---------------------------------------------------------------------------
__global__ __launch_bounds__(256, 2) void gemm_tc(
    const float* __restrict__ A, const float* __restrict__ B,
    const float* __restrict__ bias, const float* __restrict__ res,
    float* __restrict__ C, int M, int N, int K, int relu,
    int nxPerMat, long bMatStride, long cMatStride, int biasMatStride)
{
    __shared__ unsigned As[2][128][20];   // stride 20: conflict-free frag reads
    __shared__ unsigned Bs[2][16][136];   // stride 136 (mod32=8): conflict-free

    const int tid = threadIdx.x;
    const int bx = blockIdx.x, by = blockIdx.y;
    const int mat = bx / nxPerMat;
    const int bxn = bx - mat * nxPerMat;

    const float* Bp    = B + (size_t)mat * bMatStride;
    const float* biasP = bias + (size_t)mat * biasMatStride;
    float*       Cp    = C + (size_t)mat * cMatStride;

    const float* Ablk = A + (size_t)(by * 128) * K;
    const float* Bblk = Bp + bxn * 128;

    const int lane = tid & 31, wid = tid >> 5;
    const int wm = wid >> 2, wn = wid & 3;
    const int gid = lane >> 2, tg = lane & 3;

    // load-mapping: two float4 per thread per tile
    const int f0 = tid, f1 = tid + 256;
    const int ar0 = f0 >> 2, ac0 = (f0 & 3) << 2;
    const int ar1 = f1 >> 2, ac1 = (f1 & 3) << 2;
    const int bk0 = f0 >> 5, bc0 = (f0 & 31) << 2;
    const int bk1 = f1 >> 5, bc1 = (f1 & 31) << 2;

    float acc[4][4][4];
#pragma unroll
    for (int mt = 0; mt < 4; mt++)
#pragma unroll
        for (int nt = 0; nt < 4; nt++)
#pragma unroll
            for (int i = 0; i < 4; i++) acc[mt][nt][i] = 0.f;

    float4 av0, av1, bv0, bv1;

    // prologue: stage tile 0
    av0 = ldA4g(Ablk, ar0, ac0, K);
    av1 = ldA4g(Ablk, ar1, ac1, K);
    bv0 = (bk0 < K) ? *(const float4*)(Bblk + (size_t)bk0 * N + bc0) : make_float4(0,0,0,0);
    bv1 = (bk1 < K) ? *(const float4*)(Bblk + (size_t)bk1 * N + bc1) : make_float4(0,0,0,0);
    {
        As[0][ar0][ac0+0] = f2tf(av0.x); As[0][ar0][ac0+1] = f2tf(av0.y);
        As[0][ar0][ac0+2] = f2tf(av0.z); As[0][ar0][ac0+3] = f2tf(av0.w);
        As[0][ar1][ac1+0] = f2tf(av1.x); As[0][ar1][ac1+1] = f2tf(av1.y);
        As[0][ar1][ac1+2] = f2tf(av1.z); As[0][ar1][ac1+3] = f2tf(av1.w);
        uint4 p0 = make_uint4(f2tf(bv0.x), f2tf(bv0.y), f2tf(bv0.z), f2tf(bv0.w));
        uint4 p1 = make_uint4(f2tf(bv1.x), f2tf(bv1.y), f2tf(bv1.z), f2tf(bv1.w));
        *(uint4*)&Bs[0][bk0][bc0] = p0;
        *(uint4*)&Bs[0][bk1][bc1] = p1;
    }
    __syncthreads();

    int cur = 0;
    for (int k0 = 0; k0 < K; k0 += 16) {
        const bool hn = (k0 + 16 < K);
        if (hn) {
            av0 = ldA4g(Ablk, ar0, k0 + 16 + ac0, K);
            av1 = ldA4g(Ablk, ar1, k0 + 16 + ac1, K);
            bv0 = (k0 + 16 + bk0 < K)
                ? *(const float4*)(Bblk + (size_t)(k0 + 16 + bk0) * N + bc0) : make_float4(0,0,0,0);
            bv1 = (k0 + 16 + bk1 < K)
                ? *(const float4*)(Bblk + (size_t)(k0 + 16 + bk1) * N + bc1) : make_float4(0,0,0,0);
        }

#pragma unroll
        for (int ks = 0; ks < 16; ks += 8) {
            unsigned a[4][4], b[4][2];
#pragma unroll
            for (int mt = 0; mt < 4; mt++) {
                int r = wm * 64 + mt * 16 + gid;
                a[mt][0] = As[cur][r][ks + tg];
                a[mt][1] = As[cur][r + 8][ks + tg];
                a[mt][2] = As[cur][r][ks + tg + 4];
                a[mt][3] = As[cur][r + 8][ks + tg + 4];
            }
#pragma unroll
            for (int nt = 0; nt < 4; nt++) {
                int cb = wn * 32 + nt * 8 + gid;
                b[nt][0] = Bs[cur][ks + tg][cb];
                b[nt][1] = Bs[cur][ks + tg + 4][cb];
            }
#pragma unroll
            for (int mt = 0; mt < 4; mt++)
#pragma unroll
                for (int nt = 0; nt < 4; nt++)
                    mma_tf32(acc[mt][nt], a[mt], b[nt]);
        }

        if (hn) {
            int nxt = cur ^ 1;
            As[nxt][ar0][ac0+0] = f2tf(av0.x); As[nxt][ar0][ac0+1] = f2tf(av0.y);
            As[nxt][ar0][ac0+2] = f2tf(av0.z); As[nxt][ar0][ac0+3] = f2tf(av0.w);
            As[nxt][ar1][ac1+0] = f2tf(av1.x); As[nxt][ar1][ac1+1] = f2tf(av1.y);
            As[nxt][ar1][ac1+2] = f2tf(av1.z); As[nxt][ar1][ac1+3] = f2tf(av1.w);
            uint4 p0 = make_uint4(f2tf(bv0.x), f2tf(bv0.y), f2tf(bv0.z), f2tf(bv0.w));
            uint4 p1 = make_uint4(f2tf(bv1.x), f2tf(bv1.y), f2tf(bv1.z), f2tf(bv1.w));
            *(uint4*)&Bs[nxt][bk0][bc0] = p0;
            *(uint4*)&Bs[nxt][bk1][bc1] = p1;
            __syncthreads();
            cur = nxt;
        }
    }

    // epilogue
#pragma unroll
    for (int mt = 0; mt < 4; mt++) {
        int r0 = by * 128 + wm * 64 + mt * 16 + gid;
#pragma unroll
        for (int nt = 0; nt < 4; nt++) {
            int c0 = bxn * 128 + wn * 32 + nt * 8 + tg * 2;
            float bza = biasP[c0], bzb = biasP[c0 + 1];
            size_t off0 = (size_t)r0 * N + c0;
            size_t off1 = (size_t)(r0 + 8) * N + c0;
            float v0 = acc[mt][nt][0] + bza, v1 = acc[mt][nt][1] + bzb;
            float v2 = acc[mt][nt][2] + bza, v3 = acc[mt][nt][3] + bzb;
            if (res) {
                v0 += res[off0]; v1 += res[off0 + 1];
                v2 += res[off1]; v3 += res[off1 + 1];
            }
            if (relu) {
                v0 = fmaxf(v0, 0.f); v1 = fmaxf(v1, 0.f);
                v2 = fmaxf(v2, 0.f); v3 = fmaxf(v3, 0.f);
            }
            *(float2*)(Cp + off0) = make_float2(v0, v1);
            *(float2*)(Cp + off1) = make_float2(v2, v3);
        }
    }
}

// ---------------------------------------------------------------------------
// LayerNorm: warp per row (E=256), float4, 8 rows per 256-thread block.
// var = sum((x-mean)^2)/(n-1); denom = sqrt(var)+eps (reference semantics)
// ---------------------------------------------------------------------------
__global__ __launch_bounds__(256) void layernorm_k(
    const float* __restrict__ x, const float* __restrict__ g,
    const float* __restrict__ b, float* __restrict__ y)
{
    int tid = threadIdx.x;
    int lane = tid & 31;
    int row = blockIdx.x * 8 + (tid >> 5);

    const float4* xr = (const float4*)(x + (size_t)row * 256);
    float4 v0 = xr[lane], v1 = xr[lane + 32];

    float s = v0.x + v0.y + v0.z + v0.w + v1.x + v1.y + v1.z + v1.w;
#pragma unroll
    for (int o = 16; o > 0; o >>= 1) s += __shfl_xor_sync(0xffffffffu, s, o);
    float mean = s * (1.f / 256.f);

    float4 d0 = make_float4(v0.x - mean, v0.y - mean, v0.z - mean, v0.w - mean);
    float4 d1 = make_float4(v1.x - mean, v1.y - mean, v1.z - mean, v1.w - mean);
    float sq = d0.x * d0.x + d0.y * d0.y + d0.z * d0.z + d0.w * d0.w
             + d1.x * d1.x + d1.y * d1.y + d1.z * d1.z + d1.w * d1.w;
#pragma unroll
    for (int o = 16; o > 0; o >>= 1) sq += __shfl_xor_sync(0xffffffffu, sq, o);
    float var = sq * (1.f / 255.f);
    float r = 1.f / (sqrtf(var) + 1e-6f);

    const float4* g4 = (const float4*)g;
    const float4* b4 = (const float4*)b;
    float4 gg0 = g4[lane], gg1 = g4[lane + 32];
    float4 bb0 = b4[lane], bb1 = b4[lane + 32];

    float4 o0, o1;
    o0.x = gg0.x * d0.x * r + bb0.x; o0.y = gg0.y * d0.y * r + bb0.y;
    o0.z = gg0.z * d0.z * r + bb0.z; o0.w = gg0.w * d0.w * r + bb0.w;
    o1.x = gg1.x * d1.x * r + bb1.x; o1.y = gg1.y * d1.y * r + bb1.y;
    o1.z = gg1.z * d1.z * r + bb1.z; o1.w = gg1.w * d1.w * r + bb1.w;

    float4* yr = (float4*)(y + (size_t)row * 256);
    yr[lane] = o0;
    yr[lane + 32] = o1;
}

// ---------------------------------------------------------------------------
// Fused attention: one block per (b,h). K,V tiles (512x32) in smem, float4,
// chunk-of-8 online softmax. 512 threads, one q-row per thread, dk=32.
// ---------------------------------------------------------------------------
__global__ __launch_bounds__(512) void attention_k(
    const float* __restrict__ Q, const float* __restrict__ K,
    const float* __restrict__ V, const float* __restrict__ mask,
    float* __restrict__ O)
{
    extern __shared__ float sm[];
    float* Ks = sm;
    float* Vs = sm + 512 * 32;

    int bh = blockIdx.x;
    int b = bh >> 3, h = bh & 7;
    int tid = threadIdx.x;

    const float* Kb = K + (size_t)(b * 512) * 256 + h * 32;
    const float* Vb = V + (size_t)(b * 512) * 256 + h * 32;
    for (int idx = tid; idx < 512 * 8; idx += 512) {
        int r = idx >> 3, d4 = idx & 7;
        ((float4*)Ks)[idx] = ((const float4*)(Kb + (size_t)r * 256))[d4];
        ((float4*)Vs)[idx] = ((const float4*)(Vb + (size_t)r * 256))[d4];
    }

    float4 q4[8];
    const float* Qr = Q + (size_t)(b * 512 + tid) * 256 + h * 32;
#pragma unroll
    for (int d4 = 0; d4 < 8; d4++) q4[d4] = ((const float4*)Qr)[d4];
    bool mz = (mask[b * 512 + tid] == 0.f);
    __syncthreads();

    const float scale = 0.17677669529663689f;  // 1/sqrt(32)
    float m = -1e30f, l = 0.f, acc[32];
#pragma unroll
    for (int d = 0; d < 32; d++) acc[d] = 0.f;

    for (int j0 = 0; j0 < 512; j0 += 8) {
        float s[8];
#pragma unroll
        for (int jj = 0; jj < 8; jj++) {
            const float4* kr = (const float4*)(Ks + (j0 + jj) * 32);
            float a = 0.f;
#pragma unroll
            for (int d4 = 0; d4 < 8; d4++) {
                float4 kv = kr[d4];
                a = fmaf(q4[d4].x, kv.x, a);
                a = fmaf(q4[d4].y, kv.y, a);
                a = fmaf(q4[d4].z, kv.z, a);
                a = fmaf(q4[d4].w, kv.w, a);
            }
            s[jj] = a * scale;
        }
        if (mz) {
#pragma unroll
            for (int jj = 0; jj < 8; jj++) s[jj] = -1e9f;
        }
        float cm = s[0];
#pragma unroll
        for (int jj = 1; jj < 8; jj++) cm = fmaxf(cm, s[jj]);
        float mn = fmaxf(m, cm);
        float corr = __expf(m - mn);
        m = mn;
        l *= corr;
#pragma unroll
        for (int d = 0; d < 32; d++) acc[d] *= corr;
#pragma unroll
        for (int jj = 0; jj < 8; jj++) {
            float p = __expf(s[jj] - mn);
            l += p;
            const float4* vr = (const float4*)(Vs + (j0 + jj) * 32);
#pragma unroll
            for (int d4 = 0; d4 < 8; d4++) {
                float4 vv = vr[d4];
                acc[d4 * 4 + 0] = fmaf(p, vv.x, acc[d4 * 4 + 0]);
                acc[d4 * 4 + 1] = fmaf(p, vv.y, acc[d4 * 4 + 1]);
                acc[d4 * 4 + 2] = fmaf(p, vv.z, acc[d4 * 4 + 2]);
                acc[d4 * 4 + 3] = fmaf(p, vv.w, acc[d4 * 4 + 3]);
            }
        }
    }
    float inv = 1.f / l;
    float* Or = O + (size_t)(b * 512 + tid) * 256 + h * 32;
#pragma unroll
    for (int d = 0; d < 32; d++) Or[d] = acc[d] * inv;
}

// ---------------------------------------------------------------------------
// LSTM prep: build transposed/merged weights, g0, biasTot, w1t; zero barrier.
// ---------------------------------------------------------------------------
__global__ __launch_bounds__(256) void lstm_prep_k(
    const float* __restrict__ wih, const float* __restrict__ whh,
    const float* __restrict__ bih, const float* __restrict__ bhh,
    const float* __restrict__ dec_h0, const float* __restrict__ out_w1,
    float* __restrict__ WihEncT, float* __restrict__ WmR,
    float* __restrict__ w1t, float* __restrict__ g0,
    float* __restrict__ biasTot, unsigned* __restrict__ sync)
{
    int idx = blockIdx.x * 256 + threadIdx.x;
    if (idx == 0) *sync = 0u;
    if (idx < 262144) {
        int k = idx >> 10, n = idx & 1023;
        WihEncT[idx] = wih[(size_t)n * 512 + 256 + k];

        int gb = idx >> 12;
        int r = idx & 4095;
        int gi = r >> 10;
        int rem = r & 1023;
        int el = rem >> 8;
        int kk = rem & 255;
        int col = gi * 256 + gb * 4 + el;
        WmR[idx] = wih[(size_t)col * 512 + kk] + whh[(size_t)col * 256 + kk];
    }
    if (idx < 32768) {
        int h = idx >> 8, k = idx & 255;
        w1t[idx] = out_w1[(size_t)k * 128 + h];
    }
    if (idx < 1024) {
        float a = 0.f;
        for (int k = 0; k < 256; k++) a = fmaf(dec_h0[k], whh[(size_t)idx * 256 + k], a);
        g0[idx] = a;
        biasTot[idx] = bih[idx] + bhh[idx];
    }
}

// ---------------------------------------------------------------------------
// Persistent LSTM: 96 blocks (64 gate + 32 MLP), all co-resident (1/SM),
// custom grid barrier on g_sync.
// ---------------------------------------------------------------------------
__device__ __forceinline__ float sigf(float x) { return 1.f / (1.f + __expf(-x)); }

__device__ __forceinline__ void grid_bar(unsigned* sync, unsigned target) {
    __threadfence();
    __syncthreads();
    if (threadIdx.x == 0) {
        atomicAdd(sync, 1u);
        while (*(volatile unsigned*)sync < target) { __nanosleep(20); }
        __threadfence();
    }
    __syncthreads();
}

__global__ __launch_bounds__(256, 1) void lstm_persist_k(
    const float* __restrict__ pre, const float* __restrict__ WmR,
    const float* __restrict__ w1t, const float* __restrict__ g0,
    const float* __restrict__ dec_c0,
    const float* __restrict__ b1, const float* __restrict__ w2,
    const float* __restrict__ b2, const float* __restrict__ mask,
    float* __restrict__ hbuf, unsigned* __restrict__ sync,
    float* __restrict__ out)
{
    extern __shared__ float sm[];
    const int tid = threadIdx.x;
    const unsigned NBLK = 96;

    if (blockIdx.x < 64) {
        const int gb = blockIdx.x;
        const int half = tid & 1;
        const int p = tid >> 1;
        const int b = p & 31;
        const int el = p >> 5;
        const int e = gb * 4 + el;

        float4* ws4 = (float4*)sm;
        float4* hs4 = (float4*)(sm + 4096);

        const float4* wsrc = (const float4*)(WmR + (size_t)gb * 4096);
        for (int i = tid; i < 1024; i += 256) ws4[i] = wsrc[i];

        float c = dec_c0[e];

        for (int t = 0; t < 512; ++t) {
            float gv0 = 0.f, gv1 = 0.f, gv2 = 0.f, gv3 = 0.f;
            if (t == 0) {
                if (half == 0) {
                    const float* pr = pre + (size_t)b * 512 * 1024;
                    gv0 = pr[e]       + g0[e];
                    gv1 = pr[256 + e] + g0[256 + e];
                    gv2 = pr[512 + e] + g0[512 + e];
                    gv3 = pr[768 + e] + g0[768 + e];
                }
            } else {
                const float4* hsrc = (const float4*)(hbuf + (t & 1) * 8192);
                for (int j = tid; j < 2048; j += 256) {
                    float4 v = __ldcg(hsrc + j);
                    int bb = j >> 6, k4 = j & 63;
                    hs4[bb * 66 + (k4 >> 5) * 33 + (k4 & 31)] = v;
                }
                __syncthreads();

                float a0 = 0.f, a1 = 0.f, a2 = 0.f, a3 = 0.f;
                const float4* hp = hs4 + b * 66 + half * 33;
                const float4* wp = ws4 + el * 64 + half * 32;
#pragma unroll
                for (int kk = 0; kk < 32; kk++) {
                    float4 hv = hp[kk];
                    float4 w0 = wp[kk];
                    float4 w1v = wp[256 + kk];
                    float4 w2v = wp[512 + kk];
                    float4 w3v = wp[768 + kk];
                    a0 = fmaf(hv.x, w0.x, fmaf(hv.y, w0.y, fmaf(hv.z, w0.z, fmaf(hv.w, w0.w, a0))));
                    a1 = fmaf(hv.x, w1v.x, fmaf(hv.y, w1v.y, fmaf(hv.z, w1v.z, fmaf(hv.w, w1v.w, a1))));
                    a2 = fmaf(hv.x, w2v.x, fmaf(hv.y, w2v.y, fmaf(hv.z, w2v.z, fmaf(hv.w, w2v.w, a2))));
                    a3 = fmaf(hv.x, w3v.x, fmaf(hv.y, w3v.y, fmaf(hv.z, w3v.z, fmaf(hv.w, w3v.w, a3))));
                }
                a0 += __shfl_xor_sync(0xffffffffu, a0, 1);
                a1 += __shfl_xor_sync(0xffffffffu, a1, 1);
                a2 += __shfl_xor_sync(0xffffffffu, a2, 1);
                a3 += __shfl_xor_sync(0xffffffffu, a3, 1);
                if (half == 0) {
                    const float* pr = pre + ((size_t)b * 512 + t) * 1024;
                    gv0 = a0 + pr[e];
                    gv1 = a1 + pr[256 + e];
                    gv2 = a2 + pr[512 + e];
                    gv3 = a3 + pr[768 + e];
                }
            }
            if (half == 0) {
                float cn = sigf(gv1) * c + sigf(gv0) * tanhf(gv2);
                float hn = sigf(gv3) * tanhf(cn);
                c = cn;
                __stcg(hbuf + ((t + 1) & 1) * 8192 + b * 256 + e, hn);
            }
            grid_bar(sync, (unsigned)(t + 1) * NBLK);
        }
    } else {
        const int b = blockIdx.x - 64;
        float* w1s  = sm;
        float* hrow = sm + 33280;
        float* red  = sm + 33536;

        for (int i = tid; i < 8192; i += 256) {
            int h = i >> 6, k4 = i & 63;
            ((float4*)w1s)[h * 65 + k4] = ((const float4*)w1t)[i];
        }
        float w2v = (tid < 128) ? w2[tid] : 0.f;
        float b1v = (tid < 128) ? b1[tid] : 0.f;
        float b2v = b2[0];

        for (int t = 0; t <= 512; ++t) {
            if (t >= 1) {
                hrow[tid] = __ldcg(hbuf + (t & 1) * 8192 + b * 256 + tid);
                __syncthreads();
                float contrib = 0.f;
                if (tid < 128) {
                    float a = b1v;
                    const float4* h4 = (const float4*)hrow;
                    const float4* w4 = (const float4*)(w1s + tid * 260);
#pragma unroll 16
                    for (int kk = 0; kk < 64; kk++) {
                        float4 hv = h4[kk];
                        float4 wv = w4[kk];
                        a = fmaf(hv.x, wv.x, fmaf(hv.y, wv.y, fmaf(hv.z, wv.z, fmaf(hv.w, wv.w, a))));
                    }
                    contrib = fmaxf(a, 0.f) * w2v;
                }
#pragma unroll
                for (int o = 16; o > 0; o >>= 1)
                    contrib += __shfl_down_sync(0xffffffffu, contrib, o);
                if (tid < 128 && (tid & 31) == 0) red[tid >> 5] = contrib;
                __syncthreads();
                if (tid == 0) {
                    float pp = red[0] + red[1] + red[2] + red[3] + b2v;
                    out[b * 512 + (t - 1)] = pp * mask[b * 512 + (t - 1)];
                }
                __syncthreads();
            }
            if (t < 512) grid_bar(sync, (unsigned)(t + 1) * NBLK);
        }
    }
}

// ---------------------------------------------------------------------------
// Launcher
// ---------------------------------------------------------------------------
extern "C" void kernel_launch(void* const* d_in, const int* in_sizes, int n_in,
                              void* d_out, int out_size)
{
    const float* inputs   = (const float*)d_in[0];
    const float* mask     = (const float*)d_in[1];
    /* d_in[2] = lengths (unused) */
    const float* embed_w  = (const float*)d_in[3];
    const float* embed_b  = (const float*)d_in[4];
    const float* qkvo_w   = (const float*)d_in[5];
    const float* qkvo_b   = (const float*)d_in[6];
    const float* ln_g     = (const float*)d_in[7];
    const float* ln_b     = (const float*)d_in[8];
    const float* ff_w1    = (const float*)d_in[9];
    const float* ff_b1    = (const float*)d_in[10];
    const float* ff_w2    = (const float*)d_in[11];
    const float* ff_b2    = (const float*)d_in[12];
    const float* enc_ln_g = (const float*)d_in[13];
    const float* enc_ln_b = (const float*)d_in[14];
    const float* wih      = (const float*)d_in[15];
    const float* whh      = (const float*)d_in[16];
    const float* bih      = (const float*)d_in[17];
    const float* bhh      = (const float*)d_in[18];
    const float* dec_h0   = (const float*)d_in[19];
    const float* dec_c0   = (const float*)d_in[20];
    const float* out_w1   = (const float*)d_in[21];
    const float* out_b1   = (const float*)d_in[22];
    const float* out_w2   = (const float*)d_in[23];
    const float* out_b2   = (const float*)d_in[24];
    float* out = (float*)d_out;
    (void)in_sizes; (void)n_in; (void)out_size;

    float *px, *py, *pqkv, *po, *ph1, *ppre, *pWET, *pWmR, *pw1t, *pg0, *pbt, *phb;
    unsigned* psync;
    cudaGetSymbolAddress((void**)&px,    g_x);
    cudaGetSymbolAddress((void**)&py,    g_y);
    cudaGetSymbolAddress((void**)&pqkv,  g_qkv);
    cudaGetSymbolAddress((void**)&po,    g_o);
    cudaGetSymbolAddress((void**)&ph1,   g_h1);
    cudaGetSymbolAddress((void**)&ppre,  g_pre);
    cudaGetSymbolAddress((void**)&pWET,  g_WihEncT);
    cudaGetSymbolAddress((void**)&pWmR,  g_WmR);
    cudaGetSymbolAddress((void**)&pw1t,  g_w1t);
    cudaGetSymbolAddress((void**)&pg0,   g_g0);
    cudaGetSymbolAddress((void**)&pbt,   g_biasTot);
    cudaGetSymbolAddress((void**)&phb,   g_hbuf);
    cudaGetSymbolAddress((void**)&psync, g_sync);

    cudaFuncSetAttribute(attention_k, cudaFuncAttributeMaxDynamicSharedMemorySize, 131072);
    cudaFuncSetAttribute(lstm_persist_k, cudaFuncAttributeMaxDynamicSharedMemorySize, 137216);

    const int M = 16384;
    const long QKV_C = 16384L * 256;

    // LSTM weight prep + barrier reset
    lstm_prep_k<<<1024, 256>>>(wih, whh, bih, bhh, dec_h0, out_w1,
                               pWET, pWmR, pw1t, pg0, pbt, psync);

    // Embed (K=300)
    gemm_tc<<<dim3(2, 128), 256>>>(inputs, embed_w, embed_b, nullptr, px,
                                   M, 256, 300, 0, 2, 0, 0, 0);

    // Transformer layers
    for (int l = 0; l < 6; l++) {
        const float* Wq = qkvo_w + (size_t)(l * 4) * 65536;
        const float* Wo = qkvo_w + (size_t)(l * 4 + 3) * 65536;
        const float* bq = qkvo_b + (l * 4) * 256;
        const float* bo = qkvo_b + (l * 4 + 3) * 256;

        layernorm_k<<<2048, 256>>>(px, ln_g + l * 512, ln_b + l * 512, py);
        // fused Q,K,V: 3 matrices x 2 col-blocks
        gemm_tc<<<dim3(6, 128), 256>>>(py, Wq, bq, nullptr, pqkv,
                                       M, 256, 256, 0, 2, 65536, QKV_C, 256);
        attention_k<<<256, 512, 131072>>>(pqkv, pqkv + QKV_C, pqkv + 2 * QKV_C,
                                          mask, po);
        gemm_tc<<<dim3(2, 128), 256>>>(po, Wo, bo, px, px,
                                       M, 256, 256, 0, 2, 0, 0, 0);

        layernorm_k<<<2048, 256>>>(px, ln_g + l * 512 + 256, ln_b + l * 512 + 256, py);
        gemm_tc<<<dim3(1, 128), 256>>>(py, ff_w1 + (size_t)l * 256 * 128,
                                       ff_b1 + l * 128, nullptr, ph1,
                                       M, 128, 256, 1, 1, 0, 0, 0);
        gemm_tc<<<dim3(2, 128), 256>>>(ph1, ff_w2 + (size_t)l * 128 * 256,
                                       ff_b2 + l * 256, px, px,
                                       M, 256, 128, 0, 2, 0, 0, 0);
    }

    // Encoder LN -> enc (in py)
    layernorm_k<<<2048, 256>>>(px, enc_ln_g, enc_ln_b, py);

    // pre = enc @ wih[:,256:].T + (bih+bhh)
    gemm_tc<<<dim3(8, 128), 256>>>(py, pWET, pbt, nullptr, ppre,
                                   M, 1024, 256, 0, 8, 0, 0, 0);

    // Persistent LSTM scan + output head (single launch, 96 blocks)
    lstm_persist_k<<<96, 256, 137216>>>(ppre, pWmR, pw1t, pg0, dec_c0,
                                        out_b1, out_w2, out_b2, mask,
                                        phb, psync, out);
}

// round 5
// speedup vs baseline: 2.1507x; 1.2946x over previous
#include <cuda_runtime.h>
#include <cuda_bf16.h>
#include <math.h>

// ---------------------------------------------------------------------------
// Scratch (device globals — allocation-free per harness rules)
// ---------------------------------------------------------------------------
__device__ float g_x   [16384 * 256];
__device__ float g_y   [16384 * 256];
__device__ float g_qkv [3 * 16384 * 256];
__device__ float g_o   [16384 * 256];
__device__ float g_h1  [16384 * 128];
__device__ float g_pre [16384 * 1024];
__device__ float g_inT [16384 * 300];     // tf32-rounded inputs
__device__ float g_wtf [2042880];         // tf32-rounded weights (emb|qkvo|ff1|ff2)
__device__ float g_WihEncT[256 * 1024];   // (wih[:,256:512]).T, tf32-rounded
__device__ float g_WmR [64 * 4096];       // merged (wih[:,:256]+whh).T per gate-block
__device__ float g_w1t [128 * 256];       // out_w1 transposed [h][k]
__device__ float g_g0  [1024];            // dec_h0 @ whh.T
__device__ float g_biasTot[1024];         // bih + bhh
__device__ float g_hbuf[2 * 32 * 256];
__device__ unsigned g_sync;               // grid barrier counter (zeroed in prep)

#define OFF_EMB  0
#define OFF_QKVO 76800
#define OFF_FF1  1649664
#define OFF_FF2  1846272

// ---------------------------------------------------------------------------
// tf32 / mma helpers
// ---------------------------------------------------------------------------
__device__ __forceinline__ unsigned f2tf(float f) {
    unsigned u;
    asm("cvt.rna.tf32.f32 %0, %1;" : "=r"(u) : "f"(f));
    return u;
}
__device__ __forceinline__ float tfv(float f) { return __uint_as_float(f2tf(f)); }

__device__ __forceinline__ void mma_tf32(float (&d)[4], const unsigned (&a)[4],
                                         const unsigned (&b)[2]) {
    asm volatile(
        "mma.sync.aligned.m16n8k8.row.col.f32.tf32.tf32.f32 "
        "{%0,%1,%2,%3}, {%4,%5,%6,%7}, {%8,%9}, {%0,%1,%2,%3};"
        : "+f"(d[0]), "+f"(d[1]), "+f"(d[2]), "+f"(d[3])
        : "r"(a[0]), "r"(a[1]), "r"(a[2]), "r"(a[3]), "r"(b[0]), "r"(b[1]));
}

__device__ __forceinline__ void cp16(unsigned dst, const void* src, int bytes) {
    asm volatile("cp.async.cg.shared.global [%0], [%1], 16, %2;"
                 :: "r"(dst), "l"(src), "r"(bytes));
}
__device__ __forceinline__ void cp_commit() {
    asm volatile("cp.async.commit_group;" ::: "memory");
}
__device__ __forceinline__ void cp_wait0() {
    asm volatile("cp.async.wait_group 0;" ::: "memory");
}

// ---------------------------------------------------------------------------
// tf32 tensor-core GEMM (inputs pre-rounded to tf32 values; no in-kernel cvt).
// C = [res +] A(MxK) @ B(KxN) + bias(N) [, relu][, outCvt -> tf32-rounded out]
// BM=BN=128, BK=16, 256 threads (8 warps 2x4), warp tile 64x32, cp.async DB.
// ---------------------------------------------------------------------------
__global__ __launch_bounds__(256, 2) void gemm_tc(
    const float* __restrict__ A, const float* __restrict__ B,
    const float* __restrict__ bias, const float* __restrict__ res,
    float* __restrict__ C, int M, int N, int K, int relu, int outCvt,
    int nxPerMat, long bMatStride, long cMatStride, int biasMatStride)
{
    __shared__ unsigned As[2][128][20];   // [buf][row][k] stride 20
    __shared__ unsigned Bs[2][16][136];   // [buf][k][col] stride 136

    const int tid = threadIdx.x;
    const int bx = blockIdx.x, by = blockIdx.y;
    const int mat = bx / nxPerMat;
    const int bxn = bx - mat * nxPerMat;

    const float* Bp    = B + (size_t)mat * bMatStride;
    const float* biasP = bias + (size_t)mat * biasMatStride;
    float*       Cp    = C + (size_t)mat * cMatStride;

    const float* Ablk = A + (size_t)(by * 128) * K;
    const float* Bblk = Bp + bxn * 128;

    const int lane = tid & 31, wid = tid >> 5;
    const int wm = wid >> 2, wn = wid & 3;
    const int gid = lane >> 2, tg = lane & 3;

    const int ar0 = tid >> 2, ac0 = (tid & 3) << 2;
    const int ar1 = ar0 + 64;
    const int bk0 = tid >> 5, bc0 = (tid & 31) << 2;
    const int bk1 = bk0 + 8;

    const unsigned sA = (unsigned)__cvta_generic_to_shared(&As[0][0][0]);
    const unsigned sB = (unsigned)__cvta_generic_to_shared(&Bs[0][0][0]);

    float acc[4][4][4];
#pragma unroll
    for (int mt = 0; mt < 4; mt++)
#pragma unroll
        for (int nt = 0; nt < 4; nt++)
#pragma unroll
            for (int i = 0; i < 4; i++) acc[mt][nt][i] = 0.f;

    auto issue = [&](int buf, int k0) {
        int c0 = k0 + ac0;
        int rem0 = K - c0;
        int by0 = rem0 >= 4 ? 16 : (rem0 > 0 ? rem0 * 4 : 0);
        cp16(sA + ((buf * 128 + ar0) * 20 + ac0) * 4,
             Ablk + (size_t)ar0 * K + (by0 ? c0 : 0), by0);
        cp16(sA + ((buf * 128 + ar1) * 20 + ac0) * 4,
             Ablk + (size_t)ar1 * K + (by0 ? c0 : 0), by0);
        int kr0 = k0 + bk0;
        int bb0 = (kr0 < K) ? 16 : 0;
        cp16(sB + ((buf * 16 + bk0) * 136 + bc0) * 4,
             Bblk + (size_t)(bb0 ? kr0 : 0) * N + bc0, bb0);
        int kr1 = k0 + bk1;
        int bb1 = (kr1 < K) ? 16 : 0;
        cp16(sB + ((buf * 16 + bk1) * 136 + bc0) * 4,
             Bblk + (size_t)(bb1 ? kr1 : 0) * N + bc0, bb1);
        cp_commit();
    };

    issue(0, 0);
    int cur = 0;
    for (int k0 = 0; k0 < K; k0 += 16) {
        cp_wait0();
        __syncthreads();
        bool hn = (k0 + 16 < K);
        if (hn) issue(cur ^ 1, k0 + 16);

#pragma unroll
        for (int ks = 0; ks < 16; ks += 8) {
            unsigned a[4][4], b[4][2];
#pragma unroll
            for (int mt = 0; mt < 4; mt++) {
                int r = wm * 64 + mt * 16 + gid;
                a[mt][0] = As[cur][r][ks + tg];
                a[mt][1] = As[cur][r + 8][ks + tg];
                a[mt][2] = As[cur][r][ks + tg + 4];
                a[mt][3] = As[cur][r + 8][ks + tg + 4];
            }
#pragma unroll
            for (int nt = 0; nt < 4; nt++) {
                int cb = wn * 32 + nt * 8 + gid;
                b[nt][0] = Bs[cur][ks + tg][cb];
                b[nt][1] = Bs[cur][ks + tg + 4][cb];
            }
#pragma unroll
            for (int mt = 0; mt < 4; mt++)
#pragma unroll
                for (int nt = 0; nt < 4; nt++)
                    mma_tf32(acc[mt][nt], a[mt], b[nt]);
        }
        cur ^= 1;
    }

#pragma unroll
    for (int mt = 0; mt < 4; mt++) {
        int r0 = by * 128 + wm * 64 + mt * 16 + gid;
#pragma unroll
        for (int nt = 0; nt < 4; nt++) {
            int c0 = bxn * 128 + wn * 32 + nt * 8 + tg * 2;
            float bza = biasP[c0], bzb = biasP[c0 + 1];
            size_t off0 = (size_t)r0 * N + c0;
            size_t off1 = (size_t)(r0 + 8) * N + c0;
            float v0 = acc[mt][nt][0] + bza, v1 = acc[mt][nt][1] + bzb;
            float v2 = acc[mt][nt][2] + bza, v3 = acc[mt][nt][3] + bzb;
            if (res) {
                v0 += res[off0]; v1 += res[off0 + 1];
                v2 += res[off1]; v3 += res[off1 + 1];
            }
            if (relu) {
                v0 = fmaxf(v0, 0.f); v1 = fmaxf(v1, 0.f);
                v2 = fmaxf(v2, 0.f); v3 = fmaxf(v3, 0.f);
            }
            if (outCvt) {
                v0 = tfv(v0); v1 = tfv(v1); v2 = tfv(v2); v3 = tfv(v3);
            }
            *(float2*)(Cp + off0) = make_float2(v0, v1);
            *(float2*)(Cp + off1) = make_float2(v2, v3);
        }
    }
}

// ---------------------------------------------------------------------------
// LayerNorm: warp per row (E=256), float4, 8 rows/block; output tf32-rounded
// (LN outputs feed only GEMMs / attention mma).
// ---------------------------------------------------------------------------
__global__ __launch_bounds__(256) void layernorm_k(
    const float* __restrict__ x, const float* __restrict__ g,
    const float* __restrict__ b, float* __restrict__ y)
{
    int tid = threadIdx.x;
    int lane = tid & 31;
    int row = blockIdx.x * 8 + (tid >> 5);

    const float4* xr = (const float4*)(x + (size_t)row * 256);
    float4 v0 = xr[lane], v1 = xr[lane + 32];

    float s = v0.x + v0.y + v0.z + v0.w + v1.x + v1.y + v1.z + v1.w;
#pragma unroll
    for (int o = 16; o > 0; o >>= 1) s += __shfl_xor_sync(0xffffffffu, s, o);
    float mean = s * (1.f / 256.f);

    float4 d0 = make_float4(v0.x - mean, v0.y - mean, v0.z - mean, v0.w - mean);
    float4 d1 = make_float4(v1.x - mean, v1.y - mean, v1.z - mean, v1.w - mean);
    float sq = d0.x * d0.x + d0.y * d0.y + d0.z * d0.z + d0.w * d0.w
             + d1.x * d1.x + d1.y * d1.y + d1.z * d1.z + d1.w * d1.w;
#pragma unroll
    for (int o = 16; o > 0; o >>= 1) sq += __shfl_xor_sync(0xffffffffu, sq, o);
    float var = sq * (1.f / 255.f);
    float r = 1.f / (sqrtf(var) + 1e-6f);

    const float4* g4 = (const float4*)g;
    const float4* b4 = (const float4*)b;
    float4 gg0 = g4[lane], gg1 = g4[lane + 32];
    float4 bb0 = b4[lane], bb1 = b4[lane + 32];

    float4 o0, o1;
    o0.x = tfv(gg0.x * d0.x * r + bb0.x); o0.y = tfv(gg0.y * d0.y * r + bb0.y);
    o0.z = tfv(gg0.z * d0.z * r + bb0.z); o0.w = tfv(gg0.w * d0.w * r + bb0.w);
    o1.x = tfv(gg1.x * d1.x * r + bb1.x); o1.y = tfv(gg1.y * d1.y * r + bb1.y);
    o1.z = tfv(gg1.z * d1.z * r + bb1.z); o1.w = tfv(gg1.w * d1.w * r + bb1.w);

    float4* yr = (float4*)(y + (size_t)row * 256);
    yr[lane] = o0;
    yr[lane + 32] = o1;
}

// ---------------------------------------------------------------------------
// Tensor-core flash attention. Block = (qtile of 128 rows, bh). 8 warps,
// each warp owns 16 q-rows. K/V chunks of 128 keys staged in smem (tf32 bits,
// conflict-free strides 44/40), S via mma, online softmax in registers
// (row quads -> shfl), P staged to warp-private smem rows, PV via mma.
// ---------------------------------------------------------------------------
__global__ __launch_bounds__(256, 2) void attn_tc(
    const float* __restrict__ Q, const float* __restrict__ K,
    const float* __restrict__ V, const float* __restrict__ mask,
    float* __restrict__ O)
{
    extern __shared__ unsigned smu[];
    unsigned* Ks = smu;                        // [128][44]
    unsigned* Vs = smu + 128 * 44;             // [128][40]
    unsigned* Ps = smu + 128 * 44 + 128 * 40;  // [128][132]

    const int qt = blockIdx.x;   // 0..3
    const int bh = blockIdx.y;   // 0..255
    const int b = bh >> 3, h = bh & 7;
    const int tid = threadIdx.x;
    const int w = tid >> 5, lane = tid & 31;
    const int gid = lane >> 2, tg = lane & 3;

    const int r0 = w * 16 + gid;
    const int r1 = r0 + 8;
    const size_t qbase = ((size_t)(b * 512 + qt * 128)) * 256 + h * 32;
    const float scale = 0.17677669529663689f;  // 1/sqrt(32)

    unsigned aQ[4][4];
#pragma unroll
    for (int ks = 0; ks < 4; ks++) {
        aQ[ks][0] = f2tf(Q[qbase + (size_t)r0 * 256 + ks * 8 + tg] * scale);
        aQ[ks][1] = f2tf(Q[qbase + (size_t)r1 * 256 + ks * 8 + tg] * scale);
        aQ[ks][2] = f2tf(Q[qbase + (size_t)r0 * 256 + ks * 8 + tg + 4] * scale);
        aQ[ks][3] = f2tf(Q[qbase + (size_t)r1 * 256 + ks * 8 + tg + 4] * scale);
    }
    const bool mz0 = (mask[b * 512 + qt * 128 + r0] == 0.f);
    const bool mz1 = (mask[b * 512 + qt * 128 + r1] == 0.f);

    float m0 = -1e30f, m1 = -1e30f, l0 = 0.f, l1 = 0.f;
    float o[4][4];
#pragma unroll
    for (int nt = 0; nt < 4; nt++)
#pragma unroll
        for (int i = 0; i < 4; i++) o[nt][i] = 0.f;

    for (int kc = 0; kc < 4; kc++) {
        __syncthreads();   // prior S/PV reads of Ks/Vs complete
        const size_t kvbase = ((size_t)(b * 512 + kc * 128)) * 256 + h * 32;
        for (int idx = tid; idx < 1024; idx += 256) {
            int key = idx >> 3, d4 = idx & 7;
            const uint4* ks4 = (const uint4*)(K + kvbase + (size_t)key * 256) + d4;
            const uint4* vs4 = (const uint4*)(V + kvbase + (size_t)key * 256) + d4;
            *(uint4*)(Ks + key * 44 + d4 * 4) = *ks4;
            *(uint4*)(Vs + key * 40 + d4 * 4) = *vs4;
        }
        __syncthreads();

        // S = Q @ K^T
        float s[16][4];
#pragma unroll
        for (int nt = 0; nt < 16; nt++) {
            s[nt][0] = s[nt][1] = s[nt][2] = s[nt][3] = 0.f;
            const unsigned* kp = Ks + (nt * 8 + gid) * 44;
#pragma unroll
            for (int ks = 0; ks < 4; ks++) {
                unsigned bk[2] = { kp[ks * 8 + tg], kp[ks * 8 + tg + 4] };
                mma_tf32(s[nt], aQ[ks], bk);
            }
        }
        if (mz0) {
#pragma unroll
            for (int nt = 0; nt < 16; nt++) { s[nt][0] = -1e9f; s[nt][1] = -1e9f; }
        }
        if (mz1) {
#pragma unroll
            for (int nt = 0; nt < 16; nt++) { s[nt][2] = -1e9f; s[nt][3] = -1e9f; }
        }

        // online softmax
        float rm0 = -1e30f, rm1 = -1e30f;
#pragma unroll
        for (int nt = 0; nt < 16; nt++) {
            rm0 = fmaxf(rm0, fmaxf(s[nt][0], s[nt][1]));
            rm1 = fmaxf(rm1, fmaxf(s[nt][2], s[nt][3]));
        }
        rm0 = fmaxf(rm0, __shfl_xor_sync(0xffffffffu, rm0, 1));
        rm0 = fmaxf(rm0, __shfl_xor_sync(0xffffffffu, rm0, 2));
        rm1 = fmaxf(rm1, __shfl_xor_sync(0xffffffffu, rm1, 1));
        rm1 = fmaxf(rm1, __shfl_xor_sync(0xffffffffu, rm1, 2));
        float mn0 = fmaxf(m0, rm0), mn1 = fmaxf(m1, rm1);
        float c0 = __expf(m0 - mn0), c1 = __expf(m1 - mn1);
        m0 = mn0; m1 = mn1;

        float ps0 = 0.f, ps1 = 0.f;
        unsigned* pr0 = Ps + r0 * 132;
        unsigned* pr1 = Ps + r1 * 132;
#pragma unroll
        for (int nt = 0; nt < 16; nt++) {
            float p00 = __expf(s[nt][0] - mn0), p01 = __expf(s[nt][1] - mn0);
            float p10 = __expf(s[nt][2] - mn1), p11 = __expf(s[nt][3] - mn1);
            ps0 += p00 + p01;
            ps1 += p10 + p11;
            int cc = nt * 8 + 2 * tg;
            pr0[cc] = f2tf(p00); pr0[cc + 1] = f2tf(p01);
            pr1[cc] = f2tf(p10); pr1[cc + 1] = f2tf(p11);
        }
        ps0 += __shfl_xor_sync(0xffffffffu, ps0, 1);
        ps0 += __shfl_xor_sync(0xffffffffu, ps0, 2);
        ps1 += __shfl_xor_sync(0xffffffffu, ps1, 1);
        ps1 += __shfl_xor_sync(0xffffffffu, ps1, 2);
        l0 = l0 * c0 + ps0;
        l1 = l1 * c1 + ps1;
#pragma unroll
        for (int nt = 0; nt < 4; nt++) {
            o[nt][0] *= c0; o[nt][1] *= c0;
            o[nt][2] *= c1; o[nt][3] *= c1;
        }
        __syncwarp();   // Ps rows are warp-private

        // O += P @ V
#pragma unroll
        for (int ks = 0; ks < 16; ks++) {
            unsigned aP[4] = { pr0[ks * 8 + tg], pr1[ks * 8 + tg],
                               pr0[ks * 8 + tg + 4], pr1[ks * 8 + tg + 4] };
#pragma unroll
            for (int nt = 0; nt < 4; nt++) {
                const unsigned* vp = Vs + nt * 8 + gid;
                unsigned bv[2] = { vp[(ks * 8 + tg) * 40], vp[(ks * 8 + tg + 4) * 40] };
                mma_tf32(o[nt], aP, bv);
            }
        }
    }

    float inv0 = 1.f / l0, inv1 = 1.f / l1;
    float* Or0 = O + qbase + (size_t)r0 * 256;
    float* Or1 = O + qbase + (size_t)r1 * 256;
#pragma unroll
    for (int nt = 0; nt < 4; nt++) {
        int cc = nt * 8 + 2 * tg;
        Or0[cc]     = tfv(o[nt][0] * inv0);
        Or0[cc + 1] = tfv(o[nt][1] * inv0);
        Or1[cc]     = tfv(o[nt][2] * inv1);
        Or1[cc + 1] = tfv(o[nt][3] * inv1);
    }
}

// ---------------------------------------------------------------------------
// Weight/input pre-conversion to tf32-rounded fp32 values
// ---------------------------------------------------------------------------
__global__ __launch_bounds__(256) void cvtw_k(
    const float* __restrict__ inputs, const float* __restrict__ emb,
    const float* __restrict__ qkvo, const float* __restrict__ f1,
    const float* __restrict__ f2, float* __restrict__ inT,
    float* __restrict__ wtf)
{
    int idx = blockIdx.x * 256 + threadIdx.x;
    if (idx < 4915200) inT[idx] = tfv(inputs[idx]);
    if (idx < 2042880) {
        float v;
        if (idx < OFF_QKVO)      v = emb[idx - OFF_EMB];
        else if (idx < OFF_FF1)  v = qkvo[idx - OFF_QKVO];
        else if (idx < OFF_FF2)  v = f1[idx - OFF_FF1];
        else                     v = f2[idx - OFF_FF2];
        wtf[idx] = tfv(v);
    }
}

// ---------------------------------------------------------------------------
// LSTM prep: build transposed/merged weights, g0, biasTot, w1t; zero barrier.
// ---------------------------------------------------------------------------
__global__ __launch_bounds__(256) void lstm_prep_k(
    const float* __restrict__ wih, const float* __restrict__ whh,
    const float* __restrict__ bih, const float* __restrict__ bhh,
    const float* __restrict__ dec_h0, const float* __restrict__ out_w1,
    float* __restrict__ WihEncT, float* __restrict__ WmR,
    float* __restrict__ w1t, float* __restrict__ g0,
    float* __restrict__ biasTot, unsigned* __restrict__ sync)
{
    int idx = blockIdx.x * 256 + threadIdx.x;
    if (idx == 0) *sync = 0u;
    if (idx < 262144) {
        int k = idx >> 10, n = idx & 1023;
        WihEncT[idx] = tfv(wih[(size_t)n * 512 + 256 + k]);

        int gb = idx >> 12;
        int r = idx & 4095;
        int gi = r >> 10;
        int rem = r & 1023;
        int el = rem >> 8;
        int kk = rem & 255;
        int col = gi * 256 + gb * 4 + el;
        WmR[idx] = wih[(size_t)col * 512 + kk] + whh[(size_t)col * 256 + kk];
    }
    if (idx < 32768) {
        int h = idx >> 8, k = idx & 255;
        w1t[idx] = out_w1[(size_t)k * 128 + h];
    }
    if (idx < 1024) {
        float a = 0.f;
        for (int k = 0; k < 256; k++) a = fmaf(dec_h0[k], whh[(size_t)idx * 256 + k], a);
        g0[idx] = a;
        biasTot[idx] = bih[idx] + bhh[idx];
    }
}

// ---------------------------------------------------------------------------
// Persistent LSTM: 96 blocks (64 gate + 32 MLP), all co-resident (1/SM),
// custom grid barrier on g_sync.
// ---------------------------------------------------------------------------
__device__ __forceinline__ float sigf(float x) { return 1.f / (1.f + __expf(-x)); }

__device__ __forceinline__ void grid_bar(unsigned* sync, unsigned target) {
    __threadfence();
    __syncthreads();
    if (threadIdx.x == 0) {
        atomicAdd(sync, 1u);
        while (*(volatile unsigned*)sync < target) { __nanosleep(20); }
        __threadfence();
    }
    __syncthreads();
}

__global__ __launch_bounds__(256, 1) void lstm_persist_k(
    const float* __restrict__ pre, const float* __restrict__ WmR,
    const float* __restrict__ w1t, const float* __restrict__ g0,
    const float* __restrict__ dec_c0,
    const float* __restrict__ b1, const float* __restrict__ w2,
    const float* __restrict__ b2, const float* __restrict__ mask,
    float* __restrict__ hbuf, unsigned* __restrict__ sync,
    float* __restrict__ out)
{
    extern __shared__ float sm[];
    const int tid = threadIdx.x;
    const unsigned NBLK = 96;

    if (blockIdx.x < 64) {
        const int gb = blockIdx.x;
        const int half = tid & 1;
        const int p = tid >> 1;
        const int b = p & 31;
        const int el = p >> 5;
        const int e = gb * 4 + el;

        float4* ws4 = (float4*)sm;
        float4* hs4 = (float4*)(sm + 4096);

        const float4* wsrc = (const float4*)(WmR + (size_t)gb * 4096);
        for (int i = tid; i < 1024; i += 256) ws4[i] = wsrc[i];

        float c = dec_c0[e];

        for (int t = 0; t < 512; ++t) {
            float gv0 = 0.f, gv1 = 0.f, gv2 = 0.f, gv3 = 0.f;
            if (t == 0) {
                if (half == 0) {
                    const float* pr = pre + (size_t)b * 512 * 1024;
                    gv0 = pr[e]       + g0[e];
                    gv1 = pr[256 + e] + g0[256 + e];
                    gv2 = pr[512 + e] + g0[512 + e];
                    gv3 = pr[768 + e] + g0[768 + e];
                }
            } else {
                const float4* hsrc = (const float4*)(hbuf + (t & 1) * 8192);
                for (int j = tid; j < 2048; j += 256) {
                    float4 v = __ldcg(hsrc + j);
                    int bb = j >> 6, k4 = j & 63;
                    hs4[bb * 66 + (k4 >> 5) * 33 + (k4 & 31)] = v;
                }
                __syncthreads();

                float a0 = 0.f, a1 = 0.f, a2 = 0.f, a3 = 0.f;
                const float4* hp = hs4 + b * 66 + half * 33;
                const float4* wp = ws4 + el * 64 + half * 32;
#pragma unroll
                for (int kk = 0; kk < 32; kk++) {
                    float4 hv = hp[kk];
                    float4 w0 = wp[kk];
                    float4 w1v = wp[256 + kk];
                    float4 w2v = wp[512 + kk];
                    float4 w3v = wp[768 + kk];
                    a0 = fmaf(hv.x, w0.x, fmaf(hv.y, w0.y, fmaf(hv.z, w0.z, fmaf(hv.w, w0.w, a0))));
                    a1 = fmaf(hv.x, w1v.x, fmaf(hv.y, w1v.y, fmaf(hv.z, w1v.z, fmaf(hv.w, w1v.w, a1))));
                    a2 = fmaf(hv.x, w2v.x, fmaf(hv.y, w2v.y, fmaf(hv.z, w2v.z, fmaf(hv.w, w2v.w, a2))));
                    a3 = fmaf(hv.x, w3v.x, fmaf(hv.y, w3v.y, fmaf(hv.z, w3v.z, fmaf(hv.w, w3v.w, a3))));
                }
                a0 += __shfl_xor_sync(0xffffffffu, a0, 1);
                a1 += __shfl_xor_sync(0xffffffffu, a1, 1);
                a2 += __shfl_xor_sync(0xffffffffu, a2, 1);
                a3 += __shfl_xor_sync(0xffffffffu, a3, 1);
                if (half == 0) {
                    const float* pr = pre + ((size_t)b * 512 + t) * 1024;
                    gv0 = a0 + pr[e];
                    gv1 = a1 + pr[256 + e];
                    gv2 = a2 + pr[512 + e];
                    gv3 = a3 + pr[768 + e];
                }
            }
            if (half == 0) {
                float cn = sigf(gv1) * c + sigf(gv0) * tanhf(gv2);
                float hn = sigf(gv3) * tanhf(cn);
                c = cn;
                __stcg(hbuf + ((t + 1) & 1) * 8192 + b * 256 + e, hn);
            }
            grid_bar(sync, (unsigned)(t + 1) * NBLK);
        }
    } else {
        const int b = blockIdx.x - 64;
        float* w1s  = sm;
        float* hrow = sm + 33280;
        float* red  = sm + 33536;

        for (int i = tid; i < 8192; i += 256) {
            int h = i >> 6, k4 = i & 63;
            ((float4*)w1s)[h * 65 + k4] = ((const float4*)w1t)[i];
        }
        float w2v = (tid < 128) ? w2[tid] : 0.f;
        float b1v = (tid < 128) ? b1[tid] : 0.f;
        float b2v = b2[0];

        for (int t = 0; t <= 512; ++t) {
            if (t >= 1) {
                hrow[tid] = __ldcg(hbuf + (t & 1) * 8192 + b * 256 + tid);
                __syncthreads();
                float contrib = 0.f;
                if (tid < 128) {
                    float a = b1v;
                    const float4* h4 = (const float4*)hrow;
                    const float4* w4 = (const float4*)(w1s + tid * 260);
#pragma unroll 16
                    for (int kk = 0; kk < 64; kk++) {
                        float4 hv = h4[kk];
                        float4 wv = w4[kk];
                        a = fmaf(hv.x, wv.x, fmaf(hv.y, wv.y, fmaf(hv.z, wv.z, fmaf(hv.w, wv.w, a))));
                    }
                    contrib = fmaxf(a, 0.f) * w2v;
                }
#pragma unroll
                for (int o = 16; o > 0; o >>= 1)
                    contrib += __shfl_down_sync(0xffffffffu, contrib, o);
                if (tid < 128 && (tid & 31) == 0) red[tid >> 5] = contrib;
                __syncthreads();
                if (tid == 0) {
                    float pp = red[0] + red[1] + red[2] + red[3] + b2v;
                    out[b * 512 + (t - 1)] = pp * mask[b * 512 + (t - 1)];
                }
                __syncthreads();
            }
            if (t < 512) grid_bar(sync, (unsigned)(t + 1) * NBLK);
        }
    }
}

// ---------------------------------------------------------------------------
// Launcher
// ---------------------------------------------------------------------------
extern "C" void kernel_launch(void* const* d_in, const int* in_sizes, int n_in,
                              void* d_out, int out_size)
{
    const float* inputs   = (const float*)d_in[0];
    const float* mask     = (const float*)d_in[1];
    /* d_in[2] = lengths (unused) */
    const float* embed_w  = (const float*)d_in[3];
    const float* embed_b  = (const float*)d_in[4];
    const float* qkvo_w   = (const float*)d_in[5];
    const float* qkvo_b   = (const float*)d_in[6];
    const float* ln_g     = (const float*)d_in[7];
    const float* ln_b     = (const float*)d_in[8];
    const float* ff_w1    = (const float*)d_in[9];
    const float* ff_b1    = (const float*)d_in[10];
    const float* ff_w2    = (const float*)d_in[11];
    const float* ff_b2    = (const float*)d_in[12];
    const float* enc_ln_g = (const float*)d_in[13];
    const float* enc_ln_b = (const float*)d_in[14];
    const float* wih      = (const float*)d_in[15];
    const float* whh      = (const float*)d_in[16];
    const float* bih      = (const float*)d_in[17];
    const float* bhh      = (const float*)d_in[18];
    const float* dec_h0   = (const float*)d_in[19];
    const float* dec_c0   = (const float*)d_in[20];
    const float* out_w1   = (const float*)d_in[21];
    const float* out_b1   = (const float*)d_in[22];
    const float* out_w2   = (const float*)d_in[23];
    const float* out_b2   = (const float*)d_in[24];
    float* out = (float*)d_out;
    (void)in_sizes; (void)n_in; (void)out_size;

    float *px, *py, *pqkv, *po, *ph1, *ppre, *pinT, *pwtf, *pWET, *pWmR, *pw1t,
          *pg0, *pbt, *phb;
    unsigned* psync;
    cudaGetSymbolAddress((void**)&px,    g_x);
    cudaGetSymbolAddress((void**)&py,    g_y);
    cudaGetSymbolAddress((void**)&pqkv,  g_qkv);
    cudaGetSymbolAddress((void**)&po,    g_o);
    cudaGetSymbolAddress((void**)&ph1,   g_h1);
    cudaGetSymbolAddress((void**)&ppre,  g_pre);
    cudaGetSymbolAddress((void**)&pinT,  g_inT);
    cudaGetSymbolAddress((void**)&pwtf,  g_wtf);
    cudaGetSymbolAddress((void**)&pWET,  g_WihEncT);
    cudaGetSymbolAddress((void**)&pWmR,  g_WmR);
    cudaGetSymbolAddress((void**)&pw1t,  g_w1t);
    cudaGetSymbolAddress((void**)&pg0,   g_g0);
    cudaGetSymbolAddress((void**)&pbt,   g_biasTot);
    cudaGetSymbolAddress((void**)&phb,   g_hbuf);
    cudaGetSymbolAddress((void**)&psync, g_sync);

    cudaFuncSetAttribute(attn_tc, cudaFuncAttributeMaxDynamicSharedMemorySize, 110592);
    cudaFuncSetAttribute(lstm_persist_k, cudaFuncAttributeMaxDynamicSharedMemorySize, 137216);

    const int M = 16384;
    const long QKV_C = 16384L * 256;

    // prep: tf32 conversions + LSTM weights + barrier reset
    cvtw_k<<<19200, 256>>>(inputs, embed_w, qkvo_w, ff_w1, ff_w2, pinT, pwtf);
    lstm_prep_k<<<1024, 256>>>(wih, whh, bih, bhh, dec_h0, out_w1,
                               pWET, pWmR, pw1t, pg0, pbt, psync);

    // Embed (K=300)
    gemm_tc<<<dim3(2, 128), 256>>>(pinT, pwtf + OFF_EMB, embed_b, nullptr, px,
                                   M, 256, 300, 0, 0, 2, 0, 0, 0);

    // Transformer layers
    for (int l = 0; l < 6; l++) {
        const float* Wq = pwtf + OFF_QKVO + (size_t)(l * 4) * 65536;
        const float* Wo = pwtf + OFF_QKVO + (size_t)(l * 4 + 3) * 65536;
        const float* bq = qkvo_b + (l * 4) * 256;
        const float* bo = qkvo_b + (l * 4 + 3) * 256;

        layernorm_k<<<2048, 256>>>(px, ln_g + l * 512, ln_b + l * 512, py);
        // fused Q,K,V: 3 matrices x 2 col-blocks, tf32-rounded outputs
        gemm_tc<<<dim3(6, 128), 256>>>(py, Wq, bq, nullptr, pqkv,
                                       M, 256, 256, 0, 1, 2, 65536, QKV_C, 256);
        attn_tc<<<dim3(4, 256), 256, 110592>>>(pqkv, pqkv + QKV_C,
                                               pqkv + 2 * QKV_C, mask, po);
        gemm_tc<<<dim3(2, 128), 256>>>(po, Wo, bo, px, px,
                                       M, 256, 256, 0, 0, 2, 0, 0, 0);

        layernorm_k<<<2048, 256>>>(px, ln_g + l * 512 + 256, ln_b + l * 512 + 256, py);
        gemm_tc<<<dim3(1, 128), 256>>>(py, pwtf + OFF_FF1 + (size_t)l * 32768,
                                       ff_b1 + l * 128, nullptr, ph1,
                                       M, 128, 256, 1, 1, 1, 0, 0, 0);
        gemm_tc<<<dim3(2, 128), 256>>>(ph1, pwtf + OFF_FF2 + (size_t)l * 32768,
                                       ff_b2 + l * 256, px, px,
                                       M, 256, 128, 0, 0, 2, 0, 0, 0);
    }

    // Encoder LN -> enc (in py, tf32-rounded)
    layernorm_k<<<2048, 256>>>(px, enc_ln_g, enc_ln_b, py);

    // pre = enc @ wih[:,256:].T + (bih+bhh)
    gemm_tc<<<dim3(8, 128), 256>>>(py, pWET, pbt, nullptr, ppre,
                                   M, 1024, 256, 0, 0, 8, 0, 0, 0);

    // Persistent LSTM scan + output head (single launch, 96 blocks)
    lstm_persist_k<<<96, 256, 137216>>>(ppre, pWmR, pw1t, pg0, dec_c0,
                                        out_b1, out_w2, out_b2, mask,
                                        phb, psync, out);
}

// round 7
// speedup vs baseline: 2.1608x; 1.0047x over previous
#include <cuda_runtime.h>
#include <cuda_bf16.h>
#include <math.h>

// ---------------------------------------------------------------------------
// Scratch (device globals — allocation-free per harness rules)
// ---------------------------------------------------------------------------
__device__ float g_x   [16384 * 256];
__device__ float g_y   [16384 * 256];
__device__ float g_qkv [3 * 16384 * 256];
__device__ float g_o   [16384 * 256];
__device__ float g_h1  [16384 * 128];
__device__ float g_pre [16384 * 1024];
__device__ float g_inT [16384 * 300];     // tf32-rounded inputs
__device__ float g_wtf [2042880];         // tf32-rounded weights (emb|qkvo|ff1|ff2)
__device__ float g_WihEncT[256 * 1024];   // (wih[:,256:512]).T, tf32-rounded
__device__ float g_WmR [64 * 4096];       // merged (wih[:,:256]+whh).T per gate-block
__device__ float g_w1t [128 * 256];       // out_w1 transposed [h][k]
__device__ float g_g0  [1024];            // dec_h0 @ whh.T
__device__ float g_biasTot[1024];         // bih + bhh
__device__ float g_hbuf[2 * 32 * 256];
__device__ unsigned g_sync;               // grid barrier counter (zeroed in prep)

#define OFF_EMB  0
#define OFF_QKVO 76800
#define OFF_FF1  1649664
#define OFF_FF2  1846272

// ---------------------------------------------------------------------------
// tf32 / mma helpers
// ---------------------------------------------------------------------------
__device__ __forceinline__ unsigned f2tf(float f) {
    unsigned u;
    asm("cvt.rna.tf32.f32 %0, %1;" : "=r"(u) : "f"(f));
    return u;
}
__device__ __forceinline__ float tfv(float f) { return __uint_as_float(f2tf(f)); }

__device__ __forceinline__ void mma_tf32(float (&d)[4], const unsigned (&a)[4],
                                         const unsigned (&b)[2]) {
    asm volatile(
        "mma.sync.aligned.m16n8k8.row.col.f32.tf32.tf32.f32 "
        "{%0,%1,%2,%3}, {%4,%5,%6,%7}, {%8,%9}, {%0,%1,%2,%3};"
        : "+f"(d[0]), "+f"(d[1]), "+f"(d[2]), "+f"(d[3])
        : "r"(a[0]), "r"(a[1]), "r"(a[2]), "r"(a[3]), "r"(b[0]), "r"(b[1]));
}

__device__ __forceinline__ void cp16(unsigned dst, const void* src, int bytes) {
    asm volatile("cp.async.cg.shared.global [%0], [%1], 16, %2;"
                 :: "r"(dst), "l"(src), "r"(bytes));
}
__device__ __forceinline__ void cp_commit() {
    asm volatile("cp.async.commit_group;" ::: "memory");
}

// ---------------------------------------------------------------------------
// tf32 tensor-core GEMM (inputs pre-rounded to tf32 values; no in-kernel cvt).
// C = [res +] A(MxK) @ B(KxN) + bias(N) [, relu][, outCvt -> tf32-rounded out]
// BM=BN=128, BK=16, 256 threads (8 warps 2x4), warp tile 64x32.
// 3-stage cp.async pipeline in dynamic smem (issue 2 tiles ahead, wait_group 1).
// ---------------------------------------------------------------------------
#define GEMM_SMEM (3 * 128 * 20 * 4 + 3 * 16 * 136 * 4)

__global__ __launch_bounds__(256, 2) void gemm_tc(
    const float* __restrict__ A, const float* __restrict__ B,
    const float* __restrict__ bias, const float* __restrict__ res,
    float* __restrict__ C, int M, int N, int K, int relu, int outCvt,
    int nxPerMat, long bMatStride, long cMatStride, int biasMatStride)
{
    extern __shared__ unsigned dynsm[];
    unsigned (*As)[128][20] = (unsigned (*)[128][20])dynsm;
    unsigned (*Bs)[16][136] = (unsigned (*)[16][136])(dynsm + 3 * 128 * 20);

    const int tid = threadIdx.x;
    const int bx = blockIdx.x, by = blockIdx.y;
    const int mat = bx / nxPerMat;
    const int bxn = bx - mat * nxPerMat;

    const float* Bp    = B + (size_t)mat * bMatStride;
    const float* biasP = bias + (size_t)mat * biasMatStride;
    float*       Cp    = C + (size_t)mat * cMatStride;

    const float* Ablk = A + (size_t)(by * 128) * K;
    const float* Bblk = Bp + bxn * 128;

    const int lane = tid & 31, wid = tid >> 5;
    const int wm = wid >> 2, wn = wid & 3;
    const int gid = lane >> 2, tg = lane & 3;

    const int ar0 = tid >> 2, ac0 = (tid & 3) << 2;
    const int ar1 = ar0 + 64;
    const int bk0 = tid >> 5, bc0 = (tid & 31) << 2;
    const int bk1 = bk0 + 8;

    const unsigned sA = (unsigned)__cvta_generic_to_shared(&dynsm[0]);
    const unsigned sB = (unsigned)__cvta_generic_to_shared(&dynsm[3 * 128 * 20]);

    float acc[4][4][4];
#pragma unroll
    for (int mt = 0; mt < 4; mt++)
#pragma unroll
        for (int nt = 0; nt < 4; nt++)
#pragma unroll
            for (int i = 0; i < 4; i++) acc[mt][nt][i] = 0.f;

    auto issue = [&](int buf, int k0) {
        int c0 = k0 + ac0;
        int rem0 = K - c0;
        int by0 = rem0 >= 4 ? 16 : (rem0 > 0 ? rem0 * 4 : 0);
        cp16(sA + ((buf * 128 + ar0) * 20 + ac0) * 4,
             Ablk + (size_t)ar0 * K + (by0 ? c0 : 0), by0);
        cp16(sA + ((buf * 128 + ar1) * 20 + ac0) * 4,
             Ablk + (size_t)ar1 * K + (by0 ? c0 : 0), by0);
        int kr0 = k0 + bk0;
        int bb0 = (kr0 < K) ? 16 : 0;
        cp16(sB + ((buf * 16 + bk0) * 136 + bc0) * 4,
             Bblk + (size_t)(bb0 ? kr0 : 0) * N + bc0, bb0);
        int kr1 = k0 + bk1;
        int bb1 = (kr1 < K) ? 16 : 0;
        cp16(sB + ((buf * 16 + bk1) * 136 + bc0) * 4,
             Bblk + (size_t)(bb1 ? kr1 : 0) * N + bc0, bb1);
        cp_commit();
    };

    // prologue: stage up to 2 tiles
    issue(0, 0);
    if (16 < K) issue(1, 16);

    int cur = 0;
    for (int k0 = 0; k0 < K; k0 += 16) {
        // wait for tile `cur` (keep 1 group in flight when more tiles remain)
        if (k0 + 16 < K) {
            asm volatile("cp.async.wait_group 1;" ::: "memory");
        } else {
            asm volatile("cp.async.wait_group 0;" ::: "memory");
        }
        __syncthreads();
        if (k0 + 32 < K) {
            int nb = cur + 2; if (nb >= 3) nb -= 3;
            issue(nb, k0 + 32);
        }

#pragma unroll
        for (int ks = 0; ks < 16; ks += 8) {
            unsigned a[4][4], b[4][2];
#pragma unroll
            for (int mt = 0; mt < 4; mt++) {
                int r = wm * 64 + mt * 16 + gid;
                a[mt][0] = As[cur][r][ks + tg];
                a[mt][1] = As[cur][r + 8][ks + tg];
                a[mt][2] = As[cur][r][ks + tg + 4];
                a[mt][3] = As[cur][r + 8][ks + tg + 4];
            }
#pragma unroll
            for (int nt = 0; nt < 4; nt++) {
                int cb = wn * 32 + nt * 8 + gid;
                b[nt][0] = Bs[cur][ks + tg][cb];
                b[nt][1] = Bs[cur][ks + tg + 4][cb];
            }
#pragma unroll
            for (int mt = 0; mt < 4; mt++)
#pragma unroll
                for (int nt = 0; nt < 4; nt++)
                    mma_tf32(acc[mt][nt], a[mt], b[nt]);
        }
        __syncthreads();   // compute done before this buffer can be re-filled
        cur = cur + 1; if (cur >= 3) cur -= 3;
    }

#pragma unroll
    for (int mt = 0; mt < 4; mt++) {
        int r0 = by * 128 + wm * 64 + mt * 16 + gid;
#pragma unroll
        for (int nt = 0; nt < 4; nt++) {
            int c0 = bxn * 128 + wn * 32 + nt * 8 + tg * 2;
            float bza = biasP[c0], bzb = biasP[c0 + 1];
            size_t off0 = (size_t)r0 * N + c0;
            size_t off1 = (size_t)(r0 + 8) * N + c0;
            float v0 = acc[mt][nt][0] + bza, v1 = acc[mt][nt][1] + bzb;
            float v2 = acc[mt][nt][2] + bza, v3 = acc[mt][nt][3] + bzb;
            if (res) {
                v0 += res[off0]; v1 += res[off0 + 1];
                v2 += res[off1]; v3 += res[off1 + 1];
            }
            if (relu) {
                v0 = fmaxf(v0, 0.f); v1 = fmaxf(v1, 0.f);
                v2 = fmaxf(v2, 0.f); v3 = fmaxf(v3, 0.f);
            }
            if (outCvt) {
                v0 = tfv(v0); v1 = tfv(v1); v2 = tfv(v2); v3 = tfv(v3);
            }
            *(float2*)(Cp + off0) = make_float2(v0, v1);
            *(float2*)(Cp + off1) = make_float2(v2, v3);
        }
    }
}

// ---------------------------------------------------------------------------
// LayerNorm: warp per row (E=256), float4, 8 rows/block; output tf32-rounded.
// ---------------------------------------------------------------------------
__global__ __launch_bounds__(256) void layernorm_k(
    const float* __restrict__ x, const float* __restrict__ g,
    const float* __restrict__ b, float* __restrict__ y)
{
    int tid = threadIdx.x;
    int lane = tid & 31;
    int row = blockIdx.x * 8 + (tid >> 5);

    const float4* xr = (const float4*)(x + (size_t)row * 256);
    float4 v0 = xr[lane], v1 = xr[lane + 32];

    float s = v0.x + v0.y + v0.z + v0.w + v1.x + v1.y + v1.z + v1.w;
#pragma unroll
    for (int o = 16; o > 0; o >>= 1) s += __shfl_xor_sync(0xffffffffu, s, o);
    float mean = s * (1.f / 256.f);

    float4 d0 = make_float4(v0.x - mean, v0.y - mean, v0.z - mean, v0.w - mean);
    float4 d1 = make_float4(v1.x - mean, v1.y - mean, v1.z - mean, v1.w - mean);
    float sq = d0.x * d0.x + d0.y * d0.y + d0.z * d0.z + d0.w * d0.w
             + d1.x * d1.x + d1.y * d1.y + d1.z * d1.z + d1.w * d1.w;
#pragma unroll
    for (int o = 16; o > 0; o >>= 1) sq += __shfl_xor_sync(0xffffffffu, sq, o);
    float var = sq * (1.f / 255.f);
    float r = 1.f / (sqrtf(var) + 1e-6f);

    const float4* g4 = (const float4*)g;
    const float4* b4 = (const float4*)b;
    float4 gg0 = g4[lane], gg1 = g4[lane + 32];
    float4 bb0 = b4[lane], bb1 = b4[lane + 32];

    float4 o0, o1;
    o0.x = tfv(gg0.x * d0.x * r + bb0.x); o0.y = tfv(gg0.y * d0.y * r + bb0.y);
    o0.z = tfv(gg0.z * d0.z * r + bb0.z); o0.w = tfv(gg0.w * d0.w * r + bb0.w);
    o1.x = tfv(gg1.x * d1.x * r + bb1.x); o1.y = tfv(gg1.y * d1.y * r + bb1.y);
    o1.z = tfv(gg1.z * d1.z * r + bb1.z); o1.w = tfv(gg1.w * d1.w * r + bb1.w);

    float4* yr = (float4*)(y + (size_t)row * 256);
    yr[lane] = o0;
    yr[lane + 32] = o1;
}

// ---------------------------------------------------------------------------
// Tensor-core flash attention (R5-proven).
// ---------------------------------------------------------------------------
__global__ __launch_bounds__(256, 2) void attn_tc(
    const float* __restrict__ Q, const float* __restrict__ K,
    const float* __restrict__ V, const float* __restrict__ mask,
    float* __restrict__ O)
{
    extern __shared__ unsigned smu[];
    unsigned* Ks = smu;                        // [128][44]
    unsigned* Vs = smu + 128 * 44;             // [128][40]
    unsigned* Ps = smu + 128 * 44 + 128 * 40;  // [128][132]

    const int qt = blockIdx.x;
    const int bh = blockIdx.y;
    const int b = bh >> 3, h = bh & 7;
    const int tid = threadIdx.x;
    const int w = tid >> 5, lane = tid & 31;
    const int gid = lane >> 2, tg = lane & 3;

    const int r0 = w * 16 + gid;
    const int r1 = r0 + 8;
    const size_t qbase = ((size_t)(b * 512 + qt * 128)) * 256 + h * 32;
    const float scale = 0.17677669529663689f;

    unsigned aQ[4][4];
#pragma unroll
    for (int ks = 0; ks < 4; ks++) {
        aQ[ks][0] = f2tf(Q[qbase + (size_t)r0 * 256 + ks * 8 + tg] * scale);
        aQ[ks][1] = f2tf(Q[qbase + (size_t)r1 * 256 + ks * 8 + tg] * scale);
        aQ[ks][2] = f2tf(Q[qbase + (size_t)r0 * 256 + ks * 8 + tg + 4] * scale);
        aQ[ks][3] = f2tf(Q[qbase + (size_t)r1 * 256 + ks * 8 + tg + 4] * scale);
    }
    const bool mz0 = (mask[b * 512 + qt * 128 + r0] == 0.f);
    const bool mz1 = (mask[b * 512 + qt * 128 + r1] == 0.f);

    float m0 = -1e30f, m1 = -1e30f, l0 = 0.f, l1 = 0.f;
    float o[4][4];
#pragma unroll
    for (int nt = 0; nt < 4; nt++)
#pragma unroll
        for (int i = 0; i < 4; i++) o[nt][i] = 0.f;

    for (int kc = 0; kc < 4; kc++) {
        __syncthreads();
        const size_t kvbase = ((size_t)(b * 512 + kc * 128)) * 256 + h * 32;
        for (int idx = tid; idx < 1024; idx += 256) {
            int key = idx >> 3, d4 = idx & 7;
            const uint4* ks4 = (const uint4*)(K + kvbase + (size_t)key * 256) + d4;
            const uint4* vs4 = (const uint4*)(V + kvbase + (size_t)key * 256) + d4;
            *(uint4*)(Ks + key * 44 + d4 * 4) = *ks4;
            *(uint4*)(Vs + key * 40 + d4 * 4) = *vs4;
        }
        __syncthreads();

        float s[16][4];
#pragma unroll
        for (int nt = 0; nt < 16; nt++) {
            s[nt][0] = s[nt][1] = s[nt][2] = s[nt][3] = 0.f;
            const unsigned* kp = Ks + (nt * 8 + gid) * 44;
#pragma unroll
            for (int ks = 0; ks < 4; ks++) {
                unsigned bk[2] = { kp[ks * 8 + tg], kp[ks * 8 + tg + 4] };
                mma_tf32(s[nt], aQ[ks], bk);
            }
        }
        if (mz0) {
#pragma unroll
            for (int nt = 0; nt < 16; nt++) { s[nt][0] = -1e9f; s[nt][1] = -1e9f; }
        }
        if (mz1) {
#pragma unroll
            for (int nt = 0; nt < 16; nt++) { s[nt][2] = -1e9f; s[nt][3] = -1e9f; }
        }

        float rm0 = -1e30f, rm1 = -1e30f;
#pragma unroll
        for (int nt = 0; nt < 16; nt++) {
            rm0 = fmaxf(rm0, fmaxf(s[nt][0], s[nt][1]));
            rm1 = fmaxf(rm1, fmaxf(s[nt][2], s[nt][3]));
        }
        rm0 = fmaxf(rm0, __shfl_xor_sync(0xffffffffu, rm0, 1));
        rm0 = fmaxf(rm0, __shfl_xor_sync(0xffffffffu, rm0, 2));
        rm1 = fmaxf(rm1, __shfl_xor_sync(0xffffffffu, rm1, 1));
        rm1 = fmaxf(rm1, __shfl_xor_sync(0xffffffffu, rm1, 2));
        float mn0 = fmaxf(m0, rm0), mn1 = fmaxf(m1, rm1);
        float c0 = __expf(m0 - mn0), c1 = __expf(m1 - mn1);
        m0 = mn0; m1 = mn1;

        float ps0 = 0.f, ps1 = 0.f;
        unsigned* pr0 = Ps + r0 * 132;
        unsigned* pr1 = Ps + r1 * 132;
#pragma unroll
        for (int nt = 0; nt < 16; nt++) {
            float p00 = __expf(s[nt][0] - mn0), p01 = __expf(s[nt][1] - mn0);
            float p10 = __expf(s[nt][2] - mn1), p11 = __expf(s[nt][3] - mn1);
            ps0 += p00 + p01;
            ps1 += p10 + p11;
            int cc = nt * 8 + 2 * tg;
            pr0[cc] = f2tf(p00); pr0[cc + 1] = f2tf(p01);
            pr1[cc] = f2tf(p10); pr1[cc + 1] = f2tf(p11);
        }
        ps0 += __shfl_xor_sync(0xffffffffu, ps0, 1);
        ps0 += __shfl_xor_sync(0xffffffffu, ps0, 2);
        ps1 += __shfl_xor_sync(0xffffffffu, ps1, 1);
        ps1 += __shfl_xor_sync(0xffffffffu, ps1, 2);
        l0 = l0 * c0 + ps0;
        l1 = l1 * c1 + ps1;
#pragma unroll
        for (int nt = 0; nt < 4; nt++) {
            o[nt][0] *= c0; o[nt][1] *= c0;
            o[nt][2] *= c1; o[nt][3] *= c1;
        }
        __syncwarp();

#pragma unroll
        for (int ks = 0; ks < 16; ks++) {
            unsigned aP[4] = { pr0[ks * 8 + tg], pr1[ks * 8 + tg],
                               pr0[ks * 8 + tg + 4], pr1[ks * 8 + tg + 4] };
#pragma unroll
            for (int nt = 0; nt < 4; nt++) {
                const unsigned* vp = Vs + nt * 8 + gid;
                unsigned bv[2] = { vp[(ks * 8 + tg) * 40], vp[(ks * 8 + tg + 4) * 40] };
                mma_tf32(o[nt], aP, bv);
            }
        }
    }

    float inv0 = 1.f / l0, inv1 = 1.f / l1;
    float* Or0 = O + qbase + (size_t)r0 * 256;
    float* Or1 = O + qbase + (size_t)r1 * 256;
#pragma unroll
    for (int nt = 0; nt < 4; nt++) {
        int cc = nt * 8 + 2 * tg;
        Or0[cc]     = tfv(o[nt][0] * inv0);
        Or0[cc + 1] = tfv(o[nt][1] * inv0);
        Or1[cc]     = tfv(o[nt][2] * inv1);
        Or1[cc + 1] = tfv(o[nt][3] * inv1);
    }
}

// ---------------------------------------------------------------------------
// Weight/input pre-conversion to tf32-rounded fp32 values
// ---------------------------------------------------------------------------
__global__ __launch_bounds__(256) void cvtw_k(
    const float* __restrict__ inputs, const float* __restrict__ emb,
    const float* __restrict__ qkvo, const float* __restrict__ f1,
    const float* __restrict__ f2, float* __restrict__ inT,
    float* __restrict__ wtf)
{
    int idx = blockIdx.x * 256 + threadIdx.x;
    if (idx < 4915200) inT[idx] = tfv(inputs[idx]);
    if (idx < 2042880) {
        float v;
        if (idx < OFF_QKVO)      v = emb[idx - OFF_EMB];
        else if (idx < OFF_FF1)  v = qkvo[idx - OFF_QKVO];
        else if (idx < OFF_FF2)  v = f1[idx - OFF_FF1];
        else                     v = f2[idx - OFF_FF2];
        wtf[idx] = tfv(v);
    }
}

// ---------------------------------------------------------------------------
// LSTM prep: build transposed/merged weights, g0, biasTot, w1t; zero barrier.
// ---------------------------------------------------------------------------
__global__ __launch_bounds__(256) void lstm_prep_k(
    const float* __restrict__ wih, const float* __restrict__ whh,
    const float* __restrict__ bih, const float* __restrict__ bhh,
    const float* __restrict__ dec_h0, const float* __restrict__ out_w1,
    float* __restrict__ WihEncT, float* __restrict__ WmR,
    float* __restrict__ w1t, float* __restrict__ g0,
    float* __restrict__ biasTot, unsigned* __restrict__ sync)
{
    int idx = blockIdx.x * 256 + threadIdx.x;
    if (idx == 0) *sync = 0u;
    if (idx < 262144) {
        int k = idx >> 10, n = idx & 1023;
        WihEncT[idx] = tfv(wih[(size_t)n * 512 + 256 + k]);

        int gb = idx >> 12;
        int r = idx & 4095;
        int gi = r >> 10;
        int rem = r & 1023;
        int el = rem >> 8;
        int kk = rem & 255;
        int col = gi * 256 + gb * 4 + el;
        WmR[idx] = wih[(size_t)col * 512 + kk] + whh[(size_t)col * 256 + kk];
    }
    if (idx < 32768) {
        int h = idx >> 8, k = idx & 255;
        w1t[idx] = out_w1[(size_t)k * 128 + h];
    }
    if (idx < 1024) {
        float a = 0.f;
        for (int k = 0; k < 256; k++) a = fmaf(dec_h0[k], whh[(size_t)idx * 256 + k], a);
        g0[idx] = a;
        biasTot[idx] = bih[idx] + bhh[idx];
    }
}

// ---------------------------------------------------------------------------
// Persistent LSTM: 96 blocks (64 gate + 32 MLP), all co-resident (1/SM),
// custom grid barrier on g_sync. (R5-proven version, unchanged.)
// ---------------------------------------------------------------------------
__device__ __forceinline__ float sigf(float x) { return 1.f / (1.f + __expf(-x)); }

__device__ __forceinline__ void grid_bar(unsigned* sync, unsigned target) {
    __threadfence();
    __syncthreads();
    if (threadIdx.x == 0) {
        atomicAdd(sync, 1u);
        while (*(volatile unsigned*)sync < target) { __nanosleep(20); }
        __threadfence();
    }
    __syncthreads();
}

__global__ __launch_bounds__(256, 1) void lstm_persist_k(
    const float* __restrict__ pre, const float* __restrict__ WmR,
    const float* __restrict__ w1t, const float* __restrict__ g0,
    const float* __restrict__ dec_c0,
    const float* __restrict__ b1, const float* __restrict__ w2,
    const float* __restrict__ b2, const float* __restrict__ mask,
    float* __restrict__ hbuf, unsigned* __restrict__ sync,
    float* __restrict__ out)
{
    extern __shared__ float sm[];
    const int tid = threadIdx.x;
    const unsigned NBLK = 96;

    if (blockIdx.x < 64) {
        const int gb = blockIdx.x;
        const int half = tid & 1;
        const int p = tid >> 1;
        const int b = p & 31;
        const int el = p >> 5;
        const int e = gb * 4 + el;

        float4* ws4 = (float4*)sm;
        float4* hs4 = (float4*)(sm + 4096);

        const float4* wsrc = (const float4*)(WmR + (size_t)gb * 4096);
        for (int i = tid; i < 1024; i += 256) ws4[i] = wsrc[i];

        float c = dec_c0[e];

        for (int t = 0; t < 512; ++t) {
            float gv0 = 0.f, gv1 = 0.f, gv2 = 0.f, gv3 = 0.f;
            if (t == 0) {
                if (half == 0) {
                    const float* pr = pre + (size_t)b * 512 * 1024;
                    gv0 = pr[e]       + g0[e];
                    gv1 = pr[256 + e] + g0[256 + e];
                    gv2 = pr[512 + e] + g0[512 + e];
                    gv3 = pr[768 + e] + g0[768 + e];
                }
            } else {
                const float4* hsrc = (const float4*)(hbuf + (t & 1) * 8192);
                for (int j = tid; j < 2048; j += 256) {
                    float4 v = __ldcg(hsrc + j);
                    int bb = j >> 6, k4 = j & 63;
                    hs4[bb * 66 + (k4 >> 5) * 33 + (k4 & 31)] = v;
                }
                __syncthreads();

                float a0 = 0.f, a1 = 0.f, a2 = 0.f, a3 = 0.f;
                const float4* hp = hs4 + b * 66 + half * 33;
                const float4* wp = ws4 + el * 64 + half * 32;
#pragma unroll
                for (int kk = 0; kk < 32; kk++) {
                    float4 hv = hp[kk];
                    float4 w0 = wp[kk];
                    float4 w1v = wp[256 + kk];
                    float4 w2v = wp[512 + kk];
                    float4 w3v = wp[768 + kk];
                    a0 = fmaf(hv.x, w0.x, fmaf(hv.y, w0.y, fmaf(hv.z, w0.z, fmaf(hv.w, w0.w, a0))));
                    a1 = fmaf(hv.x, w1v.x, fmaf(hv.y, w1v.y, fmaf(hv.z, w1v.z, fmaf(hv.w, w1v.w, a1))));
                    a2 = fmaf(hv.x, w2v.x, fmaf(hv.y, w2v.y, fmaf(hv.z, w2v.z, fmaf(hv.w, w2v.w, a2))));
                    a3 = fmaf(hv.x, w3v.x, fmaf(hv.y, w3v.y, fmaf(hv.z, w3v.z, fmaf(hv.w, w3v.w, a3))));
                }
                a0 += __shfl_xor_sync(0xffffffffu, a0, 1);
                a1 += __shfl_xor_sync(0xffffffffu, a1, 1);
                a2 += __shfl_xor_sync(0xffffffffu, a2, 1);
                a3 += __shfl_xor_sync(0xffffffffu, a3, 1);
                if (half == 0) {
                    const float* pr = pre + ((size_t)b * 512 + t) * 1024;
                    gv0 = a0 + pr[e];
                    gv1 = a1 + pr[256 + e];
                    gv2 = a2 + pr[512 + e];
                    gv3 = a3 + pr[768 + e];
                }
            }
            if (half == 0) {
                float cn = sigf(gv1) * c + sigf(gv0) * tanhf(gv2);
                float hn = sigf(gv3) * tanhf(cn);
                c = cn;
                __stcg(hbuf + ((t + 1) & 1) * 8192 + b * 256 + e, hn);
            }
            grid_bar(sync, (unsigned)(t + 1) * NBLK);
        }
    } else {
        const int b = blockIdx.x - 64;
        float* w1s  = sm;
        float* hrow = sm + 33280;
        float* red  = sm + 33536;

        for (int i = tid; i < 8192; i += 256) {
            int h = i >> 6, k4 = i & 63;
            ((float4*)w1s)[h * 65 + k4] = ((const float4*)w1t)[i];
        }
        float w2v = (tid < 128) ? w2[tid] : 0.f;
        float b1v = (tid < 128) ? b1[tid] : 0.f;
        float b2v = b2[0];

        for (int t = 0; t <= 512; ++t) {
            if (t >= 1) {
                hrow[tid] = __ldcg(hbuf + (t & 1) * 8192 + b * 256 + tid);
                __syncthreads();
                float contrib = 0.f;
                if (tid < 128) {
                    float a = b1v;
                    const float4* h4 = (const float4*)hrow;
                    const float4* w4 = (const float4*)(w1s + tid * 260);
#pragma unroll 16
                    for (int kk = 0; kk < 64; kk++) {
                        float4 hv = h4[kk];
                        float4 wv = w4[kk];
                        a = fmaf(hv.x, wv.x, fmaf(hv.y, wv.y, fmaf(hv.z, wv.z, fmaf(hv.w, wv.w, a))));
                    }
                    contrib = fmaxf(a, 0.f) * w2v;
                }
#pragma unroll
                for (int o = 16; o > 0; o >>= 1)
                    contrib += __shfl_down_sync(0xffffffffu, contrib, o);
                if (tid < 128 && (tid & 31) == 0) red[tid >> 5] = contrib;
                __syncthreads();
                if (tid == 0) {
                    float pp = red[0] + red[1] + red[2] + red[3] + b2v;
                    out[b * 512 + (t - 1)] = pp * mask[b * 512 + (t - 1)];
                }
                __syncthreads();
            }
            if (t < 512) grid_bar(sync, (unsigned)(t + 1) * NBLK);
        }
    }
}

// ---------------------------------------------------------------------------
// Launcher
// ---------------------------------------------------------------------------
extern "C" void kernel_launch(void* const* d_in, const int* in_sizes, int n_in,
                              void* d_out, int out_size)
{
    const float* inputs   = (const float*)d_in[0];
    const float* mask     = (const float*)d_in[1];
    /* d_in[2] = lengths (unused) */
    const float* embed_w  = (const float*)d_in[3];
    const float* embed_b  = (const float*)d_in[4];
    const float* qkvo_w   = (const float*)d_in[5];
    const float* qkvo_b   = (const float*)d_in[6];
    const float* ln_g     = (const float*)d_in[7];
    const float* ln_b     = (const float*)d_in[8];
    const float* ff_w1    = (const float*)d_in[9];
    const float* ff_b1    = (const float*)d_in[10];
    const float* ff_w2    = (const float*)d_in[11];
    const float* ff_b2    = (const float*)d_in[12];
    const float* enc_ln_g = (const float*)d_in[13];
    const float* enc_ln_b = (const float*)d_in[14];
    const float* wih      = (const float*)d_in[15];
    const float* whh      = (const float*)d_in[16];
    const float* bih      = (const float*)d_in[17];
    const float* bhh      = (const float*)d_in[18];
    const float* dec_h0   = (const float*)d_in[19];
    const float* dec_c0   = (const float*)d_in[20];
    const float* out_w1   = (const float*)d_in[21];
    const float* out_b1   = (const float*)d_in[22];
    const float* out_w2   = (const float*)d_in[23];
    const float* out_b2   = (const float*)d_in[24];
    float* out = (float*)d_out;
    (void)in_sizes; (void)n_in; (void)out_size;

    float *px, *py, *pqkv, *po, *ph1, *ppre, *pinT, *pwtf, *pWET, *pWmR, *pw1t,
          *pg0, *pbt, *phb;
    unsigned* psync;
    cudaGetSymbolAddress((void**)&px,    g_x);
    cudaGetSymbolAddress((void**)&py,    g_y);
    cudaGetSymbolAddress((void**)&pqkv,  g_qkv);
    cudaGetSymbolAddress((void**)&po,    g_o);
    cudaGetSymbolAddress((void**)&ph1,   g_h1);
    cudaGetSymbolAddress((void**)&ppre,  g_pre);
    cudaGetSymbolAddress((void**)&pinT,  g_inT);
    cudaGetSymbolAddress((void**)&pwtf,  g_wtf);
    cudaGetSymbolAddress((void**)&pWET,  g_WihEncT);
    cudaGetSymbolAddress((void**)&pWmR,  g_WmR);
    cudaGetSymbolAddress((void**)&pw1t,  g_w1t);
    cudaGetSymbolAddress((void**)&pg0,   g_g0);
    cudaGetSymbolAddress((void**)&pbt,   g_biasTot);
    cudaGetSymbolAddress((void**)&phb,   g_hbuf);
    cudaGetSymbolAddress((void**)&psync, g_sync);

    cudaFuncSetAttribute(gemm_tc, cudaFuncAttributeMaxDynamicSharedMemorySize, GEMM_SMEM);
    cudaFuncSetAttribute(attn_tc, cudaFuncAttributeMaxDynamicSharedMemorySize, 110592);
    cudaFuncSetAttribute(lstm_persist_k, cudaFuncAttributeMaxDynamicSharedMemorySize, 137216);

    const int M = 16384;
    const long QKV_C = 16384L * 256;

    // prep: tf32 conversions + LSTM weights + barrier reset
    cvtw_k<<<19200, 256>>>(inputs, embed_w, qkvo_w, ff_w1, ff_w2, pinT, pwtf);
    lstm_prep_k<<<1024, 256>>>(wih, whh, bih, bhh, dec_h0, out_w1,
                               pWET, pWmR, pw1t, pg0, pbt, psync);

    // Embed (K=300)
    gemm_tc<<<dim3(2, 128), 256, GEMM_SMEM>>>(pinT, pwtf + OFF_EMB, embed_b,
                                              nullptr, px,
                                              M, 256, 300, 0, 0, 2, 0, 0, 0);

    // Transformer layers
    for (int l = 0; l < 6; l++) {
        const float* Wq = pwtf + OFF_QKVO + (size_t)(l * 4) * 65536;
        const float* Wo = pwtf + OFF_QKVO + (size_t)(l * 4 + 3) * 65536;
        const float* bq = qkvo_b + (l * 4) * 256;
        const float* bo = qkvo_b + (l * 4 + 3) * 256;

        layernorm_k<<<2048, 256>>>(px, ln_g + l * 512, ln_b + l * 512, py);
        gemm_tc<<<dim3(6, 128), 256, GEMM_SMEM>>>(py, Wq, bq, nullptr, pqkv,
                                                  M, 256, 256, 0, 1,
                                                  2, 65536, QKV_C, 256);
        attn_tc<<<dim3(4, 256), 256, 110592>>>(pqkv, pqkv + QKV_C,
                                               pqkv + 2 * QKV_C, mask, po);
        gemm_tc<<<dim3(2, 128), 256, GEMM_SMEM>>>(po, Wo, bo, px, px,
                                                  M, 256, 256, 0, 0, 2, 0, 0, 0);

        layernorm_k<<<2048, 256>>>(px, ln_g + l * 512 + 256, ln_b + l * 512 + 256, py);
        gemm_tc<<<dim3(1, 128), 256, GEMM_SMEM>>>(py, pwtf + OFF_FF1 + (size_t)l * 32768,
                                                  ff_b1 + l * 128, nullptr, ph1,
                                                  M, 128, 256, 1, 1, 1, 0, 0, 0);
        gemm_tc<<<dim3(2, 128), 256, GEMM_SMEM>>>(ph1, pwtf + OFF_FF2 + (size_t)l * 32768,
                                                  ff_b2 + l * 256, px, px,
                                                  M, 256, 128, 0, 0, 2, 0, 0, 0);
    }

    // Encoder LN -> enc (in py, tf32-rounded)
    layernorm_k<<<2048, 256>>>(px, enc_ln_g, enc_ln_b, py);

    // pre = enc @ wih[:,256:].T + (bih+bhh)
    gemm_tc<<<dim3(8, 128), 256, GEMM_SMEM>>>(py, pWET, pbt, nullptr, ppre,
                                              M, 1024, 256, 0, 0, 8, 0, 0, 0);

    // Persistent LSTM scan + output head (single launch, 96 blocks)
    lstm_persist_k<<<96, 256, 137216>>>(ppre, pWmR, pw1t, pg0, dec_c0,
                                        out_b1, out_w2, out_b2, mask,
                                        phb, psync, out);
}

// round 8
// speedup vs baseline: 2.1643x; 1.0016x over previous
#include <cuda_runtime.h>
#include <cuda_bf16.h>
#include <math.h>

// ---------------------------------------------------------------------------
// Scratch (device globals — allocation-free per harness rules)
// ---------------------------------------------------------------------------
__device__ float g_x   [16384 * 256];
__device__ float g_y   [16384 * 256];
__device__ float g_qkv [3 * 16384 * 256];
__device__ float g_o   [16384 * 256];
__device__ float g_h1  [16384 * 128];
__device__ float g_pre [16384 * 1024];
__device__ float g_inT [16384 * 300];     // tf32-rounded inputs
__device__ float g_wtf [2042880];         // tf32-rounded weights (emb|qkvo|ff1|ff2)
__device__ float g_WihEncT[256 * 1024];   // (wih[:,256:512]).T, tf32-rounded
__device__ float g_WmR [64 * 4096];       // merged (wih[:,:256]+whh).T per gate-block
__device__ float g_w1t [128 * 256];       // out_w1 transposed [h][k]
__device__ float g_g0  [1024];            // dec_h0 @ whh.T
__device__ float g_biasTot[1024];         // bih + bhh
__device__ float g_hbuf[2 * 32 * 256];
__device__ unsigned g_sync;               // grid barrier counter (zeroed in prep)

#define OFF_EMB  0
#define OFF_QKVO 76800
#define OFF_FF1  1649664
#define OFF_FF2  1846272

// ---------------------------------------------------------------------------
// tf32 / mma helpers
// ---------------------------------------------------------------------------
__device__ __forceinline__ unsigned f2tf(float f) {
    unsigned u;
    asm("cvt.rna.tf32.f32 %0, %1;" : "=r"(u) : "f"(f));
    return u;
}
__device__ __forceinline__ float tfv(float f) { return __uint_as_float(f2tf(f)); }

__device__ __forceinline__ void mma_tf32(float (&d)[4], const unsigned (&a)[4],
                                         const unsigned (&b)[2]) {
    asm volatile(
        "mma.sync.aligned.m16n8k8.row.col.f32.tf32.tf32.f32 "
        "{%0,%1,%2,%3}, {%4,%5,%6,%7}, {%8,%9}, {%0,%1,%2,%3};"
        : "+f"(d[0]), "+f"(d[1]), "+f"(d[2]), "+f"(d[3])
        : "r"(a[0]), "r"(a[1]), "r"(a[2]), "r"(a[3]), "r"(b[0]), "r"(b[1]));
}

__device__ __forceinline__ void cp16(unsigned dst, const void* src, int bytes) {
    asm volatile("cp.async.cg.shared.global [%0], [%1], 16, %2;"
                 :: "r"(dst), "l"(src), "r"(bytes));
}
__device__ __forceinline__ void cp_commit() {
    asm volatile("cp.async.commit_group;" ::: "memory");
}

// ---------------------------------------------------------------------------
// tf32 tensor-core GEMM (inputs pre-rounded to tf32 values; no in-kernel cvt).
// C = [res +] A(MxK) @ B(KxN) + bias(N) [, relu][, outCvt -> tf32-rounded out]
// BM=BN=128, BK=16, 256 threads (8 warps 2x4), warp tile 64x32.
// 3-stage cp.async pipeline in dynamic smem (issue 2 tiles ahead, wait_group 1).
// ---------------------------------------------------------------------------
#define GEMM_SMEM (3 * 128 * 20 * 4 + 3 * 16 * 136 * 4)

__global__ __launch_bounds__(256, 2) void gemm_tc(
    const float* __restrict__ A, const float* __restrict__ B,
    const float* __restrict__ bias, const float* __restrict__ res,
    float* __restrict__ C, int M, int N, int K, int relu, int outCvt,
    int nxPerMat, long bMatStride, long cMatStride, int biasMatStride)
{
    extern __shared__ unsigned dynsm[];
    unsigned (*As)[128][20] = (unsigned (*)[128][20])dynsm;
    unsigned (*Bs)[16][136] = (unsigned (*)[16][136])(dynsm + 3 * 128 * 20);

    const int tid = threadIdx.x;
    const int bx = blockIdx.x, by = blockIdx.y;
    const int mat = bx / nxPerMat;
    const int bxn = bx - mat * nxPerMat;

    const float* Bp    = B + (size_t)mat * bMatStride;
    const float* biasP = bias + (size_t)mat * biasMatStride;
    float*       Cp    = C + (size_t)mat * cMatStride;

    const float* Ablk = A + (size_t)(by * 128) * K;
    const float* Bblk = Bp + bxn * 128;

    const int lane = tid & 31, wid = tid >> 5;
    const int wm = wid >> 2, wn = wid & 3;
    const int gid = lane >> 2, tg = lane & 3;

    const int ar0 = tid >> 2, ac0 = (tid & 3) << 2;
    const int ar1 = ar0 + 64;
    const int bk0 = tid >> 5, bc0 = (tid & 31) << 2;
    const int bk1 = bk0 + 8;

    const unsigned sA = (unsigned)__cvta_generic_to_shared(&dynsm[0]);
    const unsigned sB = (unsigned)__cvta_generic_to_shared(&dynsm[3 * 128 * 20]);

    float acc[4][4][4];
#pragma unroll
    for (int mt = 0; mt < 4; mt++)
#pragma unroll
        for (int nt = 0; nt < 4; nt++)
#pragma unroll
            for (int i = 0; i < 4; i++) acc[mt][nt][i] = 0.f;

    auto issue = [&](int buf, int k0) {
        int c0 = k0 + ac0;
        int rem0 = K - c0;
        int by0 = rem0 >= 4 ? 16 : (rem0 > 0 ? rem0 * 4 : 0);
        cp16(sA + ((buf * 128 + ar0) * 20 + ac0) * 4,
             Ablk + (size_t)ar0 * K + (by0 ? c0 : 0), by0);
        cp16(sA + ((buf * 128 + ar1) * 20 + ac0) * 4,
             Ablk + (size_t)ar1 * K + (by0 ? c0 : 0), by0);
        int kr0 = k0 + bk0;
        int bb0 = (kr0 < K) ? 16 : 0;
        cp16(sB + ((buf * 16 + bk0) * 136 + bc0) * 4,
             Bblk + (size_t)(bb0 ? kr0 : 0) * N + bc0, bb0);
        int kr1 = k0 + bk1;
        int bb1 = (kr1 < K) ? 16 : 0;
        cp16(sB + ((buf * 16 + bk1) * 136 + bc0) * 4,
             Bblk + (size_t)(bb1 ? kr1 : 0) * N + bc0, bb1);
        cp_commit();
    };

    // prologue: stage up to 2 tiles
    issue(0, 0);
    if (16 < K) issue(1, 16);

    int cur = 0;
    for (int k0 = 0; k0 < K; k0 += 16) {
        // wait for tile `cur` (keep 1 group in flight when more tiles remain)
        if (k0 + 16 < K) {
            asm volatile("cp.async.wait_group 1;" ::: "memory");
        } else {
            asm volatile("cp.async.wait_group 0;" ::: "memory");
        }
        __syncthreads();
        if (k0 + 32 < K) {
            int nb = cur + 2; if (nb >= 3) nb -= 3;
            issue(nb, k0 + 32);
        }

#pragma unroll
        for (int ks = 0; ks < 16; ks += 8) {
            unsigned a[4][4], b[4][2];
#pragma unroll
            for (int mt = 0; mt < 4; mt++) {
                int r = wm * 64 + mt * 16 + gid;
                a[mt][0] = As[cur][r][ks + tg];
                a[mt][1] = As[cur][r + 8][ks + tg];
                a[mt][2] = As[cur][r][ks + tg + 4];
                a[mt][3] = As[cur][r + 8][ks + tg + 4];
            }
#pragma unroll
            for (int nt = 0; nt < 4; nt++) {
                int cb = wn * 32 + nt * 8 + gid;
                b[nt][0] = Bs[cur][ks + tg][cb];
                b[nt][1] = Bs[cur][ks + tg + 4][cb];
            }
#pragma unroll
            for (int mt = 0; mt < 4; mt++)
#pragma unroll
                for (int nt = 0; nt < 4; nt++)
                    mma_tf32(acc[mt][nt], a[mt], b[nt]);
        }
        __syncthreads();   // compute done before this buffer can be re-filled
        cur = cur + 1; if (cur >= 3) cur -= 3;
    }

#pragma unroll
    for (int mt = 0; mt < 4; mt++) {
        int r0 = by * 128 + wm * 64 + mt * 16 + gid;
#pragma unroll
        for (int nt = 0; nt < 4; nt++) {
            int c0 = bxn * 128 + wn * 32 + nt * 8 + tg * 2;
            float bza = biasP[c0], bzb = biasP[c0 + 1];
            size_t off0 = (size_t)r0 * N + c0;
            size_t off1 = (size_t)(r0 + 8) * N + c0;
            float v0 = acc[mt][nt][0] + bza, v1 = acc[mt][nt][1] + bzb;
            float v2 = acc[mt][nt][2] + bza, v3 = acc[mt][nt][3] + bzb;
            if (res) {
                v0 += res[off0]; v1 += res[off0 + 1];
                v2 += res[off1]; v3 += res[off1 + 1];
            }
            if (relu) {
                v0 = fmaxf(v0, 0.f); v1 = fmaxf(v1, 0.f);
                v2 = fmaxf(v2, 0.f); v3 = fmaxf(v3, 0.f);
            }
            if (outCvt) {
                v0 = tfv(v0); v1 = tfv(v1); v2 = tfv(v2); v3 = tfv(v3);
            }
            *(float2*)(Cp + off0) = make_float2(v0, v1);
            *(float2*)(Cp + off1) = make_float2(v2, v3);
        }
    }
}

// ---------------------------------------------------------------------------
// LayerNorm: warp per row (E=256), float4, 8 rows/block; output tf32-rounded.
// ---------------------------------------------------------------------------
__global__ __launch_bounds__(256) void layernorm_k(
    const float* __restrict__ x, const float* __restrict__ g,
    const float* __restrict__ b, float* __restrict__ y)
{
    int tid = threadIdx.x;
    int lane = tid & 31;
    int row = blockIdx.x * 8 + (tid >> 5);

    const float4* xr = (const float4*)(x + (size_t)row * 256);
    float4 v0 = xr[lane], v1 = xr[lane + 32];

    float s = v0.x + v0.y + v0.z + v0.w + v1.x + v1.y + v1.z + v1.w;
#pragma unroll
    for (int o = 16; o > 0; o >>= 1) s += __shfl_xor_sync(0xffffffffu, s, o);
    float mean = s * (1.f / 256.f);

    float4 d0 = make_float4(v0.x - mean, v0.y - mean, v0.z - mean, v0.w - mean);
    float4 d1 = make_float4(v1.x - mean, v1.y - mean, v1.z - mean, v1.w - mean);
    float sq = d0.x * d0.x + d0.y * d0.y + d0.z * d0.z + d0.w * d0.w
             + d1.x * d1.x + d1.y * d1.y + d1.z * d1.z + d1.w * d1.w;
#pragma unroll
    for (int o = 16; o > 0; o >>= 1) sq += __shfl_xor_sync(0xffffffffu, sq, o);
    float var = sq * (1.f / 255.f);
    float r = 1.f / (sqrtf(var) + 1e-6f);

    const float4* g4 = (const float4*)g;
    const float4* b4 = (const float4*)b;
    float4 gg0 = g4[lane], gg1 = g4[lane + 32];
    float4 bb0 = b4[lane], bb1 = b4[lane + 32];

    float4 o0, o1;
    o0.x = tfv(gg0.x * d0.x * r + bb0.x); o0.y = tfv(gg0.y * d0.y * r + bb0.y);
    o0.z = tfv(gg0.z * d0.z * r + bb0.z); o0.w = tfv(gg0.w * d0.w * r + bb0.w);
    o1.x = tfv(gg1.x * d1.x * r + bb1.x); o1.y = tfv(gg1.y * d1.y * r + bb1.y);
    o1.z = tfv(gg1.z * d1.z * r + bb1.z); o1.w = tfv(gg1.w * d1.w * r + bb1.w);

    float4* yr = (float4*)(y + (size_t)row * 256);
    yr[lane] = o0;
    yr[lane + 32] = o1;
}

// ---------------------------------------------------------------------------
// Tensor-core flash attention (R5-proven).
// ---------------------------------------------------------------------------
__global__ __launch_bounds__(256, 2) void attn_tc(
    const float* __restrict__ Q, const float* __restrict__ K,
    const float* __restrict__ V, const float* __restrict__ mask,
    float* __restrict__ O)
{
    extern __shared__ unsigned smu[];
    unsigned* Ks = smu;                        // [128][44]
    unsigned* Vs = smu + 128 * 44;             // [128][40]
    unsigned* Ps = smu + 128 * 44 + 128 * 40;  // [128][132]

    const int qt = blockIdx.x;
    const int bh = blockIdx.y;
    const int b = bh >> 3, h = bh & 7;
    const int tid = threadIdx.x;
    const int w = tid >> 5, lane = tid & 31;
    const int gid = lane >> 2, tg = lane & 3;

    const int r0 = w * 16 + gid;
    const int r1 = r0 + 8;
    const size_t qbase = ((size_t)(b * 512 + qt * 128)) * 256 + h * 32;
    const float scale = 0.17677669529663689f;

    unsigned aQ[4][4];
#pragma unroll
    for (int ks = 0; ks < 4; ks++) {
        aQ[ks][0] = f2tf(Q[qbase + (size_t)r0 * 256 + ks * 8 + tg] * scale);
        aQ[ks][1] = f2tf(Q[qbase + (size_t)r1 * 256 + ks * 8 + tg] * scale);
        aQ[ks][2] = f2tf(Q[qbase + (size_t)r0 * 256 + ks * 8 + tg + 4] * scale);
        aQ[ks][3] = f2tf(Q[qbase + (size_t)r1 * 256 + ks * 8 + tg + 4] * scale);
    }
    const bool mz0 = (mask[b * 512 + qt * 128 + r0] == 0.f);
    const bool mz1 = (mask[b * 512 + qt * 128 + r1] == 0.f);

    float m0 = -1e30f, m1 = -1e30f, l0 = 0.f, l1 = 0.f;
    float o[4][4];
#pragma unroll
    for (int nt = 0; nt < 4; nt++)
#pragma unroll
        for (int i = 0; i < 4; i++) o[nt][i] = 0.f;

    for (int kc = 0; kc < 4; kc++) {
        __syncthreads();
        const size_t kvbase = ((size_t)(b * 512 + kc * 128)) * 256 + h * 32;
        for (int idx = tid; idx < 1024; idx += 256) {
            int key = idx >> 3, d4 = idx & 7;
            const uint4* ks4 = (const uint4*)(K + kvbase + (size_t)key * 256) + d4;
            const uint4* vs4 = (const uint4*)(V + kvbase + (size_t)key * 256) + d4;
            *(uint4*)(Ks + key * 44 + d4 * 4) = *ks4;
            *(uint4*)(Vs + key * 40 + d4 * 4) = *vs4;
        }
        __syncthreads();

        float s[16][4];
#pragma unroll
        for (int nt = 0; nt < 16; nt++) {
            s[nt][0] = s[nt][1] = s[nt][2] = s[nt][3] = 0.f;
            const unsigned* kp = Ks + (nt * 8 + gid) * 44;
#pragma unroll
            for (int ks = 0; ks < 4; ks++) {
                unsigned bk[2] = { kp[ks * 8 + tg], kp[ks * 8 + tg + 4] };
                mma_tf32(s[nt], aQ[ks], bk);
            }
        }
        if (mz0) {
#pragma unroll
            for (int nt = 0; nt < 16; nt++) { s[nt][0] = -1e9f; s[nt][1] = -1e9f; }
        }
        if (mz1) {
#pragma unroll
            for (int nt = 0; nt < 16; nt++) { s[nt][2] = -1e9f; s[nt][3] = -1e9f; }
        }

        float rm0 = -1e30f, rm1 = -1e30f;
#pragma unroll
        for (int nt = 0; nt < 16; nt++) {
            rm0 = fmaxf(rm0, fmaxf(s[nt][0], s[nt][1]));
            rm1 = fmaxf(rm1, fmaxf(s[nt][2], s[nt][3]));
        }
        rm0 = fmaxf(rm0, __shfl_xor_sync(0xffffffffu, rm0, 1));
        rm0 = fmaxf(rm0, __shfl_xor_sync(0xffffffffu, rm0, 2));
        rm1 = fmaxf(rm1, __shfl_xor_sync(0xffffffffu, rm1, 1));
        rm1 = fmaxf(rm1, __shfl_xor_sync(0xffffffffu, rm1, 2));
        float mn0 = fmaxf(m0, rm0), mn1 = fmaxf(m1, rm1);
        float c0 = __expf(m0 - mn0), c1 = __expf(m1 - mn1);
        m0 = mn0; m1 = mn1;

        float ps0 = 0.f, ps1 = 0.f;
        unsigned* pr0 = Ps + r0 * 132;
        unsigned* pr1 = Ps + r1 * 132;
#pragma unroll
        for (int nt = 0; nt < 16; nt++) {
            float p00 = __expf(s[nt][0] - mn0), p01 = __expf(s[nt][1] - mn0);
            float p10 = __expf(s[nt][2] - mn1), p11 = __expf(s[nt][3] - mn1);
            ps0 += p00 + p01;
            ps1 += p10 + p11;
            int cc = nt * 8 + 2 * tg;
            pr0[cc] = f2tf(p00); pr0[cc + 1] = f2tf(p01);
            pr1[cc] = f2tf(p10); pr1[cc + 1] = f2tf(p11);
        }
        ps0 += __shfl_xor_sync(0xffffffffu, ps0, 1);
        ps0 += __shfl_xor_sync(0xffffffffu, ps0, 2);
        ps1 += __shfl_xor_sync(0xffffffffu, ps1, 1);
        ps1 += __shfl_xor_sync(0xffffffffu, ps1, 2);
        l0 = l0 * c0 + ps0;
        l1 = l1 * c1 + ps1;
#pragma unroll
        for (int nt = 0; nt < 4; nt++) {
            o[nt][0] *= c0; o[nt][1] *= c0;
            o[nt][2] *= c1; o[nt][3] *= c1;
        }
        __syncwarp();

#pragma unroll
        for (int ks = 0; ks < 16; ks++) {
            unsigned aP[4] = { pr0[ks * 8 + tg], pr1[ks * 8 + tg],
                               pr0[ks * 8 + tg + 4], pr1[ks * 8 + tg + 4] };
#pragma unroll
            for (int nt = 0; nt < 4; nt++) {
                const unsigned* vp = Vs + nt * 8 + gid;
                unsigned bv[2] = { vp[(ks * 8 + tg) * 40], vp[(ks * 8 + tg + 4) * 40] };
                mma_tf32(o[nt], aP, bv);
            }
        }
    }

    float inv0 = 1.f / l0, inv1 = 1.f / l1;
    float* Or0 = O + qbase + (size_t)r0 * 256;
    float* Or1 = O + qbase + (size_t)r1 * 256;
#pragma unroll
    for (int nt = 0; nt < 4; nt++) {
        int cc = nt * 8 + 2 * tg;
        Or0[cc]     = tfv(o[nt][0] * inv0);
        Or0[cc + 1] = tfv(o[nt][1] * inv0);
        Or1[cc]     = tfv(o[nt][2] * inv1);
        Or1[cc + 1] = tfv(o[nt][3] * inv1);
    }
}

// ---------------------------------------------------------------------------
// Weight/input pre-conversion to tf32-rounded fp32 values
// ---------------------------------------------------------------------------
__global__ __launch_bounds__(256) void cvtw_k(
    const float* __restrict__ inputs, const float* __restrict__ emb,
    const float* __restrict__ qkvo, const float* __restrict__ f1,
    const float* __restrict__ f2, float* __restrict__ inT,
    float* __restrict__ wtf)
{
    int idx = blockIdx.x * 256 + threadIdx.x;
    if (idx < 4915200) inT[idx] = tfv(inputs[idx]);
    if (idx < 2042880) {
        float v;
        if (idx < OFF_QKVO)      v = emb[idx - OFF_EMB];
        else if (idx < OFF_FF1)  v = qkvo[idx - OFF_QKVO];
        else if (idx < OFF_FF2)  v = f1[idx - OFF_FF1];
        else                     v = f2[idx - OFF_FF2];
        wtf[idx] = tfv(v);
    }
}

// ---------------------------------------------------------------------------
// LSTM prep: build transposed/merged weights, g0, biasTot, w1t; zero barrier.
// ---------------------------------------------------------------------------
__global__ __launch_bounds__(256) void lstm_prep_k(
    const float* __restrict__ wih, const float* __restrict__ whh,
    const float* __restrict__ bih, const float* __restrict__ bhh,
    const float* __restrict__ dec_h0, const float* __restrict__ out_w1,
    float* __restrict__ WihEncT, float* __restrict__ WmR,
    float* __restrict__ w1t, float* __restrict__ g0,
    float* __restrict__ biasTot, unsigned* __restrict__ sync)
{
    int idx = blockIdx.x * 256 + threadIdx.x;
    if (idx == 0) *sync = 0u;
    if (idx < 262144) {
        int k = idx >> 10, n = idx & 1023;
        WihEncT[idx] = tfv(wih[(size_t)n * 512 + 256 + k]);

        int gb = idx >> 12;
        int r = idx & 4095;
        int gi = r >> 10;
        int rem = r & 1023;
        int el = rem >> 8;
        int kk = rem & 255;
        int col = gi * 256 + gb * 4 + el;
        WmR[idx] = wih[(size_t)col * 512 + kk] + whh[(size_t)col * 256 + kk];
    }
    if (idx < 32768) {
        int h = idx >> 8, k = idx & 255;
        w1t[idx] = out_w1[(size_t)k * 128 + h];
    }
    if (idx < 1024) {
        float a = 0.f;
        for (int k = 0; k < 256; k++) a = fmaf(dec_h0[k], whh[(size_t)idx * 256 + k], a);
        g0[idx] = a;
        biasTot[idx] = bih[idx] + bhh[idx];
    }
}

// ---------------------------------------------------------------------------
// Persistent LSTM: 96 blocks (64 gate + 32 MLP), all co-resident (1/SM),
// custom grid barrier on g_sync. Single change vs R7: spin WITHOUT nanosleep.
// ---------------------------------------------------------------------------
__device__ __forceinline__ float sigf(float x) { return 1.f / (1.f + __expf(-x)); }

__device__ __forceinline__ void grid_bar(unsigned* sync, unsigned target) {
    __threadfence();
    __syncthreads();
    if (threadIdx.x == 0) {
        atomicAdd(sync, 1u);
        while (*(volatile unsigned*)sync < target) { }
        __threadfence();
    }
    __syncthreads();
}

__global__ __launch_bounds__(256, 1) void lstm_persist_k(
    const float* __restrict__ pre, const float* __restrict__ WmR,
    const float* __restrict__ w1t, const float* __restrict__ g0,
    const float* __restrict__ dec_c0,
    const float* __restrict__ b1, const float* __restrict__ w2,
    const float* __restrict__ b2, const float* __restrict__ mask,
    float* __restrict__ hbuf, unsigned* __restrict__ sync,
    float* __restrict__ out)
{
    extern __shared__ float sm[];
    const int tid = threadIdx.x;
    const unsigned NBLK = 96;

    if (blockIdx.x < 64) {
        const int gb = blockIdx.x;
        const int half = tid & 1;
        const int p = tid >> 1;
        const int b = p & 31;
        const int el = p >> 5;
        const int e = gb * 4 + el;

        float4* ws4 = (float4*)sm;
        float4* hs4 = (float4*)(sm + 4096);

        const float4* wsrc = (const float4*)(WmR + (size_t)gb * 4096);
        for (int i = tid; i < 1024; i += 256) ws4[i] = wsrc[i];

        float c = dec_c0[e];

        for (int t = 0; t < 512; ++t) {
            float gv0 = 0.f, gv1 = 0.f, gv2 = 0.f, gv3 = 0.f;
            if (t == 0) {
                if (half == 0) {
                    const float* pr = pre + (size_t)b * 512 * 1024;
                    gv0 = pr[e]       + g0[e];
                    gv1 = pr[256 + e] + g0[256 + e];
                    gv2 = pr[512 + e] + g0[512 + e];
                    gv3 = pr[768 + e] + g0[768 + e];
                }
            } else {
                const float4* hsrc = (const float4*)(hbuf + (t & 1) * 8192);
                for (int j = tid; j < 2048; j += 256) {
                    float4 v = __ldcg(hsrc + j);
                    int bb = j >> 6, k4 = j & 63;
                    hs4[bb * 66 + (k4 >> 5) * 33 + (k4 & 31)] = v;
                }
                __syncthreads();

                float a0 = 0.f, a1 = 0.f, a2 = 0.f, a3 = 0.f;
                const float4* hp = hs4 + b * 66 + half * 33;
                const float4* wp = ws4 + el * 64 + half * 32;
#pragma unroll
                for (int kk = 0; kk < 32; kk++) {
                    float4 hv = hp[kk];
                    float4 w0 = wp[kk];
                    float4 w1v = wp[256 + kk];
                    float4 w2v = wp[512 + kk];
                    float4 w3v = wp[768 + kk];
                    a0 = fmaf(hv.x, w0.x, fmaf(hv.y, w0.y, fmaf(hv.z, w0.z, fmaf(hv.w, w0.w, a0))));
                    a1 = fmaf(hv.x, w1v.x, fmaf(hv.y, w1v.y, fmaf(hv.z, w1v.z, fmaf(hv.w, w1v.w, a1))));
                    a2 = fmaf(hv.x, w2v.x, fmaf(hv.y, w2v.y, fmaf(hv.z, w2v.z, fmaf(hv.w, w2v.w, a2))));
                    a3 = fmaf(hv.x, w3v.x, fmaf(hv.y, w3v.y, fmaf(hv.z, w3v.z, fmaf(hv.w, w3v.w, a3))));
                }
                a0 += __shfl_xor_sync(0xffffffffu, a0, 1);
                a1 += __shfl_xor_sync(0xffffffffu, a1, 1);
                a2 += __shfl_xor_sync(0xffffffffu, a2, 1);
                a3 += __shfl_xor_sync(0xffffffffu, a3, 1);
                if (half == 0) {
                    const float* pr = pre + ((size_t)b * 512 + t) * 1024;
                    gv0 = a0 + pr[e];
                    gv1 = a1 + pr[256 + e];
                    gv2 = a2 + pr[512 + e];
                    gv3 = a3 + pr[768 + e];
                }
            }
            if (half == 0) {
                float cn = sigf(gv1) * c + sigf(gv0) * tanhf(gv2);
                float hn = sigf(gv3) * tanhf(cn);
                c = cn;
                __stcg(hbuf + ((t + 1) & 1) * 8192 + b * 256 + e, hn);
            }
            grid_bar(sync, (unsigned)(t + 1) * NBLK);
        }
    } else {
        const int b = blockIdx.x - 64;
        float* w1s  = sm;
        float* hrow = sm + 33280;
        float* red  = sm + 33536;

        for (int i = tid; i < 8192; i += 256) {
            int h = i >> 6, k4 = i & 63;
            ((float4*)w1s)[h * 65 + k4] = ((const float4*)w1t)[i];
        }
        float w2v = (tid < 128) ? w2[tid] : 0.f;
        float b1v = (tid < 128) ? b1[tid] : 0.f;
        float b2v = b2[0];

        for (int t = 0; t <= 512; ++t) {
            if (t >= 1) {
                hrow[tid] = __ldcg(hbuf + (t & 1) * 8192 + b * 256 + tid);
                __syncthreads();
                float contrib = 0.f;
                if (tid < 128) {
                    float a = b1v;
                    const float4* h4 = (const float4*)hrow;
                    const float4* w4 = (const float4*)(w1s + tid * 260);
#pragma unroll 16
                    for (int kk = 0; kk < 64; kk++) {
                        float4 hv = h4[kk];
                        float4 wv = w4[kk];
                        a = fmaf(hv.x, wv.x, fmaf(hv.y, wv.y, fmaf(hv.z, wv.z, fmaf(hv.w, wv.w, a))));
                    }
                    contrib = fmaxf(a, 0.f) * w2v;
                }
#pragma unroll
                for (int o = 16; o > 0; o >>= 1)
                    contrib += __shfl_down_sync(0xffffffffu, contrib, o);
                if (tid < 128 && (tid & 31) == 0) red[tid >> 5] = contrib;
                __syncthreads();
                if (tid == 0) {
                    float pp = red[0] + red[1] + red[2] + red[3] + b2v;
                    out[b * 512 + (t - 1)] = pp * mask[b * 512 + (t - 1)];
                }
                __syncthreads();
            }
            if (t < 512) grid_bar(sync, (unsigned)(t + 1) * NBLK);
        }
    }
}

// ---------------------------------------------------------------------------
// Launcher
// ---------------------------------------------------------------------------
extern "C" void kernel_launch(void* const* d_in, const int* in_sizes, int n_in,
                              void* d_out, int out_size)
{
    const float* inputs   = (const float*)d_in[0];
    const float* mask     = (const float*)d_in[1];
    /* d_in[2] = lengths (unused) */
    const float* embed_w  = (const float*)d_in[3];
    const float* embed_b  = (const float*)d_in[4];
    const float* qkvo_w   = (const float*)d_in[5];
    const float* qkvo_b   = (const float*)d_in[6];
    const float* ln_g     = (const float*)d_in[7];
    const float* ln_b     = (const float*)d_in[8];
    const float* ff_w1    = (const float*)d_in[9];
    const float* ff_b1    = (const float*)d_in[10];
    const float* ff_w2    = (const float*)d_in[11];
    const float* ff_b2    = (const float*)d_in[12];
    const float* enc_ln_g = (const float*)d_in[13];
    const float* enc_ln_b = (const float*)d_in[14];
    const float* wih      = (const float*)d_in[15];
    const float* whh      = (const float*)d_in[16];
    const float* bih      = (const float*)d_in[17];
    const float* bhh      = (const float*)d_in[18];
    const float* dec_h0   = (const float*)d_in[19];
    const float* dec_c0   = (const float*)d_in[20];
    const float* out_w1   = (const float*)d_in[21];
    const float* out_b1   = (const float*)d_in[22];
    const float* out_w2   = (const float*)d_in[23];
    const float* out_b2   = (const float*)d_in[24];
    float* out = (float*)d_out;
    (void)in_sizes; (void)n_in; (void)out_size;

    float *px, *py, *pqkv, *po, *ph1, *ppre, *pinT, *pwtf, *pWET, *pWmR, *pw1t,
          *pg0, *pbt, *phb;
    unsigned* psync;
    cudaGetSymbolAddress((void**)&px,    g_x);
    cudaGetSymbolAddress((void**)&py,    g_y);
    cudaGetSymbolAddress((void**)&pqkv,  g_qkv);
    cudaGetSymbolAddress((void**)&po,    g_o);
    cudaGetSymbolAddress((void**)&ph1,   g_h1);
    cudaGetSymbolAddress((void**)&ppre,  g_pre);
    cudaGetSymbolAddress((void**)&pinT,  g_inT);
    cudaGetSymbolAddress((void**)&pwtf,  g_wtf);
    cudaGetSymbolAddress((void**)&pWET,  g_WihEncT);
    cudaGetSymbolAddress((void**)&pWmR,  g_WmR);
    cudaGetSymbolAddress((void**)&pw1t,  g_w1t);
    cudaGetSymbolAddress((void**)&pg0,   g_g0);
    cudaGetSymbolAddress((void**)&pbt,   g_biasTot);
    cudaGetSymbolAddress((void**)&phb,   g_hbuf);
    cudaGetSymbolAddress((void**)&psync, g_sync);

    cudaFuncSetAttribute(gemm_tc, cudaFuncAttributeMaxDynamicSharedMemorySize, GEMM_SMEM);
    cudaFuncSetAttribute(attn_tc, cudaFuncAttributeMaxDynamicSharedMemorySize, 110592);
    cudaFuncSetAttribute(lstm_persist_k, cudaFuncAttributeMaxDynamicSharedMemorySize, 137216);

    const int M = 16384;
    const long QKV_C = 16384L * 256;

    // prep: tf32 conversions + LSTM weights + barrier reset
    cvtw_k<<<19200, 256>>>(inputs, embed_w, qkvo_w, ff_w1, ff_w2, pinT, pwtf);
    lstm_prep_k<<<1024, 256>>>(wih, whh, bih, bhh, dec_h0, out_w1,
                               pWET, pWmR, pw1t, pg0, pbt, psync);

    // Embed (K=300)
    gemm_tc<<<dim3(2, 128), 256, GEMM_SMEM>>>(pinT, pwtf + OFF_EMB, embed_b,
                                              nullptr, px,
                                              M, 256, 300, 0, 0, 2, 0, 0, 0);

    // Transformer layers
    for (int l = 0; l < 6; l++) {
        const float* Wq = pwtf + OFF_QKVO + (size_t)(l * 4) * 65536;
        const float* Wo = pwtf + OFF_QKVO + (size_t)(l * 4 + 3) * 65536;
        const float* bq = qkvo_b + (l * 4) * 256;
        const float* bo = qkvo_b + (l * 4 + 3) * 256;

        layernorm_k<<<2048, 256>>>(px, ln_g + l * 512, ln_b + l * 512, py);
        gemm_tc<<<dim3(6, 128), 256, GEMM_SMEM>>>(py, Wq, bq, nullptr, pqkv,
                                                  M, 256, 256, 0, 1,
                                                  2, 65536, QKV_C, 256);
        attn_tc<<<dim3(4, 256), 256, 110592>>>(pqkv, pqkv + QKV_C,
                                               pqkv + 2 * QKV_C, mask, po);
        gemm_tc<<<dim3(2, 128), 256, GEMM_SMEM>>>(po, Wo, bo, px, px,
                                                  M, 256, 256, 0, 0, 2, 0, 0, 0);

        layernorm_k<<<2048, 256>>>(px, ln_g + l * 512 + 256, ln_b + l * 512 + 256, py);
        gemm_tc<<<dim3(1, 128), 256, GEMM_SMEM>>>(py, pwtf + OFF_FF1 + (size_t)l * 32768,
                                                  ff_b1 + l * 128, nullptr, ph1,
                                                  M, 128, 256, 1, 1, 1, 0, 0, 0);
        gemm_tc<<<dim3(2, 128), 256, GEMM_SMEM>>>(ph1, pwtf + OFF_FF2 + (size_t)l * 32768,
                                                  ff_b2 + l * 256, px, px,
                                                  M, 256, 128, 0, 0, 2, 0, 0, 0);
    }

    // Encoder LN -> enc (in py, tf32-rounded)
    layernorm_k<<<2048, 256>>>(px, enc_ln_g, enc_ln_b, py);

    // pre = enc @ wih[:,256:].T + (bih+bhh)
    gemm_tc<<<dim3(8, 128), 256, GEMM_SMEM>>>(py, pWET, pbt, nullptr, ppre,
                                              M, 1024, 256, 0, 0, 8, 0, 0, 0);

    // Persistent LSTM scan + output head (single launch, 96 blocks)
    lstm_persist_k<<<96, 256, 137216>>>(ppre, pWmR, pw1t, pg0, dec_c0,
                                        out_b1, out_w2, out_b2, mask,
                                        phb, psync, out);
}

// round 9
// speedup vs baseline: 2.4904x; 1.1507x over previous
#include <cuda_runtime.h>
#include <cuda_bf16.h>
#include <math.h>

// ---------------------------------------------------------------------------
// Scratch (device globals — allocation-free per harness rules)
// ---------------------------------------------------------------------------
__device__ float g_x   [16384 * 256];
__device__ float g_y   [16384 * 256];
__device__ float g_qkv [3 * 16384 * 256];
__device__ float g_o   [16384 * 256];
__device__ float g_h1  [16384 * 128];
__device__ float g_pre [16384 * 1024];
__device__ float g_inT [16384 * 300];     // tf32-rounded inputs
__device__ float g_wtf [2042880];         // tf32-rounded weights (emb|qkvo|ff1|ff2)
__device__ float g_WihEncT[256 * 1024];   // (wih[:,256:512]).T, tf32-rounded
__device__ float g_WmR [128 * 2048];      // merged (wih[:,:256]+whh).T, [gb][sub][k]
__device__ float g_w1t [128 * 256];       // out_w1 transposed [h][k]
__device__ float g_g0  [1024];            // dec_h0 @ whh.T
__device__ float g_biasTot[1024];         // bih + bhh
__device__ float g_hbuf[2 * 32 * 256];
__device__ unsigned g_sync;               // grid barrier counter (zeroed in prep)

#define OFF_EMB  0
#define OFF_QKVO 76800
#define OFF_FF1  1649664
#define OFF_FF2  1846272

// ---------------------------------------------------------------------------
// tf32 / mma helpers
// ---------------------------------------------------------------------------
__device__ __forceinline__ unsigned f2tf(float f) {
    unsigned u;
    asm("cvt.rna.tf32.f32 %0, %1;" : "=r"(u) : "f"(f));
    return u;
}
__device__ __forceinline__ float tfv(float f) { return __uint_as_float(f2tf(f)); }

__device__ __forceinline__ void mma_tf32(float (&d)[4], const unsigned (&a)[4],
                                         const unsigned (&b)[2]) {
    asm volatile(
        "mma.sync.aligned.m16n8k8.row.col.f32.tf32.tf32.f32 "
        "{%0,%1,%2,%3}, {%4,%5,%6,%7}, {%8,%9}, {%0,%1,%2,%3};"
        : "+f"(d[0]), "+f"(d[1]), "+f"(d[2]), "+f"(d[3])
        : "r"(a[0]), "r"(a[1]), "r"(a[2]), "r"(a[3]), "r"(b[0]), "r"(b[1]));
}

__device__ __forceinline__ void cp16(unsigned dst, const void* src, int bytes) {
    asm volatile("cp.async.cg.shared.global [%0], [%1], 16, %2;"
                 :: "r"(dst), "l"(src), "r"(bytes));
}
__device__ __forceinline__ void cp_commit() {
    asm volatile("cp.async.commit_group;" ::: "memory");
}

// ---------------------------------------------------------------------------
// tf32 tensor-core GEMM (unchanged from R8/passing).
// ---------------------------------------------------------------------------
#define GEMM_SMEM (3 * 128 * 20 * 4 + 3 * 16 * 136 * 4)

__global__ __launch_bounds__(256, 2) void gemm_tc(
    const float* __restrict__ A, const float* __restrict__ B,
    const float* __restrict__ bias, const float* __restrict__ res,
    float* __restrict__ C, int M, int N, int K, int relu, int outCvt,
    int nxPerMat, long bMatStride, long cMatStride, int biasMatStride)
{
    extern __shared__ unsigned dynsm[];
    unsigned (*As)[128][20] = (unsigned (*)[128][20])dynsm;
    unsigned (*Bs)[16][136] = (unsigned (*)[16][136])(dynsm + 3 * 128 * 20);

    const int tid = threadIdx.x;
    const int bx = blockIdx.x, by = blockIdx.y;
    const int mat = bx / nxPerMat;
    const int bxn = bx - mat * nxPerMat;

    const float* Bp    = B + (size_t)mat * bMatStride;
    const float* biasP = bias + (size_t)mat * biasMatStride;
    float*       Cp    = C + (size_t)mat * cMatStride;

    const float* Ablk = A + (size_t)(by * 128) * K;
    const float* Bblk = Bp + bxn * 128;

    const int lane = tid & 31, wid = tid >> 5;
    const int wm = wid >> 2, wn = wid & 3;
    const int gid = lane >> 2, tg = lane & 3;

    const int ar0 = tid >> 2, ac0 = (tid & 3) << 2;
    const int ar1 = ar0 + 64;
    const int bk0 = tid >> 5, bc0 = (tid & 31) << 2;
    const int bk1 = bk0 + 8;

    const unsigned sA = (unsigned)__cvta_generic_to_shared(&dynsm[0]);
    const unsigned sB = (unsigned)__cvta_generic_to_shared(&dynsm[3 * 128 * 20]);

    float acc[4][4][4];
#pragma unroll
    for (int mt = 0; mt < 4; mt++)
#pragma unroll
        for (int nt = 0; nt < 4; nt++)
#pragma unroll
            for (int i = 0; i < 4; i++) acc[mt][nt][i] = 0.f;

    auto issue = [&](int buf, int k0) {
        int c0 = k0 + ac0;
        int rem0 = K - c0;
        int by0 = rem0 >= 4 ? 16 : (rem0 > 0 ? rem0 * 4 : 0);
        cp16(sA + ((buf * 128 + ar0) * 20 + ac0) * 4,
             Ablk + (size_t)ar0 * K + (by0 ? c0 : 0), by0);
        cp16(sA + ((buf * 128 + ar1) * 20 + ac0) * 4,
             Ablk + (size_t)ar1 * K + (by0 ? c0 : 0), by0);
        int kr0 = k0 + bk0;
        int bb0 = (kr0 < K) ? 16 : 0;
        cp16(sB + ((buf * 16 + bk0) * 136 + bc0) * 4,
             Bblk + (size_t)(bb0 ? kr0 : 0) * N + bc0, bb0);
        int kr1 = k0 + bk1;
        int bb1 = (kr1 < K) ? 16 : 0;
        cp16(sB + ((buf * 16 + bk1) * 136 + bc0) * 4,
             Bblk + (size_t)(bb1 ? kr1 : 0) * N + bc0, bb1);
        cp_commit();
    };

    issue(0, 0);
    if (16 < K) issue(1, 16);

    int cur = 0;
    for (int k0 = 0; k0 < K; k0 += 16) {
        if (k0 + 16 < K) {
            asm volatile("cp.async.wait_group 1;" ::: "memory");
        } else {
            asm volatile("cp.async.wait_group 0;" ::: "memory");
        }
        __syncthreads();
        if (k0 + 32 < K) {
            int nb = cur + 2; if (nb >= 3) nb -= 3;
            issue(nb, k0 + 32);
        }

#pragma unroll
        for (int ks = 0; ks < 16; ks += 8) {
            unsigned a[4][4], b[4][2];
#pragma unroll
            for (int mt = 0; mt < 4; mt++) {
                int r = wm * 64 + mt * 16 + gid;
                a[mt][0] = As[cur][r][ks + tg];
                a[mt][1] = As[cur][r + 8][ks + tg];
                a[mt][2] = As[cur][r][ks + tg + 4];
                a[mt][3] = As[cur][r + 8][ks + tg + 4];
            }
#pragma unroll
            for (int nt = 0; nt < 4; nt++) {
                int cb = wn * 32 + nt * 8 + gid;
                b[nt][0] = Bs[cur][ks + tg][cb];
                b[nt][1] = Bs[cur][ks + tg + 4][cb];
            }
#pragma unroll
            for (int mt = 0; mt < 4; mt++)
#pragma unroll
                for (int nt = 0; nt < 4; nt++)
                    mma_tf32(acc[mt][nt], a[mt], b[nt]);
        }
        __syncthreads();
        cur = cur + 1; if (cur >= 3) cur -= 3;
    }

#pragma unroll
    for (int mt = 0; mt < 4; mt++) {
        int r0 = by * 128 + wm * 64 + mt * 16 + gid;
#pragma unroll
        for (int nt = 0; nt < 4; nt++) {
            int c0 = bxn * 128 + wn * 32 + nt * 8 + tg * 2;
            float bza = biasP[c0], bzb = biasP[c0 + 1];
            size_t off0 = (size_t)r0 * N + c0;
            size_t off1 = (size_t)(r0 + 8) * N + c0;
            float v0 = acc[mt][nt][0] + bza, v1 = acc[mt][nt][1] + bzb;
            float v2 = acc[mt][nt][2] + bza, v3 = acc[mt][nt][3] + bzb;
            if (res) {
                v0 += res[off0]; v1 += res[off0 + 1];
                v2 += res[off1]; v3 += res[off1 + 1];
            }
            if (relu) {
                v0 = fmaxf(v0, 0.f); v1 = fmaxf(v1, 0.f);
                v2 = fmaxf(v2, 0.f); v3 = fmaxf(v3, 0.f);
            }
            if (outCvt) {
                v0 = tfv(v0); v1 = tfv(v1); v2 = tfv(v2); v3 = tfv(v3);
            }
            *(float2*)(Cp + off0) = make_float2(v0, v1);
            *(float2*)(Cp + off1) = make_float2(v2, v3);
        }
    }
}

// ---------------------------------------------------------------------------
// LayerNorm (unchanged).
// ---------------------------------------------------------------------------
__global__ __launch_bounds__(256) void layernorm_k(
    const float* __restrict__ x, const float* __restrict__ g,
    const float* __restrict__ b, float* __restrict__ y)
{
    int tid = threadIdx.x;
    int lane = tid & 31;
    int row = blockIdx.x * 8 + (tid >> 5);

    const float4* xr = (const float4*)(x + (size_t)row * 256);
    float4 v0 = xr[lane], v1 = xr[lane + 32];

    float s = v0.x + v0.y + v0.z + v0.w + v1.x + v1.y + v1.z + v1.w;
#pragma unroll
    for (int o = 16; o > 0; o >>= 1) s += __shfl_xor_sync(0xffffffffu, s, o);
    float mean = s * (1.f / 256.f);

    float4 d0 = make_float4(v0.x - mean, v0.y - mean, v0.z - mean, v0.w - mean);
    float4 d1 = make_float4(v1.x - mean, v1.y - mean, v1.z - mean, v1.w - mean);
    float sq = d0.x * d0.x + d0.y * d0.y + d0.z * d0.z + d0.w * d0.w
             + d1.x * d1.x + d1.y * d1.y + d1.z * d1.z + d1.w * d1.w;
#pragma unroll
    for (int o = 16; o > 0; o >>= 1) sq += __shfl_xor_sync(0xffffffffu, sq, o);
    float var = sq * (1.f / 255.f);
    float r = 1.f / (sqrtf(var) + 1e-6f);

    const float4* g4 = (const float4*)g;
    const float4* b4 = (const float4*)b;
    float4 gg0 = g4[lane], gg1 = g4[lane + 32];
    float4 bb0 = b4[lane], bb1 = b4[lane + 32];

    float4 o0, o1;
    o0.x = tfv(gg0.x * d0.x * r + bb0.x); o0.y = tfv(gg0.y * d0.y * r + bb0.y);
    o0.z = tfv(gg0.z * d0.z * r + bb0.z); o0.w = tfv(gg0.w * d0.w * r + bb0.w);
    o1.x = tfv(gg1.x * d1.x * r + bb1.x); o1.y = tfv(gg1.y * d1.y * r + bb1.y);
    o1.z = tfv(gg1.z * d1.z * r + bb1.z); o1.w = tfv(gg1.w * d1.w * r + bb1.w);

    float4* yr = (float4*)(y + (size_t)row * 256);
    yr[lane] = o0;
    yr[lane + 32] = o1;
}

// ---------------------------------------------------------------------------
// Tensor-core flash attention (unchanged).
// ---------------------------------------------------------------------------
__global__ __launch_bounds__(256, 2) void attn_tc(
    const float* __restrict__ Q, const float* __restrict__ K,
    const float* __restrict__ V, const float* __restrict__ mask,
    float* __restrict__ O)
{
    extern __shared__ unsigned smu[];
    unsigned* Ks = smu;                        // [128][44]
    unsigned* Vs = smu + 128 * 44;             // [128][40]
    unsigned* Ps = smu + 128 * 44 + 128 * 40;  // [128][132]

    const int qt = blockIdx.x;
    const int bh = blockIdx.y;
    const int b = bh >> 3, h = bh & 7;
    const int tid = threadIdx.x;
    const int w = tid >> 5, lane = tid & 31;
    const int gid = lane >> 2, tg = lane & 3;

    const int r0 = w * 16 + gid;
    const int r1 = r0 + 8;
    const size_t qbase = ((size_t)(b * 512 + qt * 128)) * 256 + h * 32;
    const float scale = 0.17677669529663689f;

    unsigned aQ[4][4];
#pragma unroll
    for (int ks = 0; ks < 4; ks++) {
        aQ[ks][0] = f2tf(Q[qbase + (size_t)r0 * 256 + ks * 8 + tg] * scale);
        aQ[ks][1] = f2tf(Q[qbase + (size_t)r1 * 256 + ks * 8 + tg] * scale);
        aQ[ks][2] = f2tf(Q[qbase + (size_t)r0 * 256 + ks * 8 + tg + 4] * scale);
        aQ[ks][3] = f2tf(Q[qbase + (size_t)r1 * 256 + ks * 8 + tg + 4] * scale);
    }
    const bool mz0 = (mask[b * 512 + qt * 128 + r0] == 0.f);
    const bool mz1 = (mask[b * 512 + qt * 128 + r1] == 0.f);

    float m0 = -1e30f, m1 = -1e30f, l0 = 0.f, l1 = 0.f;
    float o[4][4];
#pragma unroll
    for (int nt = 0; nt < 4; nt++)
#pragma unroll
        for (int i = 0; i < 4; i++) o[nt][i] = 0.f;

    for (int kc = 0; kc < 4; kc++) {
        __syncthreads();
        const size_t kvbase = ((size_t)(b * 512 + kc * 128)) * 256 + h * 32;
        for (int idx = tid; idx < 1024; idx += 256) {
            int key = idx >> 3, d4 = idx & 7;
            const uint4* ks4 = (const uint4*)(K + kvbase + (size_t)key * 256) + d4;
            const uint4* vs4 = (const uint4*)(V + kvbase + (size_t)key * 256) + d4;
            *(uint4*)(Ks + key * 44 + d4 * 4) = *ks4;
            *(uint4*)(Vs + key * 40 + d4 * 4) = *vs4;
        }
        __syncthreads();

        float s[16][4];
#pragma unroll
        for (int nt = 0; nt < 16; nt++) {
            s[nt][0] = s[nt][1] = s[nt][2] = s[nt][3] = 0.f;
            const unsigned* kp = Ks + (nt * 8 + gid) * 44;
#pragma unroll
            for (int ks = 0; ks < 4; ks++) {
                unsigned bk[2] = { kp[ks * 8 + tg], kp[ks * 8 + tg + 4] };
                mma_tf32(s[nt], aQ[ks], bk);
            }
        }
        if (mz0) {
#pragma unroll
            for (int nt = 0; nt < 16; nt++) { s[nt][0] = -1e9f; s[nt][1] = -1e9f; }
        }
        if (mz1) {
#pragma unroll
            for (int nt = 0; nt < 16; nt++) { s[nt][2] = -1e9f; s[nt][3] = -1e9f; }
        }

        float rm0 = -1e30f, rm1 = -1e30f;
#pragma unroll
        for (int nt = 0; nt < 16; nt++) {
            rm0 = fmaxf(rm0, fmaxf(s[nt][0], s[nt][1]));
            rm1 = fmaxf(rm1, fmaxf(s[nt][2], s[nt][3]));
        }
        rm0 = fmaxf(rm0, __shfl_xor_sync(0xffffffffu, rm0, 1));
        rm0 = fmaxf(rm0, __shfl_xor_sync(0xffffffffu, rm0, 2));
        rm1 = fmaxf(rm1, __shfl_xor_sync(0xffffffffu, rm1, 1));
        rm1 = fmaxf(rm1, __shfl_xor_sync(0xffffffffu, rm1, 2));
        float mn0 = fmaxf(m0, rm0), mn1 = fmaxf(m1, rm1);
        float c0 = __expf(m0 - mn0), c1 = __expf(m1 - mn1);
        m0 = mn0; m1 = mn1;

        float ps0 = 0.f, ps1 = 0.f;
        unsigned* pr0 = Ps + r0 * 132;
        unsigned* pr1 = Ps + r1 * 132;
#pragma unroll
        for (int nt = 0; nt < 16; nt++) {
            float p00 = __expf(s[nt][0] - mn0), p01 = __expf(s[nt][1] - mn0);
            float p10 = __expf(s[nt][2] - mn1), p11 = __expf(s[nt][3] - mn1);
            ps0 += p00 + p01;
            ps1 += p10 + p11;
            int cc = nt * 8 + 2 * tg;
            pr0[cc] = f2tf(p00); pr0[cc + 1] = f2tf(p01);
            pr1[cc] = f2tf(p10); pr1[cc + 1] = f2tf(p11);
        }
        ps0 += __shfl_xor_sync(0xffffffffu, ps0, 1);
        ps0 += __shfl_xor_sync(0xffffffffu, ps0, 2);
        ps1 += __shfl_xor_sync(0xffffffffu, ps1, 1);
        ps1 += __shfl_xor_sync(0xffffffffu, ps1, 2);
        l0 = l0 * c0 + ps0;
        l1 = l1 * c1 + ps1;
#pragma unroll
        for (int nt = 0; nt < 4; nt++) {
            o[nt][0] *= c0; o[nt][1] *= c0;
            o[nt][2] *= c1; o[nt][3] *= c1;
        }
        __syncwarp();

#pragma unroll
        for (int ks = 0; ks < 16; ks++) {
            unsigned aP[4] = { pr0[ks * 8 + tg], pr1[ks * 8 + tg],
                               pr0[ks * 8 + tg + 4], pr1[ks * 8 + tg + 4] };
#pragma unroll
            for (int nt = 0; nt < 4; nt++) {
                const unsigned* vp = Vs + nt * 8 + gid;
                unsigned bv[2] = { vp[(ks * 8 + tg) * 40], vp[(ks * 8 + tg + 4) * 40] };
                mma_tf32(o[nt], aP, bv);
            }
        }
    }

    float inv0 = 1.f / l0, inv1 = 1.f / l1;
    float* Or0 = O + qbase + (size_t)r0 * 256;
    float* Or1 = O + qbase + (size_t)r1 * 256;
#pragma unroll
    for (int nt = 0; nt < 4; nt++) {
        int cc = nt * 8 + 2 * tg;
        Or0[cc]     = tfv(o[nt][0] * inv0);
        Or0[cc + 1] = tfv(o[nt][1] * inv0);
        Or1[cc]     = tfv(o[nt][2] * inv1);
        Or1[cc + 1] = tfv(o[nt][3] * inv1);
    }
}

// ---------------------------------------------------------------------------
// Weight/input pre-conversion to tf32-rounded fp32 values (unchanged)
// ---------------------------------------------------------------------------
__global__ __launch_bounds__(256) void cvtw_k(
    const float* __restrict__ inputs, const float* __restrict__ emb,
    const float* __restrict__ qkvo, const float* __restrict__ f1,
    const float* __restrict__ f2, float* __restrict__ inT,
    float* __restrict__ wtf)
{
    int idx = blockIdx.x * 256 + threadIdx.x;
    if (idx < 4915200) inT[idx] = tfv(inputs[idx]);
    if (idx < 2042880) {
        float v;
        if (idx < OFF_QKVO)      v = emb[idx - OFF_EMB];
        else if (idx < OFF_FF1)  v = qkvo[idx - OFF_QKVO];
        else if (idx < OFF_FF2)  v = f1[idx - OFF_FF1];
        else                     v = f2[idx - OFF_FF2];
        wtf[idx] = tfv(v);
    }
}

// ---------------------------------------------------------------------------
// LSTM prep: WmR layout now [gb(128)][sub(8)][k(256)],
//   sub = (el<<2)|g,  col = g*256 + gb*2 + el
// ---------------------------------------------------------------------------
__global__ __launch_bounds__(256) void lstm_prep_k(
    const float* __restrict__ wih, const float* __restrict__ whh,
    const float* __restrict__ bih, const float* __restrict__ bhh,
    const float* __restrict__ dec_h0, const float* __restrict__ out_w1,
    float* __restrict__ WihEncT, float* __restrict__ WmR,
    float* __restrict__ w1t, float* __restrict__ g0,
    float* __restrict__ biasTot, unsigned* __restrict__ sync)
{
    int idx = blockIdx.x * 256 + threadIdx.x;
    if (idx == 0) *sync = 0u;
    if (idx < 262144) {
        int k = idx >> 10, n = idx & 1023;
        WihEncT[idx] = tfv(wih[(size_t)n * 512 + 256 + k]);

        int gb = idx >> 11;          // 0..127
        int r = idx & 2047;
        int sub = r >> 8;            // 0..7
        int kk = r & 255;
        int g = sub & 3, el = sub >> 2;
        int col = g * 256 + gb * 2 + el;
        WmR[idx] = wih[(size_t)col * 512 + kk] + whh[(size_t)col * 256 + kk];
    }
    if (idx < 32768) {
        int h = idx >> 8, k = idx & 255;
        w1t[idx] = out_w1[(size_t)k * 128 + h];
    }
    if (idx < 1024) {
        float a = 0.f;
        for (int k = 0; k < 256; k++) a = fmaf(dec_h0[k], whh[(size_t)idx * 256 + k], a);
        g0[idx] = a;
        biasTot[idx] = bih[idx] + bhh[idx];
    }
}

// ---------------------------------------------------------------------------
// Persistent LSTM: 144 blocks (128 gate + 16 MLP), all co-resident (1/SM).
// Gate block gb owns e in {2gb, 2gb+1}. Thread (b = tid>>3, sub = tid&7)
// computes one full 256-length gate dot; gates gathered via intra-warp shfl.
// MLP block handles 2 batches. Grid barrier on g_sync (NBLK=144).
// ---------------------------------------------------------------------------
__device__ __forceinline__ float sigf(float x) { return 1.f / (1.f + __expf(-x)); }

__device__ __forceinline__ void grid_bar(unsigned* sync, unsigned target) {
    __threadfence();
    __syncthreads();
    if (threadIdx.x == 0) {
        atomicAdd(sync, 1u);
        while (*(volatile unsigned*)sync < target) { }
        __threadfence();
    }
    __syncthreads();
}

__global__ __launch_bounds__(256, 1) void lstm_persist_k(
    const float* __restrict__ pre, const float* __restrict__ WmR,
    const float* __restrict__ w1t, const float* __restrict__ g0,
    const float* __restrict__ dec_c0,
    const float* __restrict__ b1, const float* __restrict__ w2,
    const float* __restrict__ b2, const float* __restrict__ mask,
    float* __restrict__ hbuf, unsigned* __restrict__ sync,
    float* __restrict__ out)
{
    extern __shared__ float sm[];
    const int tid = threadIdx.x;
    const unsigned NBLK = 144;

    if (blockIdx.x < 128) {
        // -------- gate block: 2 e-cols, one full dot per thread --------
        const int gb = blockIdx.x;
        const int b = tid >> 3;          // batch 0..31
        const int sub = tid & 7;         // (el<<2)|g
        const int g = sub & 3;
        const int el = sub >> 2;
        const int e = gb * 2 + el;
        const int col = g * 256 + e;
        const int lane = tid & 31;
        const int base = lane & ~3;      // lane of g==0 in this quad

        float* ws = sm;                       // [8][260] floats (padded)
        float4* hs4 = (float4*)(sm + 2080);   // [32][64] float4 (unpadded)

        // stage weights once (rows padded to 260 floats: conflict-free LDS.128)
        for (int i = tid; i < 2048; i += 256) {
            int ss = i >> 8, kk = i & 255;
            ws[ss * 260 + kk] = WmR[(size_t)gb * 2048 + i];
        }
        const float4* wp = (const float4*)(ws + sub * 260);

        float c = (g == 0) ? dec_c0[e] : 0.f;

        for (int t = 0; t < 512; ++t) {
            float gate;
            if (t == 0) {
                gate = pre[(size_t)b * 524288 + col] + g0[col];
            } else {
                // prefetch pre (off critical path)
                float prv = __ldg(pre + ((size_t)b * 512 + t) * 1024 + col);

                // stage h_t (32x256 floats) into smem
                const float4* hsrc = (const float4*)(hbuf + (t & 1) * 8192);
                for (int j = tid; j < 2048; j += 256) hs4[j] = __ldcg(hsrc + j);
                __syncthreads();

                const float4* hp = hs4 + b * 64;
                float a0 = 0.f, a1 = 0.f, a2 = 0.f, a3 = 0.f;
#pragma unroll 8
                for (int kk = 0; kk < 64; kk += 4) {
                    float4 h0 = hp[kk],     w0 = wp[kk];
                    float4 h1 = hp[kk + 1], w1v = wp[kk + 1];
                    float4 h2 = hp[kk + 2], w2v = wp[kk + 2];
                    float4 h3 = hp[kk + 3], w3v = wp[kk + 3];
                    a0 = fmaf(h0.x, w0.x, fmaf(h0.y, w0.y, fmaf(h0.z, w0.z, fmaf(h0.w, w0.w, a0))));
                    a1 = fmaf(h1.x, w1v.x, fmaf(h1.y, w1v.y, fmaf(h1.z, w1v.z, fmaf(h1.w, w1v.w, a1))));
                    a2 = fmaf(h2.x, w2v.x, fmaf(h2.y, w2v.y, fmaf(h2.z, w2v.z, fmaf(h2.w, w2v.w, a2))));
                    a3 = fmaf(h3.x, w3v.x, fmaf(h3.y, w3v.y, fmaf(h3.z, w3v.z, fmaf(h3.w, w3v.w, a3))));
                }
                gate = (a0 + a1) + (a2 + a3) + prv;
                __syncthreads();   // dot reads done before next staging
            }

            // gather 4 gates within the quad (lane&3 == g)
            float gi = __shfl_sync(0xffffffffu, gate, base + 0);
            float gf = __shfl_sync(0xffffffffu, gate, base + 1);
            float gg = __shfl_sync(0xffffffffu, gate, base + 2);
            float go = __shfl_sync(0xffffffffu, gate, base + 3);
            if (g == 0) {
                float cn = sigf(gf) * c + sigf(gi) * tanhf(gg);
                float hn = sigf(go) * tanhf(cn);
                c = cn;
                __stcg(hbuf + ((t + 1) & 1) * 8192 + b * 256 + e, hn);
            }
            grid_bar(sync, (unsigned)(t + 1) * NBLK);
        }
    } else {
        // -------- MLP block: 2 batches, lagged output head --------
        const int mb = blockIdx.x - 128;
        const int bat = tid >> 7;        // 0/1 within block
        const int ho = tid & 127;
        float* w1s  = sm;                // [128][260] floats
        float* hrow = sm + 33280;        // [2][256]
        float* red  = sm + 33792;        // [8]

        for (int i = tid; i < 8192; i += 256) {
            int h = i >> 6, k4 = i & 63;
            ((float4*)w1s)[h * 65 + k4] = ((const float4*)w1t)[i];
        }
        float w2v = w2[ho];
        float b1v = b1[ho];
        float b2v = b2[0];

        for (int t = 0; t <= 512; ++t) {
            if (t >= 1) {
                // stage 2 h rows
                for (int i = tid; i < 512; i += 256) {
                    int bb = i >> 8, k = i & 255;
                    hrow[bb * 256 + k] =
                        __ldcg(hbuf + (t & 1) * 8192 + (mb * 2 + bb) * 256 + k);
                }
                __syncthreads();

                float a = b1v;
                const float4* h4 = (const float4*)(hrow + bat * 256);
                const float4* w4 = (const float4*)(w1s + ho * 260);
#pragma unroll 16
                for (int kk = 0; kk < 64; kk++) {
                    float4 hv = h4[kk];
                    float4 wv = w4[kk];
                    a = fmaf(hv.x, wv.x, fmaf(hv.y, wv.y, fmaf(hv.z, wv.z, fmaf(hv.w, wv.w, a))));
                }
                float contrib = fmaxf(a, 0.f) * w2v;
#pragma unroll
                for (int o = 16; o > 0; o >>= 1)
                    contrib += __shfl_down_sync(0xffffffffu, contrib, o);
                if ((tid & 31) == 0) red[tid >> 5] = contrib;
                __syncthreads();
                if (tid == 0) {
                    int bidx = mb * 2;
                    float pp = red[0] + red[1] + red[2] + red[3] + b2v;
                    out[bidx * 512 + (t - 1)] = pp * mask[bidx * 512 + (t - 1)];
                }
                if (tid == 128) {
                    int bidx = mb * 2 + 1;
                    float pp = red[4] + red[5] + red[6] + red[7] + b2v;
                    out[bidx * 512 + (t - 1)] = pp * mask[bidx * 512 + (t - 1)];
                }
                __syncthreads();
            }
            if (t < 512) grid_bar(sync, (unsigned)(t + 1) * NBLK);
        }
    }
}

// ---------------------------------------------------------------------------
// Launcher
// ---------------------------------------------------------------------------
extern "C" void kernel_launch(void* const* d_in, const int* in_sizes, int n_in,
                              void* d_out, int out_size)
{
    const float* inputs   = (const float*)d_in[0];
    const float* mask     = (const float*)d_in[1];
    /* d_in[2] = lengths (unused) */
    const float* embed_w  = (const float*)d_in[3];
    const float* embed_b  = (const float*)d_in[4];
    const float* qkvo_w   = (const float*)d_in[5];
    const float* qkvo_b   = (const float*)d_in[6];
    const float* ln_g     = (const float*)d_in[7];
    const float* ln_b     = (const float*)d_in[8];
    const float* ff_w1    = (const float*)d_in[9];
    const float* ff_b1    = (const float*)d_in[10];
    const float* ff_w2    = (const float*)d_in[11];
    const float* ff_b2    = (const float*)d_in[12];
    const float* enc_ln_g = (const float*)d_in[13];
    const float* enc_ln_b = (const float*)d_in[14];
    const float* wih      = (const float*)d_in[15];
    const float* whh      = (const float*)d_in[16];
    const float* bih      = (const float*)d_in[17];
    const float* bhh      = (const float*)d_in[18];
    const float* dec_h0   = (const float*)d_in[19];
    const float* dec_c0   = (const float*)d_in[20];
    const float* out_w1   = (const float*)d_in[21];
    const float* out_b1   = (const float*)d_in[22];
    const float* out_w2   = (const float*)d_in[23];
    const float* out_b2   = (const float*)d_in[24];
    float* out = (float*)d_out;
    (void)in_sizes; (void)n_in; (void)out_size;

    float *px, *py, *pqkv, *po, *ph1, *ppre, *pinT, *pwtf, *pWET, *pWmR, *pw1t,
          *pg0, *pbt, *phb;
    unsigned* psync;
    cudaGetSymbolAddress((void**)&px,    g_x);
    cudaGetSymbolAddress((void**)&py,    g_y);
    cudaGetSymbolAddress((void**)&pqkv,  g_qkv);
    cudaGetSymbolAddress((void**)&po,    g_o);
    cudaGetSymbolAddress((void**)&ph1,   g_h1);
    cudaGetSymbolAddress((void**)&ppre,  g_pre);
    cudaGetSymbolAddress((void**)&pinT,  g_inT);
    cudaGetSymbolAddress((void**)&pwtf,  g_wtf);
    cudaGetSymbolAddress((void**)&pWET,  g_WihEncT);
    cudaGetSymbolAddress((void**)&pWmR,  g_WmR);
    cudaGetSymbolAddress((void**)&pw1t,  g_w1t);
    cudaGetSymbolAddress((void**)&pg0,   g_g0);
    cudaGetSymbolAddress((void**)&pbt,   g_biasTot);
    cudaGetSymbolAddress((void**)&phb,   g_hbuf);
    cudaGetSymbolAddress((void**)&psync, g_sync);

    cudaFuncSetAttribute(gemm_tc, cudaFuncAttributeMaxDynamicSharedMemorySize, GEMM_SMEM);
    cudaFuncSetAttribute(attn_tc, cudaFuncAttributeMaxDynamicSharedMemorySize, 110592);
    cudaFuncSetAttribute(lstm_persist_k, cudaFuncAttributeMaxDynamicSharedMemorySize, 137216);

    const int M = 16384;
    const long QKV_C = 16384L * 256;

    // prep: tf32 conversions + LSTM weights + barrier reset
    cvtw_k<<<19200, 256>>>(inputs, embed_w, qkvo_w, ff_w1, ff_w2, pinT, pwtf);
    lstm_prep_k<<<1024, 256>>>(wih, whh, bih, bhh, dec_h0, out_w1,
                               pWET, pWmR, pw1t, pg0, pbt, psync);

    // Embed (K=300)
    gemm_tc<<<dim3(2, 128), 256, GEMM_SMEM>>>(pinT, pwtf + OFF_EMB, embed_b,
                                              nullptr, px,
                                              M, 256, 300, 0, 0, 2, 0, 0, 0);

    // Transformer layers
    for (int l = 0; l < 6; l++) {
        const float* Wq = pwtf + OFF_QKVO + (size_t)(l * 4) * 65536;
        const float* Wo = pwtf + OFF_QKVO + (size_t)(l * 4 + 3) * 65536;
        const float* bq = qkvo_b + (l * 4) * 256;
        const float* bo = qkvo_b + (l * 4 + 3) * 256;

        layernorm_k<<<2048, 256>>>(px, ln_g + l * 512, ln_b + l * 512, py);
        gemm_tc<<<dim3(6, 128), 256, GEMM_SMEM>>>(py, Wq, bq, nullptr, pqkv,
                                                  M, 256, 256, 0, 1,
                                                  2, 65536, QKV_C, 256);
        attn_tc<<<dim3(4, 256), 256, 110592>>>(pqkv, pqkv + QKV_C,
                                               pqkv + 2 * QKV_C, mask, po);
        gemm_tc<<<dim3(2, 128), 256, GEMM_SMEM>>>(po, Wo, bo, px, px,
                                                  M, 256, 256, 0, 0, 2, 0, 0, 0);

        layernorm_k<<<2048, 256>>>(px, ln_g + l * 512 + 256, ln_b + l * 512 + 256, py);
        gemm_tc<<<dim3(1, 128), 256, GEMM_SMEM>>>(py, pwtf + OFF_FF1 + (size_t)l * 32768,
                                                  ff_b1 + l * 128, nullptr, ph1,
                                                  M, 128, 256, 1, 1, 1, 0, 0, 0);
        gemm_tc<<<dim3(2, 128), 256, GEMM_SMEM>>>(ph1, pwtf + OFF_FF2 + (size_t)l * 32768,
                                                  ff_b2 + l * 256, px, px,
                                                  M, 256, 128, 0, 0, 2, 0, 0, 0);
    }

    // Encoder LN -> enc (in py, tf32-rounded)
    layernorm_k<<<2048, 256>>>(px, enc_ln_g, enc_ln_b, py);

    // pre = enc @ wih[:,256:].T + (bih+bhh)
    gemm_tc<<<dim3(8, 128), 256, GEMM_SMEM>>>(py, pWET, pbt, nullptr, ppre,
                                              M, 1024, 256, 0, 0, 8, 0, 0, 0);

    // Persistent LSTM scan + output head (single launch, 144 blocks)
    lstm_persist_k<<<144, 256, 137216>>>(ppre, pWmR, pw1t, pg0, dec_c0,
                                         out_b1, out_w2, out_b2, mask,
                                         phb, psync, out);
}

// round 10
// speedup vs baseline: 2.6636x; 1.0696x over previous
#include <cuda_runtime.h>
#include <cuda_bf16.h>
#include <math.h>

// ---------------------------------------------------------------------------
// Scratch (device globals — allocation-free per harness rules)
// ---------------------------------------------------------------------------
__device__ float g_x   [16384 * 256];
__device__ float g_y   [16384 * 256];
__device__ float g_qkv [3 * 16384 * 256];
__device__ float g_o   [16384 * 256];
__device__ float g_h1  [16384 * 128];
__device__ float g_pre [16384 * 1024];
__device__ float g_inT [16384 * 300];     // tf32-rounded inputs
__device__ float g_wtf [2042880];         // tf32-rounded weights (emb|qkvo|ff1|ff2)
__device__ float g_WihEncT[256 * 1024];   // (wih[:,256:512]).T, tf32-rounded
__device__ float g_WmR [128 * 2048];      // merged (wih[:,:256]+whh).T, [gb][sub][k]
__device__ float g_w1t [128 * 256];       // out_w1 transposed [h][k]
__device__ float g_g0  [1024];            // dec_h0 @ whh.T
__device__ float g_biasTot[1024];         // bih + bhh
__device__ float g_hbuf[2 * 32 * 256];
__device__ unsigned g_sync;               // grid barrier counter (zeroed in prep)

#define OFF_EMB  0
#define OFF_QKVO 76800
#define OFF_FF1  1649664
#define OFF_FF2  1846272

// ---------------------------------------------------------------------------
// tf32 / mma helpers
// ---------------------------------------------------------------------------
__device__ __forceinline__ unsigned f2tf(float f) {
    unsigned u;
    asm("cvt.rna.tf32.f32 %0, %1;" : "=r"(u) : "f"(f));
    return u;
}
__device__ __forceinline__ float tfv(float f) { return __uint_as_float(f2tf(f)); }

__device__ __forceinline__ void mma_tf32(float (&d)[4], const unsigned (&a)[4],
                                         const unsigned (&b)[2]) {
    asm volatile(
        "mma.sync.aligned.m16n8k8.row.col.f32.tf32.tf32.f32 "
        "{%0,%1,%2,%3}, {%4,%5,%6,%7}, {%8,%9}, {%0,%1,%2,%3};"
        : "+f"(d[0]), "+f"(d[1]), "+f"(d[2]), "+f"(d[3])
        : "r"(a[0]), "r"(a[1]), "r"(a[2]), "r"(a[3]), "r"(b[0]), "r"(b[1]));
}

__device__ __forceinline__ void cp16(unsigned dst, const void* src, int bytes) {
    asm volatile("cp.async.cg.shared.global [%0], [%1], 16, %2;"
                 :: "r"(dst), "l"(src), "r"(bytes));
}
__device__ __forceinline__ void cp_commit() {
    asm volatile("cp.async.commit_group;" ::: "memory");
}

// ---------------------------------------------------------------------------
// tf32 tensor-core GEMM (unchanged / passing).
// ---------------------------------------------------------------------------
#define GEMM_SMEM (3 * 128 * 20 * 4 + 3 * 16 * 136 * 4)

__global__ __launch_bounds__(256, 2) void gemm_tc(
    const float* __restrict__ A, const float* __restrict__ B,
    const float* __restrict__ bias, const float* __restrict__ res,
    float* __restrict__ C, int M, int N, int K, int relu, int outCvt,
    int nxPerMat, long bMatStride, long cMatStride, int biasMatStride)
{
    extern __shared__ unsigned dynsm[];
    unsigned (*As)[128][20] = (unsigned (*)[128][20])dynsm;
    unsigned (*Bs)[16][136] = (unsigned (*)[16][136])(dynsm + 3 * 128 * 20);

    const int tid = threadIdx.x;
    const int bx = blockIdx.x, by = blockIdx.y;
    const int mat = bx / nxPerMat;
    const int bxn = bx - mat * nxPerMat;

    const float* Bp    = B + (size_t)mat * bMatStride;
    const float* biasP = bias + (size_t)mat * biasMatStride;
    float*       Cp    = C + (size_t)mat * cMatStride;

    const float* Ablk = A + (size_t)(by * 128) * K;
    const float* Bblk = Bp + bxn * 128;

    const int lane = tid & 31, wid = tid >> 5;
    const int wm = wid >> 2, wn = wid & 3;
    const int gid = lane >> 2, tg = lane & 3;

    const int ar0 = tid >> 2, ac0 = (tid & 3) << 2;
    const int ar1 = ar0 + 64;
    const int bk0 = tid >> 5, bc0 = (tid & 31) << 2;
    const int bk1 = bk0 + 8;

    const unsigned sA = (unsigned)__cvta_generic_to_shared(&dynsm[0]);
    const unsigned sB = (unsigned)__cvta_generic_to_shared(&dynsm[3 * 128 * 20]);

    float acc[4][4][4];
#pragma unroll
    for (int mt = 0; mt < 4; mt++)
#pragma unroll
        for (int nt = 0; nt < 4; nt++)
#pragma unroll
            for (int i = 0; i < 4; i++) acc[mt][nt][i] = 0.f;

    auto issue = [&](int buf, int k0) {
        int c0 = k0 + ac0;
        int rem0 = K - c0;
        int by0 = rem0 >= 4 ? 16 : (rem0 > 0 ? rem0 * 4 : 0);
        cp16(sA + ((buf * 128 + ar0) * 20 + ac0) * 4,
             Ablk + (size_t)ar0 * K + (by0 ? c0 : 0), by0);
        cp16(sA + ((buf * 128 + ar1) * 20 + ac0) * 4,
             Ablk + (size_t)ar1 * K + (by0 ? c0 : 0), by0);
        int kr0 = k0 + bk0;
        int bb0 = (kr0 < K) ? 16 : 0;
        cp16(sB + ((buf * 16 + bk0) * 136 + bc0) * 4,
             Bblk + (size_t)(bb0 ? kr0 : 0) * N + bc0, bb0);
        int kr1 = k0 + bk1;
        int bb1 = (kr1 < K) ? 16 : 0;
        cp16(sB + ((buf * 16 + bk1) * 136 + bc0) * 4,
             Bblk + (size_t)(bb1 ? kr1 : 0) * N + bc0, bb1);
        cp_commit();
    };

    issue(0, 0);
    if (16 < K) issue(1, 16);

    int cur = 0;
    for (int k0 = 0; k0 < K; k0 += 16) {
        if (k0 + 16 < K) {
            asm volatile("cp.async.wait_group 1;" ::: "memory");
        } else {
            asm volatile("cp.async.wait_group 0;" ::: "memory");
        }
        __syncthreads();
        if (k0 + 32 < K) {
            int nb = cur + 2; if (nb >= 3) nb -= 3;
            issue(nb, k0 + 32);
        }

#pragma unroll
        for (int ks = 0; ks < 16; ks += 8) {
            unsigned a[4][4], b[4][2];
#pragma unroll
            for (int mt = 0; mt < 4; mt++) {
                int r = wm * 64 + mt * 16 + gid;
                a[mt][0] = As[cur][r][ks + tg];
                a[mt][1] = As[cur][r + 8][ks + tg];
                a[mt][2] = As[cur][r][ks + tg + 4];
                a[mt][3] = As[cur][r + 8][ks + tg + 4];
            }
#pragma unroll
            for (int nt = 0; nt < 4; nt++) {
                int cb = wn * 32 + nt * 8 + gid;
                b[nt][0] = Bs[cur][ks + tg][cb];
                b[nt][1] = Bs[cur][ks + tg + 4][cb];
            }
#pragma unroll
            for (int mt = 0; mt < 4; mt++)
#pragma unroll
                for (int nt = 0; nt < 4; nt++)
                    mma_tf32(acc[mt][nt], a[mt], b[nt]);
        }
        __syncthreads();
        cur = cur + 1; if (cur >= 3) cur -= 3;
    }

#pragma unroll
    for (int mt = 0; mt < 4; mt++) {
        int r0 = by * 128 + wm * 64 + mt * 16 + gid;
#pragma unroll
        for (int nt = 0; nt < 4; nt++) {
            int c0 = bxn * 128 + wn * 32 + nt * 8 + tg * 2;
            float bza = biasP[c0], bzb = biasP[c0 + 1];
            size_t off0 = (size_t)r0 * N + c0;
            size_t off1 = (size_t)(r0 + 8) * N + c0;
            float v0 = acc[mt][nt][0] + bza, v1 = acc[mt][nt][1] + bzb;
            float v2 = acc[mt][nt][2] + bza, v3 = acc[mt][nt][3] + bzb;
            if (res) {
                v0 += res[off0]; v1 += res[off0 + 1];
                v2 += res[off1]; v3 += res[off1 + 1];
            }
            if (relu) {
                v0 = fmaxf(v0, 0.f); v1 = fmaxf(v1, 0.f);
                v2 = fmaxf(v2, 0.f); v3 = fmaxf(v3, 0.f);
            }
            if (outCvt) {
                v0 = tfv(v0); v1 = tfv(v1); v2 = tfv(v2); v3 = tfv(v3);
            }
            *(float2*)(Cp + off0) = make_float2(v0, v1);
            *(float2*)(Cp + off1) = make_float2(v2, v3);
        }
    }
}

// ---------------------------------------------------------------------------
// LayerNorm (unchanged).
// ---------------------------------------------------------------------------
__global__ __launch_bounds__(256) void layernorm_k(
    const float* __restrict__ x, const float* __restrict__ g,
    const float* __restrict__ b, float* __restrict__ y)
{
    int tid = threadIdx.x;
    int lane = tid & 31;
    int row = blockIdx.x * 8 + (tid >> 5);

    const float4* xr = (const float4*)(x + (size_t)row * 256);
    float4 v0 = xr[lane], v1 = xr[lane + 32];

    float s = v0.x + v0.y + v0.z + v0.w + v1.x + v1.y + v1.z + v1.w;
#pragma unroll
    for (int o = 16; o > 0; o >>= 1) s += __shfl_xor_sync(0xffffffffu, s, o);
    float mean = s * (1.f / 256.f);

    float4 d0 = make_float4(v0.x - mean, v0.y - mean, v0.z - mean, v0.w - mean);
    float4 d1 = make_float4(v1.x - mean, v1.y - mean, v1.z - mean, v1.w - mean);
    float sq = d0.x * d0.x + d0.y * d0.y + d0.z * d0.z + d0.w * d0.w
             + d1.x * d1.x + d1.y * d1.y + d1.z * d1.z + d1.w * d1.w;
#pragma unroll
    for (int o = 16; o > 0; o >>= 1) sq += __shfl_xor_sync(0xffffffffu, sq, o);
    float var = sq * (1.f / 255.f);
    float r = 1.f / (sqrtf(var) + 1e-6f);

    const float4* g4 = (const float4*)g;
    const float4* b4 = (const float4*)b;
    float4 gg0 = g4[lane], gg1 = g4[lane + 32];
    float4 bb0 = b4[lane], bb1 = b4[lane + 32];

    float4 o0, o1;
    o0.x = tfv(gg0.x * d0.x * r + bb0.x); o0.y = tfv(gg0.y * d0.y * r + bb0.y);
    o0.z = tfv(gg0.z * d0.z * r + bb0.z); o0.w = tfv(gg0.w * d0.w * r + bb0.w);
    o1.x = tfv(gg1.x * d1.x * r + bb1.x); o1.y = tfv(gg1.y * d1.y * r + bb1.y);
    o1.z = tfv(gg1.z * d1.z * r + bb1.z); o1.w = tfv(gg1.w * d1.w * r + bb1.w);

    float4* yr = (float4*)(y + (size_t)row * 256);
    yr[lane] = o0;
    yr[lane + 32] = o1;
}

// ---------------------------------------------------------------------------
// Tensor-core flash attention (unchanged).
// ---------------------------------------------------------------------------
__global__ __launch_bounds__(256, 2) void attn_tc(
    const float* __restrict__ Q, const float* __restrict__ K,
    const float* __restrict__ V, const float* __restrict__ mask,
    float* __restrict__ O)
{
    extern __shared__ unsigned smu[];
    unsigned* Ks = smu;                        // [128][44]
    unsigned* Vs = smu + 128 * 44;             // [128][40]
    unsigned* Ps = smu + 128 * 44 + 128 * 40;  // [128][132]

    const int qt = blockIdx.x;
    const int bh = blockIdx.y;
    const int b = bh >> 3, h = bh & 7;
    const int tid = threadIdx.x;
    const int w = tid >> 5, lane = tid & 31;
    const int gid = lane >> 2, tg = lane & 3;

    const int r0 = w * 16 + gid;
    const int r1 = r0 + 8;
    const size_t qbase = ((size_t)(b * 512 + qt * 128)) * 256 + h * 32;
    const float scale = 0.17677669529663689f;

    unsigned aQ[4][4];
#pragma unroll
    for (int ks = 0; ks < 4; ks++) {
        aQ[ks][0] = f2tf(Q[qbase + (size_t)r0 * 256 + ks * 8 + tg] * scale);
        aQ[ks][1] = f2tf(Q[qbase + (size_t)r1 * 256 + ks * 8 + tg] * scale);
        aQ[ks][2] = f2tf(Q[qbase + (size_t)r0 * 256 + ks * 8 + tg + 4] * scale);
        aQ[ks][3] = f2tf(Q[qbase + (size_t)r1 * 256 + ks * 8 + tg + 4] * scale);
    }
    const bool mz0 = (mask[b * 512 + qt * 128 + r0] == 0.f);
    const bool mz1 = (mask[b * 512 + qt * 128 + r1] == 0.f);

    float m0 = -1e30f, m1 = -1e30f, l0 = 0.f, l1 = 0.f;
    float o[4][4];
#pragma unroll
    for (int nt = 0; nt < 4; nt++)
#pragma unroll
        for (int i = 0; i < 4; i++) o[nt][i] = 0.f;

    for (int kc = 0; kc < 4; kc++) {
        __syncthreads();
        const size_t kvbase = ((size_t)(b * 512 + kc * 128)) * 256 + h * 32;
        for (int idx = tid; idx < 1024; idx += 256) {
            int key = idx >> 3, d4 = idx & 7;
            const uint4* ks4 = (const uint4*)(K + kvbase + (size_t)key * 256) + d4;
            const uint4* vs4 = (const uint4*)(V + kvbase + (size_t)key * 256) + d4;
            *(uint4*)(Ks + key * 44 + d4 * 4) = *ks4;
            *(uint4*)(Vs + key * 40 + d4 * 4) = *vs4;
        }
        __syncthreads();

        float s[16][4];
#pragma unroll
        for (int nt = 0; nt < 16; nt++) {
            s[nt][0] = s[nt][1] = s[nt][2] = s[nt][3] = 0.f;
            const unsigned* kp = Ks + (nt * 8 + gid) * 44;
#pragma unroll
            for (int ks = 0; ks < 4; ks++) {
                unsigned bk[2] = { kp[ks * 8 + tg], kp[ks * 8 + tg + 4] };
                mma_tf32(s[nt], aQ[ks], bk);
            }
        }
        if (mz0) {
#pragma unroll
            for (int nt = 0; nt < 16; nt++) { s[nt][0] = -1e9f; s[nt][1] = -1e9f; }
        }
        if (mz1) {
#pragma unroll
            for (int nt = 0; nt < 16; nt++) { s[nt][2] = -1e9f; s[nt][3] = -1e9f; }
        }

        float rm0 = -1e30f, rm1 = -1e30f;
#pragma unroll
        for (int nt = 0; nt < 16; nt++) {
            rm0 = fmaxf(rm0, fmaxf(s[nt][0], s[nt][1]));
            rm1 = fmaxf(rm1, fmaxf(s[nt][2], s[nt][3]));
        }
        rm0 = fmaxf(rm0, __shfl_xor_sync(0xffffffffu, rm0, 1));
        rm0 = fmaxf(rm0, __shfl_xor_sync(0xffffffffu, rm0, 2));
        rm1 = fmaxf(rm1, __shfl_xor_sync(0xffffffffu, rm1, 1));
        rm1 = fmaxf(rm1, __shfl_xor_sync(0xffffffffu, rm1, 2));
        float mn0 = fmaxf(m0, rm0), mn1 = fmaxf(m1, rm1);
        float c0 = __expf(m0 - mn0), c1 = __expf(m1 - mn1);
        m0 = mn0; m1 = mn1;

        float ps0 = 0.f, ps1 = 0.f;
        unsigned* pr0 = Ps + r0 * 132;
        unsigned* pr1 = Ps + r1 * 132;
#pragma unroll
        for (int nt = 0; nt < 16; nt++) {
            float p00 = __expf(s[nt][0] - mn0), p01 = __expf(s[nt][1] - mn0);
            float p10 = __expf(s[nt][2] - mn1), p11 = __expf(s[nt][3] - mn1);
            ps0 += p00 + p01;
            ps1 += p10 + p11;
            int cc = nt * 8 + 2 * tg;
            pr0[cc] = f2tf(p00); pr0[cc + 1] = f2tf(p01);
            pr1[cc] = f2tf(p10); pr1[cc + 1] = f2tf(p11);
        }
        ps0 += __shfl_xor_sync(0xffffffffu, ps0, 1);
        ps0 += __shfl_xor_sync(0xffffffffu, ps0, 2);
        ps1 += __shfl_xor_sync(0xffffffffu, ps1, 1);
        ps1 += __shfl_xor_sync(0xffffffffu, ps1, 2);
        l0 = l0 * c0 + ps0;
        l1 = l1 * c1 + ps1;
#pragma unroll
        for (int nt = 0; nt < 4; nt++) {
            o[nt][0] *= c0; o[nt][1] *= c0;
            o[nt][2] *= c1; o[nt][3] *= c1;
        }
        __syncwarp();

#pragma unroll
        for (int ks = 0; ks < 16; ks++) {
            unsigned aP[4] = { pr0[ks * 8 + tg], pr1[ks * 8 + tg],
                               pr0[ks * 8 + tg + 4], pr1[ks * 8 + tg + 4] };
#pragma unroll
            for (int nt = 0; nt < 4; nt++) {
                const unsigned* vp = Vs + nt * 8 + gid;
                unsigned bv[2] = { vp[(ks * 8 + tg) * 40], vp[(ks * 8 + tg + 4) * 40] };
                mma_tf32(o[nt], aP, bv);
            }
        }
    }

    float inv0 = 1.f / l0, inv1 = 1.f / l1;
    float* Or0 = O + qbase + (size_t)r0 * 256;
    float* Or1 = O + qbase + (size_t)r1 * 256;
#pragma unroll
    for (int nt = 0; nt < 4; nt++) {
        int cc = nt * 8 + 2 * tg;
        Or0[cc]     = tfv(o[nt][0] * inv0);
        Or0[cc + 1] = tfv(o[nt][1] * inv0);
        Or1[cc]     = tfv(o[nt][2] * inv1);
        Or1[cc + 1] = tfv(o[nt][3] * inv1);
    }
}

// ---------------------------------------------------------------------------
// Weight/input pre-conversion to tf32-rounded fp32 values (unchanged)
// ---------------------------------------------------------------------------
__global__ __launch_bounds__(256) void cvtw_k(
    const float* __restrict__ inputs, const float* __restrict__ emb,
    const float* __restrict__ qkvo, const float* __restrict__ f1,
    const float* __restrict__ f2, float* __restrict__ inT,
    float* __restrict__ wtf)
{
    int idx = blockIdx.x * 256 + threadIdx.x;
    if (idx < 4915200) inT[idx] = tfv(inputs[idx]);
    if (idx < 2042880) {
        float v;
        if (idx < OFF_QKVO)      v = emb[idx - OFF_EMB];
        else if (idx < OFF_FF1)  v = qkvo[idx - OFF_QKVO];
        else if (idx < OFF_FF2)  v = f1[idx - OFF_FF1];
        else                     v = f2[idx - OFF_FF2];
        wtf[idx] = tfv(v);
    }
}

// ---------------------------------------------------------------------------
// LSTM prep (unchanged from R9).
// ---------------------------------------------------------------------------
__global__ __launch_bounds__(256) void lstm_prep_k(
    const float* __restrict__ wih, const float* __restrict__ whh,
    const float* __restrict__ bih, const float* __restrict__ bhh,
    const float* __restrict__ dec_h0, const float* __restrict__ out_w1,
    float* __restrict__ WihEncT, float* __restrict__ WmR,
    float* __restrict__ w1t, float* __restrict__ g0,
    float* __restrict__ biasTot, unsigned* __restrict__ sync)
{
    int idx = blockIdx.x * 256 + threadIdx.x;
    if (idx == 0) *sync = 0u;
    if (idx < 262144) {
        int k = idx >> 10, n = idx & 1023;
        WihEncT[idx] = tfv(wih[(size_t)n * 512 + 256 + k]);

        int gb = idx >> 11;          // 0..127
        int r = idx & 2047;
        int sub = r >> 8;            // 0..7
        int kk = r & 255;
        int g = sub & 3, el = sub >> 2;
        int col = g * 256 + gb * 2 + el;
        WmR[idx] = wih[(size_t)col * 512 + kk] + whh[(size_t)col * 256 + kk];
    }
    if (idx < 32768) {
        int h = idx >> 8, k = idx & 255;
        w1t[idx] = out_w1[(size_t)k * 128 + h];
    }
    if (idx < 1024) {
        float a = 0.f;
        for (int k = 0; k < 256; k++) a = fmaf(dec_h0[k], whh[(size_t)idx * 256 + k], a);
        g0[idx] = a;
        biasTot[idx] = bih[idx] + bhh[idx];
    }
}

// ---------------------------------------------------------------------------
// Persistent LSTM: 144 blocks (128 gate + 16 MLP). Single change vs R9:
// h staging rows padded to 65 float4 -> conflict-free hp LDS.128.
// ---------------------------------------------------------------------------
__device__ __forceinline__ float sigf(float x) { return 1.f / (1.f + __expf(-x)); }

__device__ __forceinline__ void grid_bar(unsigned* sync, unsigned target) {
    __threadfence();
    __syncthreads();
    if (threadIdx.x == 0) {
        atomicAdd(sync, 1u);
        while (*(volatile unsigned*)sync < target) { }
        __threadfence();
    }
    __syncthreads();
}

__global__ __launch_bounds__(256, 1) void lstm_persist_k(
    const float* __restrict__ pre, const float* __restrict__ WmR,
    const float* __restrict__ w1t, const float* __restrict__ g0,
    const float* __restrict__ dec_c0,
    const float* __restrict__ b1, const float* __restrict__ w2,
    const float* __restrict__ b2, const float* __restrict__ mask,
    float* __restrict__ hbuf, unsigned* __restrict__ sync,
    float* __restrict__ out)
{
    extern __shared__ float sm[];
    const int tid = threadIdx.x;
    const unsigned NBLK = 144;

    if (blockIdx.x < 128) {
        // -------- gate block: 2 e-cols, one full dot per thread --------
        const int gb = blockIdx.x;
        const int b = tid >> 3;          // batch 0..31
        const int sub = tid & 7;         // (el<<2)|g
        const int g = sub & 3;
        const int el = sub >> 2;
        const int e = gb * 2 + el;
        const int col = g * 256 + e;
        const int lane = tid & 31;
        const int base = lane & ~3;      // lane of g==0 in this quad

        float* ws = sm;                       // [8][260] floats (padded)
        float4* hs4 = (float4*)(sm + 2080);   // [32][65] float4 (PADDED rows)

        // stage weights once (rows padded to 260 floats: conflict-free LDS.128)
        for (int i = tid; i < 2048; i += 256) {
            int ss = i >> 8, kk = i & 255;
            ws[ss * 260 + kk] = WmR[(size_t)gb * 2048 + i];
        }
        const float4* wp = (const float4*)(ws + sub * 260);

        float c = (g == 0) ? dec_c0[e] : 0.f;

        for (int t = 0; t < 512; ++t) {
            float gate;
            if (t == 0) {
                gate = pre[(size_t)b * 524288 + col] + g0[col];
            } else {
                // prefetch pre (off critical path)
                float prv = __ldg(pre + ((size_t)b * 512 + t) * 1024 + col);

                // stage h_t (32x256 floats) into smem, rows padded to 65 float4
                const float4* hsrc = (const float4*)(hbuf + (t & 1) * 8192);
                for (int j = tid; j < 2048; j += 256) {
                    int row = j >> 6, cc = j & 63;
                    hs4[row * 65 + cc] = __ldcg(hsrc + j);
                }
                __syncthreads();

                const float4* hp = hs4 + b * 65;
                float a0 = 0.f, a1 = 0.f, a2 = 0.f, a3 = 0.f;
#pragma unroll 8
                for (int kk = 0; kk < 64; kk += 4) {
                    float4 h0 = hp[kk],     w0 = wp[kk];
                    float4 h1 = hp[kk + 1], w1v = wp[kk + 1];
                    float4 h2 = hp[kk + 2], w2v = wp[kk + 2];
                    float4 h3 = hp[kk + 3], w3v = wp[kk + 3];
                    a0 = fmaf(h0.x, w0.x, fmaf(h0.y, w0.y, fmaf(h0.z, w0.z, fmaf(h0.w, w0.w, a0))));
                    a1 = fmaf(h1.x, w1v.x, fmaf(h1.y, w1v.y, fmaf(h1.z, w1v.z, fmaf(h1.w, w1v.w, a1))));
                    a2 = fmaf(h2.x, w2v.x, fmaf(h2.y, w2v.y, fmaf(h2.z, w2v.z, fmaf(h2.w, w2v.w, a2))));
                    a3 = fmaf(h3.x, w3v.x, fmaf(h3.y, w3v.y, fmaf(h3.z, w3v.z, fmaf(h3.w, w3v.w, a3))));
                }
                gate = (a0 + a1) + (a2 + a3) + prv;
                __syncthreads();   // dot reads done before next staging
            }

            // gather 4 gates within the quad (lane&3 == g)
            float gi = __shfl_sync(0xffffffffu, gate, base + 0);
            float gf = __shfl_sync(0xffffffffu, gate, base + 1);
            float gg = __shfl_sync(0xffffffffu, gate, base + 2);
            float go = __shfl_sync(0xffffffffu, gate, base + 3);
            if (g == 0) {
                float cn = sigf(gf) * c + sigf(gi) * tanhf(gg);
                float hn = sigf(go) * tanhf(cn);
                c = cn;
                __stcg(hbuf + ((t + 1) & 1) * 8192 + b * 256 + e, hn);
            }
            grid_bar(sync, (unsigned)(t + 1) * NBLK);
        }
    } else {
        // -------- MLP block: 2 batches, lagged output head --------
        const int mb = blockIdx.x - 128;
        const int bat = tid >> 7;        // 0/1 within block
        const int ho = tid & 127;
        float* w1s  = sm;                // [128][260] floats
        float* hrow = sm + 33280;        // [2][256]
        float* red  = sm + 33792;        // [8]

        for (int i = tid; i < 8192; i += 256) {
            int h = i >> 6, k4 = i & 63;
            ((float4*)w1s)[h * 65 + k4] = ((const float4*)w1t)[i];
        }
        float w2v = w2[ho];
        float b1v = b1[ho];
        float b2v = b2[0];

        for (int t = 0; t <= 512; ++t) {
            if (t >= 1) {
                for (int i = tid; i < 512; i += 256) {
                    int bb = i >> 8, k = i & 255;
                    hrow[bb * 256 + k] =
                        __ldcg(hbuf + (t & 1) * 8192 + (mb * 2 + bb) * 256 + k);
                }
                __syncthreads();

                float a = b1v;
                const float4* h4 = (const float4*)(hrow + bat * 256);
                const float4* w4 = (const float4*)(w1s + ho * 260);
#pragma unroll 16
                for (int kk = 0; kk < 64; kk++) {
                    float4 hv = h4[kk];
                    float4 wv = w4[kk];
                    a = fmaf(hv.x, wv.x, fmaf(hv.y, wv.y, fmaf(hv.z, wv.z, fmaf(hv.w, wv.w, a))));
                }
                float contrib = fmaxf(a, 0.f) * w2v;
#pragma unroll
                for (int o = 16; o > 0; o >>= 1)
                    contrib += __shfl_down_sync(0xffffffffu, contrib, o);
                if ((tid & 31) == 0) red[tid >> 5] = contrib;
                __syncthreads();
                if (tid == 0) {
                    int bidx = mb * 2;
                    float pp = red[0] + red[1] + red[2] + red[3] + b2v;
                    out[bidx * 512 + (t - 1)] = pp * mask[bidx * 512 + (t - 1)];
                }
                if (tid == 128) {
                    int bidx = mb * 2 + 1;
                    float pp = red[4] + red[5] + red[6] + red[7] + b2v;
                    out[bidx * 512 + (t - 1)] = pp * mask[bidx * 512 + (t - 1)];
                }
                __syncthreads();
            }
            if (t < 512) grid_bar(sync, (unsigned)(t + 1) * NBLK);
        }
    }
}

// ---------------------------------------------------------------------------
// Launcher
// ---------------------------------------------------------------------------
extern "C" void kernel_launch(void* const* d_in, const int* in_sizes, int n_in,
                              void* d_out, int out_size)
{
    const float* inputs   = (const float*)d_in[0];
    const float* mask     = (const float*)d_in[1];
    /* d_in[2] = lengths (unused) */
    const float* embed_w  = (const float*)d_in[3];
    const float* embed_b  = (const float*)d_in[4];
    const float* qkvo_w   = (const float*)d_in[5];
    const float* qkvo_b   = (const float*)d_in[6];
    const float* ln_g     = (const float*)d_in[7];
    const float* ln_b     = (const float*)d_in[8];
    const float* ff_w1    = (const float*)d_in[9];
    const float* ff_b1    = (const float*)d_in[10];
    const float* ff_w2    = (const float*)d_in[11];
    const float* ff_b2    = (const float*)d_in[12];
    const float* enc_ln_g = (const float*)d_in[13];
    const float* enc_ln_b = (const float*)d_in[14];
    const float* wih      = (const float*)d_in[15];
    const float* whh      = (const float*)d_in[16];
    const float* bih      = (const float*)d_in[17];
    const float* bhh      = (const float*)d_in[18];
    const float* dec_h0   = (const float*)d_in[19];
    const float* dec_c0   = (const float*)d_in[20];
    const float* out_w1   = (const float*)d_in[21];
    const float* out_b1   = (const float*)d_in[22];
    const float* out_w2   = (const float*)d_in[23];
    const float* out_b2   = (const float*)d_in[24];
    float* out = (float*)d_out;
    (void)in_sizes; (void)n_in; (void)out_size;

    float *px, *py, *pqkv, *po, *ph1, *ppre, *pinT, *pwtf, *pWET, *pWmR, *pw1t,
          *pg0, *pbt, *phb;
    unsigned* psync;
    cudaGetSymbolAddress((void**)&px,    g_x);
    cudaGetSymbolAddress((void**)&py,    g_y);
    cudaGetSymbolAddress((void**)&pqkv,  g_qkv);
    cudaGetSymbolAddress((void**)&po,    g_o);
    cudaGetSymbolAddress((void**)&ph1,   g_h1);
    cudaGetSymbolAddress((void**)&ppre,  g_pre);
    cudaGetSymbolAddress((void**)&pinT,  g_inT);
    cudaGetSymbolAddress((void**)&pwtf,  g_wtf);
    cudaGetSymbolAddress((void**)&pWET,  g_WihEncT);
    cudaGetSymbolAddress((void**)&pWmR,  g_WmR);
    cudaGetSymbolAddress((void**)&pw1t,  g_w1t);
    cudaGetSymbolAddress((void**)&pg0,   g_g0);
    cudaGetSymbolAddress((void**)&pbt,   g_biasTot);
    cudaGetSymbolAddress((void**)&phb,   g_hbuf);
    cudaGetSymbolAddress((void**)&psync, g_sync);

    cudaFuncSetAttribute(gemm_tc, cudaFuncAttributeMaxDynamicSharedMemorySize, GEMM_SMEM);
    cudaFuncSetAttribute(attn_tc, cudaFuncAttributeMaxDynamicSharedMemorySize, 110592);
    cudaFuncSetAttribute(lstm_persist_k, cudaFuncAttributeMaxDynamicSharedMemorySize, 137216);

    const int M = 16384;
    const long QKV_C = 16384L * 256;

    // prep: tf32 conversions + LSTM weights + barrier reset
    cvtw_k<<<19200, 256>>>(inputs, embed_w, qkvo_w, ff_w1, ff_w2, pinT, pwtf);
    lstm_prep_k<<<1024, 256>>>(wih, whh, bih, bhh, dec_h0, out_w1,
                               pWET, pWmR, pw1t, pg0, pbt, psync);

    // Embed (K=300)
    gemm_tc<<<dim3(2, 128), 256, GEMM_SMEM>>>(pinT, pwtf + OFF_EMB, embed_b,
                                              nullptr, px,
                                              M, 256, 300, 0, 0, 2, 0, 0, 0);

    // Transformer layers
    for (int l = 0; l < 6; l++) {
        const float* Wq = pwtf + OFF_QKVO + (size_t)(l * 4) * 65536;
        const float* Wo = pwtf + OFF_QKVO + (size_t)(l * 4 + 3) * 65536;
        const float* bq = qkvo_b + (l * 4) * 256;
        const float* bo = qkvo_b + (l * 4 + 3) * 256;

        layernorm_k<<<2048, 256>>>(px, ln_g + l * 512, ln_b + l * 512, py);
        gemm_tc<<<dim3(6, 128), 256, GEMM_SMEM>>>(py, Wq, bq, nullptr, pqkv,
                                                  M, 256, 256, 0, 1,
                                                  2, 65536, QKV_C, 256);
        attn_tc<<<dim3(4, 256), 256, 110592>>>(pqkv, pqkv + QKV_C,
                                               pqkv + 2 * QKV_C, mask, po);
        gemm_tc<<<dim3(2, 128), 256, GEMM_SMEM>>>(po, Wo, bo, px, px,
                                                  M, 256, 256, 0, 0, 2, 0, 0, 0);

        layernorm_k<<<2048, 256>>>(px, ln_g + l * 512 + 256, ln_b + l * 512 + 256, py);
        gemm_tc<<<dim3(1, 128), 256, GEMM_SMEM>>>(py, pwtf + OFF_FF1 + (size_t)l * 32768,
                                                  ff_b1 + l * 128, nullptr, ph1,
                                                  M, 128, 256, 1, 1, 1, 0, 0, 0);
        gemm_tc<<<dim3(2, 128), 256, GEMM_SMEM>>>(ph1, pwtf + OFF_FF2 + (size_t)l * 32768,
                                                  ff_b2 + l * 256, px, px,
                                                  M, 256, 128, 0, 0, 2, 0, 0, 0);
    }

    // Encoder LN -> enc (in py, tf32-rounded)
    layernorm_k<<<2048, 256>>>(px, enc_ln_g, enc_ln_b, py);

    // pre = enc @ wih[:,256:].T + (bih+bhh)
    gemm_tc<<<dim3(8, 128), 256, GEMM_SMEM>>>(py, pWET, pbt, nullptr, ppre,
                                              M, 1024, 256, 0, 0, 8, 0, 0, 0);

    // Persistent LSTM scan + output head (single launch, 144 blocks)
    lstm_persist_k<<<144, 256, 137216>>>(ppre, pWmR, pw1t, pg0, dec_c0,
                                         out_b1, out_w2, out_b2, mask,
                                         phb, psync, out);
}